// round 8
// baseline (speedup 1.0000x reference)
#include <cuda_runtime.h>
#include <cuda_bf16.h>
#include <math.h>
#include <stdint.h>

// ---------------- problem constants ----------------
static constexpr int BB   = 4;
static constexpr int KK   = 256;
static constexpr int NS   = 1024;      // seeds
static constexpr int CF   = 256;       // seed feature channels
static constexpr int GPP  = 64;        // grid points per proposal
static constexpr int QQ   = KK * GPP;  // 16384 queries per batch
static constexpr int M1   = BB * QQ;   // 65536 rows for conv layers
static constexpr int CIN0 = CF + 3;    // 259 logical input channels
static constexpr int KPH0 = 288;       // padded logical K for layer0 (9 chunks of 32)
static constexpr int HH   = 128;
static constexpr int MFC  = BB * KK;   // 1024 rows for FC layers
static constexpr int IOUS = 18;
static constexpr int OUTC = 77;

static constexpr int TW   = 16 * 136;                 // one tile in words
static constexpr int SMEM_WORDS = 8 * TW + 768;       // 2 bufs x (AH,AL,WH,WL) + red arrays
static constexpr int SMEM_BYTES = SMEM_WORDS * 4;     // 72704 B

// ---------------- scratch (static device memory; no allocations) ----------------
__device__ float g_wq[M1 * 3];
__device__ float g_rel[M1 * 3];
__device__ float g_featT[BB * NS * CF];        // [b][n][c]
__device__ int   g_idx3[M1 * 3];
__device__ float g_w3[M1 * 3];
__device__ float g_Y1[(long long)M1 * HH];
__device__ float g_Y2[(long long)M1 * HH];
__device__ float g_F [MFC * HH];               // RAW maxpool output (pre-BN3)
__device__ float g_N1[MFC * HH];
__device__ float g_N2[MFC * HH];
__device__ float g_part[512 * 256];            // per-CTA partial BN stats
__device__ float g_scale[5 * 128];
__device__ float g_shift[5 * 128];
// pre-split packed-bf16 weights: [kp][n] (kp = k/2), layer0 permuted + zero-padded
__device__ uint32_t g_W0H[144 * 128], g_W0L[144 * 128];
__device__ uint32_t g_W1H[ 64 * 128], g_W1L[ 64 * 128];
__device__ uint32_t g_W2H[ 64 * 128], g_W2L[ 64 * 128];

// ---------------- small helpers ----------------
// split two fp32 values into packed-bf16 (hi pair, lo pair); word = {k_even, k_odd}
__device__ __forceinline__ void split2_bf16(float v0, float v1, uint32_t& hi, uint32_t& lo) {
    __nv_bfloat16 h0 = __float2bfloat16_rn(v0);
    __nv_bfloat16 h1 = __float2bfloat16_rn(v1);
    float l0 = v0 - __bfloat162float(h0);
    float l1 = v1 - __bfloat162float(h1);
    __nv_bfloat162 hp = __halves2bfloat162(h0, h1);
    __nv_bfloat162 lp = __floats2bfloat162_rn(l0, l1);
    hi = *reinterpret_cast<uint32_t*>(&hp);
    lo = *reinterpret_cast<uint32_t*>(&lp);
}

__device__ __forceinline__ void mma_bf16(float& c0, float& c1, float& c2, float& c3,
                                         uint32_t a0, uint32_t a1, uint32_t a2, uint32_t a3,
                                         uint32_t b0, uint32_t b1) {
    asm volatile(
        "mma.sync.aligned.m16n8k16.row.col.f32.bf16.bf16.f32 "
        "{%0,%1,%2,%3}, {%4,%5,%6,%7}, {%8,%9}, {%0,%1,%2,%3};"
        : "+f"(c0), "+f"(c1), "+f"(c2), "+f"(c3)
        : "r"(a0), "r"(a1), "r"(a2), "r"(a3), "r"(b0), "r"(b1));
}

// ---------------- weight prep: fp32 -> packed bf16 hi/lo, tile-shaped [kp][n] ----------------
__global__ void k_prepW0(const float* __restrict__ W) {
    int t = blockIdx.x * blockDim.x + threadIdx.x;   // < 144*128
    int kp = t >> 7, n = t & 127;
    int k0 = 2 * kp, k1 = 2 * kp + 1;
    float v0 = 0.f, v1 = 0.f;
    if (k0 < CIN0) { int kl = (k0 < 256) ? k0 + 3 : k0 - 256; v0 = W[n * CIN0 + kl]; }
    if (k1 < CIN0) { int kl = (k1 < 256) ? k1 + 3 : k1 - 256; v1 = W[n * CIN0 + kl]; }
    uint32_t hi, lo;
    split2_bf16(v0, v1, hi, lo);
    g_W0H[t] = hi; g_W0L[t] = lo;
}

__global__ void k_prepW128(const float* __restrict__ W,
                           uint32_t* __restrict__ WH, uint32_t* __restrict__ WL) {
    int t = blockIdx.x * blockDim.x + threadIdx.x;   // < 64*128
    int kp = t >> 7, n = t & 127;
    float v0 = W[n * 128 + 2 * kp];
    float v1 = W[n * 128 + 2 * kp + 1];
    uint32_t hi, lo;
    split2_bf16(v0, v1, hi, lo);
    WH[t] = hi; WL[t] = lo;
}

// ---------------- stage-1 kernels ----------------

// seed_features [b][c][n] -> g_featT [b][n][c]
__global__ void k_transpose(const float* __restrict__ feat) {
    __shared__ float tile[32][33];
    int b  = blockIdx.z;
    int n0 = blockIdx.x * 32;
    int c0 = blockIdx.y * 32;
    const float* src = feat    + (long long)b * CF * NS;
    float*       dst = g_featT + (long long)b * NS * CF;
#pragma unroll
    for (int r = 0; r < 4; ++r) {
        int c = c0 + threadIdx.y + r * 8;
        tile[threadIdx.y + r * 8][threadIdx.x] = src[c * NS + n0 + threadIdx.x];
    }
    __syncthreads();
#pragma unroll
    for (int r = 0; r < 4; ++r) {
        int n = n0 + threadIdx.y + r * 8;
        dst[n * CF + c0 + threadIdx.x] = tile[threadIdx.x][threadIdx.y + r * 8];
    }
}

// rotate+scale grid -> g_rel, world points -> g_wq
__global__ void k_gridpoints(const float* __restrict__ center,
                             const float* __restrict__ size_,
                             const float* __restrict__ heading) {
    int m = blockIdx.x * blockDim.x + threadIdx.x;
    if (m >= M1) return;
    int g  = m & 63;
    int bk = m >> 6;
    float sx = size_[bk * 3 + 0], sy = size_[bk * 3 + 1], sz = size_[bk * 3 + 2];
    float h  = heading[bk];
    float ch = cosf(h), sh = sinf(h);
    float gx = -1.f + (float)( g >> 4      ) * (2.f / 3.f);
    float gy = -1.f + (float)((g >> 2) & 3 ) * (2.f / 3.f);
    float gz = -1.f + (float)( g       & 3 ) * (2.f / 3.f);
    float ax = gx * sx, ay = gy * sy, az = gz * sz;
    float rx = ax * ch - ay * sh;
    float ry = ax * sh + ay * ch;
    float rz = az;
    g_rel[m * 3 + 0] = rx;
    g_rel[m * 3 + 1] = ry;
    g_rel[m * 3 + 2] = rz;
    g_wq[m * 3 + 0] = rx + center[bk * 3 + 0];
    g_wq[m * 3 + 1] = ry + center[bk * 3 + 1];
    g_wq[m * 3 + 2] = rz + center[bk * 3 + 2];
}

// 3-NN per query over 1024 seeds (seeds cached in SMEM), inverse-distance weights
__global__ void k_threenn(const float* __restrict__ seed_xyz) {
    __shared__ float4 sp[NS];
    int b = blockIdx.x >> 7;
    int q = ((blockIdx.x & 127) << 7) + threadIdx.x;
    for (int i = threadIdx.x; i < NS; i += blockDim.x) {
        float x = seed_xyz[((long long)b * NS + i) * 3 + 0];
        float y = seed_xyz[((long long)b * NS + i) * 3 + 1];
        float z = seed_xyz[((long long)b * NS + i) * 3 + 2];
        sp[i] = make_float4(x, y, z, x * x + y * y + z * z);
    }
    __syncthreads();
    int m = b * QQ + q;
    float qx = g_wq[m * 3 + 0], qy = g_wq[m * 3 + 1], qz = g_wq[m * 3 + 2];
    float qq = qx * qx + qy * qy + qz * qz;
    float d0 = 1e30f, d1 = 1e30f, d2 = 1e30f;
    int   i0 = 0, i1 = 0, i2 = 0;
    for (int n = 0; n < NS; ++n) {
        float4 p = sp[n];
        float d = qq + p.w - 2.f * (qx * p.x + qy * p.y + qz * p.z);
        if (d < d2) {
            if (d < d1) {
                d2 = d1; i2 = i1;
                if (d < d0) { d1 = d0; i1 = i0; d0 = d; i0 = n; }
                else        { d1 = d;  i1 = n; }
            } else { d2 = d; i2 = n; }
        }
    }
    int ii[3] = {i0, i1, i2};
    float w[3];
#pragma unroll
    for (int j = 0; j < 3; ++j) {
        float4 p = sp[ii[j]];
        float dx = p.x - qx, dy = p.y - qy, dz = p.z - qz;
        float dist = sqrtf(dx * dx + dy * dy + dz * dz);
        w[j] = 1.f / (dist + 1e-8f);
    }
    float inv = 1.f / (w[0] + w[1] + w[2]);
#pragma unroll
    for (int j = 0; j < 3; ++j) {
        g_idx3[m * 3 + j] = ii[j];
        g_w3[m * 3 + j]   = w[j] * inv;
    }
}

// ---- split-bf16 tensor-core GEMM: double-buffered tiles, pre-split W, fused epilogue ----
// C[m,n] = sum_k act(A[m,k]) * W[n,k] + bias[n]
// 128x128 tile, K-chunks of 32, m16n8k16 bf16 MMA, acc += aL*bH + aH*bL + aH*bH.
// 8 warps (2 over M x 4 over N), 2 CTAs/SM. ONE __syncthreads per chunk:
// chunk ch+1's tiles are built into buffer ^1 while MMAs consume buffer ch&1.
// W arrives pre-split (packed bf16 hi/lo, tile-shaped) -> W build is a pure copy.
// GATHER: layer-0 mode; A gathered on the fly from g_featT (L2-hot) + rel xyz.
// !GATHER: A registers prefetched two chunks ahead.
template <bool BNA, bool GATHER, bool POOL, bool STOREC>
__global__ void __launch_bounds__(256, 2)
k_gemm_bf(const float* __restrict__ A, int lda,
          const uint32_t* __restrict__ WH,
          const uint32_t* __restrict__ WL,
          const float* __restrict__ bias,
          const float* __restrict__ scl,
          const float* __restrict__ shf,
          float* __restrict__ C,
          float* __restrict__ partOut,
          float* __restrict__ poolOut) {
    extern __shared__ uint32_t sm[];
    // layout: buf b at b*4*TW: [AH | AL | WH | WL], each TW=16*136 words; red at 8*TW

    const int tid  = threadIdx.x;
    const int lane = tid & 31;
    const int warp = tid >> 5;
    const int g    = lane >> 2;        // 0..7
    const int q    = lane & 3;         // 0..3
    const int wm   = warp & 1;         // 2 warps over M
    const int wn   = warp >> 1;        // 4 warps over N
    const int bm   = blockIdx.x * 128;

    float acc[4][4][4];
#pragma unroll
    for (int i = 0; i < 4; ++i)
#pragma unroll
        for (int j = 0; j < 4; ++j)
#pragma unroll
            for (int r = 0; r < 4; ++r) acc[i][j][r] = 0.f;

    const int ldrow = tid >> 1;         // 0..127 (A row within tile)
    const int ldkv  = (tid & 1) * 16;   // 0 or 16
    const int kp0   = ldkv / 2;         // 0 or 8
    const int NCH   = GATHER ? (KPH0 / 32) : 4;

    // W copy mapping: 256 threads cover 16 kp x 16 n-blocks of 8
    const int wkp = tid & 15;
    const int wn0 = (tid >> 4) * 8;

    // GATHER state (row fixed for the whole k-loop)
    const float *gf0 = nullptr, *gf1 = nullptr, *gf2 = nullptr;
    float gw0 = 0.f, gw1 = 0.f, gw2 = 0.f;
    float grel[3] = {0.f, 0.f, 0.f};
    if (GATHER) {
        const int m = bm + ldrow;
        const int b = m >> 14;
        int i0 = g_idx3[m * 3 + 0], i1 = g_idx3[m * 3 + 1], i2 = g_idx3[m * 3 + 2];
        gw0 = g_w3[m * 3 + 0]; gw1 = g_w3[m * 3 + 1]; gw2 = g_w3[m * 3 + 2];
        gf0 = g_featT + ((long long)b * NS + i0) * CF;
        gf1 = g_featT + ((long long)b * NS + i1) * CF;
        gf2 = g_featT + ((long long)b * NS + i2) * CF;
        grel[0] = g_rel[m * 3 + 0];
        grel[1] = g_rel[m * 3 + 1];
        grel[2] = g_rel[m * 3 + 2];
    }

    float vA[16];
    // load A chunk 'c' into vA (non-gather)
    auto loadA = [&](int c) {
        const float* ap = A + (long long)(bm + ldrow) * lda + c * 32 + ldkv;
        float4 u0 = *(const float4*)(ap + 0);
        float4 u1 = *(const float4*)(ap + 4);
        float4 u2 = *(const float4*)(ap + 8);
        float4 u3 = *(const float4*)(ap + 12);
        vA[0]=u0.x; vA[1]=u0.y; vA[2]=u0.z; vA[3]=u0.w;
        vA[4]=u1.x; vA[5]=u1.y; vA[6]=u1.z; vA[7]=u1.w;
        vA[8]=u2.x; vA[9]=u2.y; vA[10]=u2.z; vA[11]=u2.w;
        vA[12]=u3.x; vA[13]=u3.y; vA[14]=u3.z; vA[15]=u3.w;
    };

    // build A tile for chunk 'c' into buffer base 'tb' (vA holds chunk c if !GATHER)
    auto buildA = [&](int c, uint32_t* tb) {
        float v[16];
        if (GATHER) {
            const int kbase = c * 32 + ldkv;
            if (kbase < 256) {
#pragma unroll
                for (int r4 = 0; r4 < 4; ++r4) {
                    float4 a  = *(const float4*)(gf0 + kbase + r4 * 4);
                    float4 bq = *(const float4*)(gf1 + kbase + r4 * 4);
                    float4 cq = *(const float4*)(gf2 + kbase + r4 * 4);
                    v[r4 * 4 + 0] = gw0 * a.x + gw1 * bq.x + gw2 * cq.x;
                    v[r4 * 4 + 1] = gw0 * a.y + gw1 * bq.y + gw2 * cq.y;
                    v[r4 * 4 + 2] = gw0 * a.z + gw1 * bq.z + gw2 * cq.z;
                    v[r4 * 4 + 3] = gw0 * a.w + gw1 * bq.w + gw2 * cq.w;
                }
            } else {
#pragma unroll
                for (int i = 0; i < 16; ++i) v[i] = 0.f;
                if (kbase == 256) { v[0] = grel[0]; v[1] = grel[1]; v[2] = grel[2]; }
            }
        } else {
#pragma unroll
            for (int i = 0; i < 16; ++i) v[i] = vA[i];
            if (BNA) {
#pragma unroll
                for (int i = 0; i < 16; ++i) {
                    int k = c * 32 + ldkv + i;   // KDIM=128 in BNA mode: always valid
                    v[i] = fmaxf(v[i] * scl[k] + shf[k], 0.f);
                }
            }
        }
        uint32_t* AH = tb;
        uint32_t* AL = tb + TW;
#pragma unroll
        for (int i = 0; i < 8; ++i) {
            uint32_t hi, lo;
            split2_bf16(v[2 * i], v[2 * i + 1], hi, lo);
            AH[(kp0 + i) * 136 + ldrow] = hi;
            AL[(kp0 + i) * 136 + ldrow] = lo;
        }
    };

    // copy W tile for chunk 'c' into buffer base 'tb' (pure copy, pre-split global)
    auto buildW = [&](int c, uint32_t* tb) {
        const uint4* sH = (const uint4*)(WH + (c * 16 + wkp) * 128 + wn0);
        const uint4* sL = (const uint4*)(WL + (c * 16 + wkp) * 128 + wn0);
        uint4* dH = (uint4*)(tb + 2 * TW + wkp * 136 + wn0);
        uint4* dL = (uint4*)(tb + 3 * TW + wkp * 136 + wn0);
        dH[0] = sH[0]; dH[1] = sH[1];
        dL[0] = sL[0]; dL[1] = sL[1];
    };

    // ---- prologue: fill buffer 0 with chunk 0 ----
    if (!GATHER) loadA(0);
    buildA(0, sm);
    buildW(0, sm);
    if (!GATHER && NCH > 1) loadA(1);
    __syncthreads();

    for (int ch = 0; ch < NCH; ++ch) {
        const int cur = ch & 1;
        uint32_t* tcur = sm + cur * 4 * TW;
        // ---- build next chunk's tiles into the other buffer ----
        if (ch + 1 < NCH) {
            uint32_t* tnxt = sm + (cur ^ 1) * 4 * TW;
            buildA(ch + 1, tnxt);      // !GATHER: consumes vA(ch+1); GATHER: L2-hot loads
            buildW(ch + 1, tnxt);
            if (!GATHER && ch + 2 < NCH) loadA(ch + 2);
        }
        // ---- MMAs on current buffer ----
        const uint32_t* AHc = tcur;
        const uint32_t* ALc = tcur + TW;
        const uint32_t* WHc = tcur + 2 * TW;
        const uint32_t* WLc = tcur + 3 * TW;
#pragma unroll
        for (int kb = 0; kb < 16; kb += 8) {
            uint32_t bH[4][2], bL[4][2];
#pragma unroll
            for (int nt = 0; nt < 4; ++nt) {
                int nbase = wn * 32 + nt * 8;
                bH[nt][0] = WHc[(kb + q    ) * 136 + nbase + g];
                bH[nt][1] = WHc[(kb + q + 4) * 136 + nbase + g];
                bL[nt][0] = WLc[(kb + q    ) * 136 + nbase + g];
                bL[nt][1] = WLc[(kb + q + 4) * 136 + nbase + g];
            }
#pragma unroll
            for (int mt = 0; mt < 4; ++mt) {
                int mbase = wm * 64 + mt * 16;
                uint32_t aH0 = AHc[(kb + q    ) * 136 + mbase + g    ];
                uint32_t aH1 = AHc[(kb + q    ) * 136 + mbase + g + 8];
                uint32_t aH2 = AHc[(kb + q + 4) * 136 + mbase + g    ];
                uint32_t aH3 = AHc[(kb + q + 4) * 136 + mbase + g + 8];
                uint32_t aL0 = ALc[(kb + q    ) * 136 + mbase + g    ];
                uint32_t aL1 = ALc[(kb + q    ) * 136 + mbase + g + 8];
                uint32_t aL2 = ALc[(kb + q + 4) * 136 + mbase + g    ];
                uint32_t aL3 = ALc[(kb + q + 4) * 136 + mbase + g + 8];
#pragma unroll
                for (int nt = 0; nt < 4; ++nt) {
                    mma_bf16(acc[mt][nt][0], acc[mt][nt][1], acc[mt][nt][2], acc[mt][nt][3],
                             aL0, aL1, aL2, aL3, bH[nt][0], bH[nt][1]);
                    mma_bf16(acc[mt][nt][0], acc[mt][nt][1], acc[mt][nt][2], acc[mt][nt][3],
                             aH0, aH1, aH2, aH3, bL[nt][0], bL[nt][1]);
                    mma_bf16(acc[mt][nt][0], acc[mt][nt][1], acc[mt][nt][2], acc[mt][nt][3],
                             aH0, aH1, aH2, aH3, bH[nt][0], bH[nt][1]);
                }
            }
        }
        __syncthreads();
    }

    // ---- fused epilogue: bias, optional store, BN stats partials, optional maxpool ----
    float* redS = (float*)(sm + 8 * TW);          // [2][128]
    float* redQ = redS + 256;
    float* redM = redQ + 256;

    float bsv[4][2];
#pragma unroll
    for (int nt = 0; nt < 4; ++nt) {
        int col = wn * 32 + nt * 8 + q * 2;
        bsv[nt][0] = bias[col];
        bsv[nt][1] = bias[col + 1];
    }
    float s[4][2], s2[4][2], mx[4][2];
#pragma unroll
    for (int nt = 0; nt < 4; ++nt)
#pragma unroll
        for (int j = 0; j < 2; ++j) { s[nt][j] = 0.f; s2[nt][j] = 0.f; mx[nt][j] = -1e30f; }

#pragma unroll
    for (int mt = 0; mt < 4; ++mt) {
#pragma unroll
        for (int nt = 0; nt < 4; ++nt) {
            float v0 = acc[mt][nt][0] + bsv[nt][0];
            float v1 = acc[mt][nt][1] + bsv[nt][1];
            float v2 = acc[mt][nt][2] + bsv[nt][0];
            float v3 = acc[mt][nt][3] + bsv[nt][1];
            if (STOREC) {
                int col = wn * 32 + nt * 8 + q * 2;
                int r0  = bm + wm * 64 + mt * 16 + g;
                *(float2*)(C + (long long)r0 * 128 + col)       = make_float2(v0, v1);
                *(float2*)(C + (long long)(r0 + 8) * 128 + col) = make_float2(v2, v3);
            }
            s [nt][0] += v0 + v2;       s [nt][1] += v1 + v3;
            s2[nt][0] += v0 * v0 + v2 * v2;
            s2[nt][1] += v1 * v1 + v3 * v3;
            if (POOL) {
                mx[nt][0] = fmaxf(mx[nt][0], fmaxf(v0, v2));
                mx[nt][1] = fmaxf(mx[nt][1], fmaxf(v1, v3));
            }
        }
    }
    // reduce across the 8 g-lanes (lane = g*4+q; g bits are lane bits 2..4)
#pragma unroll
    for (int nt = 0; nt < 4; ++nt)
#pragma unroll
        for (int j = 0; j < 2; ++j) {
#pragma unroll
            for (int mask = 4; mask <= 16; mask <<= 1) {
                s [nt][j] += __shfl_xor_sync(0xffffffff, s [nt][j], mask);
                s2[nt][j] += __shfl_xor_sync(0xffffffff, s2[nt][j], mask);
                if (POOL)
                    mx[nt][j] = fmaxf(mx[nt][j], __shfl_xor_sync(0xffffffff, mx[nt][j], mask));
            }
        }
    if (g == 0) {
#pragma unroll
        for (int nt = 0; nt < 4; ++nt)
#pragma unroll
            for (int j = 0; j < 2; ++j) {
                int col = wn * 32 + nt * 8 + q * 2 + j;
                redS[wm * 128 + col] = s[nt][j];
                redQ[wm * 128 + col] = s2[nt][j];
                if (POOL) redM[wm * 128 + col] = mx[nt][j];
            }
    }
    __syncthreads();
    if (tid < 128) {
        partOut[blockIdx.x * 256 + tid]       = redS[tid] + redS[128 + tid];
        partOut[blockIdx.x * 256 + 128 + tid] = redQ[tid] + redQ[128 + tid];
    }
    if (POOL) {
        poolOut[(blockIdx.x * 2 + (tid >> 7)) * 128 + (tid & 127)] =
            redM[(tid >> 7) * 128 + (tid & 127)];
    }
}

// reduce 512 per-CTA partials -> folded BN scale/shift (1 block, 512 threads)
__global__ void k_bnfin512(float Minv,
                           const float* __restrict__ gamma,
                           const float* __restrict__ beta,
                           int slot) {
    __shared__ float rs[4][128], rq[4][128];
    int c  = threadIdx.x & 127;
    int sl = threadIdx.x >> 7;
    float s = 0.f, q = 0.f;
    for (int b = sl * 128; b < sl * 128 + 128; ++b) {
        s += g_part[b * 256 + c];
        q += g_part[b * 256 + 128 + c];
    }
    rs[sl][c] = s; rq[sl][c] = q;
    __syncthreads();
    if (threadIdx.x < 128) {
        float S = rs[0][c] + rs[1][c] + rs[2][c] + rs[3][c];
        float Q = rq[0][c] + rq[1][c] + rq[2][c] + rq[3][c];
        float mean = S * Minv;
        float var  = Q * Minv - mean * mean;
        float rstd = rsqrtf(var + 1e-5f);
        float sc   = gamma[c] * rstd;
        g_scale[slot * 128 + c] = sc;
        g_shift[slot * 128 + c] = beta[c] - mean * sc;
    }
}

// -------- fp32 SIMT GEMM for the tiny FC layers (M=1024) --------
template <int KDIM, bool BNA>
__global__ void __launch_bounds__(256)
k_gemm(const float* __restrict__ A, int lda,
       const float* __restrict__ W,
       const float* __restrict__ bias,
       const float* __restrict__ scl,
       const float* __restrict__ shf,
       float* __restrict__ C) {
    __shared__ float As[16][128];
    __shared__ float Ws2[16][128];
    int tid = threadIdx.x;
    int bm  = blockIdx.x * 128;
    int tx  = tid & 15, ty = tid >> 4;
    float acc[8][8];
#pragma unroll
    for (int i = 0; i < 8; ++i)
#pragma unroll
        for (int j = 0; j < 8; ++j) acc[i][j] = 0.f;

    const int KT = (KDIM + 15) / 16;
    for (int kt = 0; kt < KT; ++kt) {
        int k0 = kt * 16;
#pragma unroll
        for (int r = 0; r < 2; ++r) {
            int row = (tid >> 2) + r * 64;
            int kv  = (tid & 3) * 4;
            int k   = k0 + kv;
            float4 v = *reinterpret_cast<const float4*>(A + (long long)(bm + row) * lda + k);
            if (BNA) {
                v.x = fmaxf(v.x * scl[k + 0] + shf[k + 0], 0.f);
                v.y = fmaxf(v.y * scl[k + 1] + shf[k + 1], 0.f);
                v.z = fmaxf(v.z * scl[k + 2] + shf[k + 2], 0.f);
                v.w = fmaxf(v.w * scl[k + 3] + shf[k + 3], 0.f);
            }
            As[kv + 0][row] = v.x;
            As[kv + 1][row] = v.y;
            As[kv + 2][row] = v.z;
            As[kv + 3][row] = v.w;
        }
        {
            int n  = tid >> 1;
            int kb = (tid & 1) * 8;
#pragma unroll
            for (int i = 0; i < 8; ++i) {
                int k = k0 + kb + i;
                Ws2[kb + i][n] = W[n * KDIM + k];
            }
        }
        __syncthreads();
#pragma unroll
        for (int kk = 0; kk < 16; ++kk) {
            float a[8], w8[8];
            *reinterpret_cast<float4*>(&a[0])  = *reinterpret_cast<const float4*>(&As[kk][ty * 8]);
            *reinterpret_cast<float4*>(&a[4])  = *reinterpret_cast<const float4*>(&As[kk][ty * 8 + 4]);
            *reinterpret_cast<float4*>(&w8[0]) = *reinterpret_cast<const float4*>(&Ws2[kk][tx * 8]);
            *reinterpret_cast<float4*>(&w8[4]) = *reinterpret_cast<const float4*>(&Ws2[kk][tx * 8 + 4]);
#pragma unroll
            for (int i = 0; i < 8; ++i)
#pragma unroll
                for (int j = 0; j < 8; ++j) acc[i][j] += a[i] * w8[j];
        }
        __syncthreads();
    }
    float bv[8];
#pragma unroll
    for (int j = 0; j < 8; ++j) bv[j] = bias[tx * 8 + j];
#pragma unroll
    for (int i = 0; i < 8; ++i) {
        long long off = (long long)(bm + ty * 8 + i) * 128 + tx * 8;
        float4 o0 = make_float4(acc[i][0] + bv[0], acc[i][1] + bv[1],
                                acc[i][2] + bv[2], acc[i][3] + bv[3]);
        float4 o1 = make_float4(acc[i][4] + bv[4], acc[i][5] + bv[5],
                                acc[i][6] + bv[6], acc[i][7] + bv[7]);
        *reinterpret_cast<float4*>(C + off)     = o0;
        *reinterpret_cast<float4*>(C + off + 4) = o1;
    }
}

// deterministic two-stage BN stats for FC layers (small)
__global__ void k_stats(const float* __restrict__ Y, int M) {
    __shared__ float ss[256], sq[256];
    int c    = threadIdx.x & 127;
    int half = threadIdx.x >> 7;
    int rowsPer = M / gridDim.x;
    int r0 = blockIdx.x * rowsPer;
    float s = 0.f, s2 = 0.f;
    for (int r = r0 + half; r < r0 + rowsPer; r += 2) {
        float v = Y[(long long)r * 128 + c];
        s += v; s2 += v * v;
    }
    ss[threadIdx.x] = s; sq[threadIdx.x] = s2;
    __syncthreads();
    if (threadIdx.x < 128) {
        g_part[blockIdx.x * 256 + threadIdx.x]       = ss[threadIdx.x] + ss[threadIdx.x + 128];
        g_part[blockIdx.x * 256 + 128 + threadIdx.x] = sq[threadIdx.x] + sq[threadIdx.x + 128];
    }
}

__global__ void k_bnfin(int NB, float Minv,
                        const float* __restrict__ gamma,
                        const float* __restrict__ beta,
                        int slot) {
    int c = threadIdx.x;
    float s = 0.f, s2 = 0.f;
    for (int b = 0; b < NB; ++b) {
        s  += g_part[b * 256 + c];
        s2 += g_part[b * 256 + 128 + c];
    }
    float mean = s * Minv;
    float var  = s2 * Minv - mean * mean;
    float rstd = rsqrtf(var + 1e-5f);
    float sc   = gamma[c] * rstd;
    g_scale[slot * 128 + c] = sc;
    g_shift[slot * 128 + c] = beta[c] - mean * sc;
}

// BN5+ReLU on N2, project to the last 18 of 77 output channels
__global__ void k_final(const float* __restrict__ cw3,
                        const float* __restrict__ cb3,
                        float* __restrict__ out) {
    int t = blockIdx.x * blockDim.x + threadIdx.x;
    if (t >= MFC * IOUS) return;
    int j   = t % IOUS;
    int row = t / IOUS;
    int o   = (OUTC - IOUS) + j;
    const float* wrow = cw3 + o * 128;
    const float* x    = g_N2 + row * 128;
    float acc = cb3[o];
#pragma unroll 8
    for (int i = 0; i < 128; ++i) {
        float v = fmaxf(x[i] * g_scale[4 * 128 + i] + g_shift[4 * 128 + i], 0.f);
        acc += v * wrow[i];
    }
    out[t] = acc;
}

// ---------------- launcher ----------------
extern "C" void kernel_launch(void* const* d_in, const int* in_sizes, int n_in,
                              void* d_out, int out_size) {
    const float* center  = (const float*)d_in[0];
    const float* size_   = (const float*)d_in[1];
    const float* heading = (const float*)d_in[2];
    const float* sxyz    = (const float*)d_in[3];
    const float* sfeat   = (const float*)d_in[4];
    const float* w0  = (const float*)d_in[5];
    const float* b0  = (const float*)d_in[6];
    const float* g0  = (const float*)d_in[7];
    const float* be0 = (const float*)d_in[8];
    const float* w1  = (const float*)d_in[9];
    const float* b1  = (const float*)d_in[10];
    const float* g1  = (const float*)d_in[11];
    const float* be1 = (const float*)d_in[12];
    const float* w2  = (const float*)d_in[13];
    const float* b2  = (const float*)d_in[14];
    const float* g2  = (const float*)d_in[15];
    const float* be2 = (const float*)d_in[16];
    const float* cw1 = (const float*)d_in[17];
    const float* cb1 = (const float*)d_in[18];
    const float* g3  = (const float*)d_in[19];
    const float* be3 = (const float*)d_in[20];
    const float* cw2 = (const float*)d_in[21];
    const float* cb2 = (const float*)d_in[22];
    const float* g4  = (const float*)d_in[23];
    const float* be4 = (const float*)d_in[24];
    const float* cw3 = (const float*)d_in[25];
    const float* cb3 = (const float*)d_in[26];
    float* out = (float*)d_out;

    void *pY1, *pY2, *pF, *pN1, *pN2, *pSC, *pSH, *pPart;
    void *pW0H, *pW0L, *pW1H, *pW1L, *pW2H, *pW2L;
    cudaGetSymbolAddress(&pY1, g_Y1);
    cudaGetSymbolAddress(&pY2, g_Y2);
    cudaGetSymbolAddress(&pF,  g_F);
    cudaGetSymbolAddress(&pN1, g_N1);
    cudaGetSymbolAddress(&pN2, g_N2);
    cudaGetSymbolAddress(&pSC, g_scale);
    cudaGetSymbolAddress(&pSH, g_shift);
    cudaGetSymbolAddress(&pPart, g_part);
    cudaGetSymbolAddress(&pW0H, g_W0H);
    cudaGetSymbolAddress(&pW0L, g_W0L);
    cudaGetSymbolAddress(&pW1H, g_W1H);
    cudaGetSymbolAddress(&pW1L, g_W1L);
    cudaGetSymbolAddress(&pW2H, g_W2H);
    cudaGetSymbolAddress(&pW2L, g_W2L);
    float* Y1 = (float*)pY1;
    float* Y2 = (float*)pY2;
    float* F  = (float*)pF;
    float* N1 = (float*)pN1;
    float* N2 = (float*)pN2;
    float* SC = (float*)pSC;
    float* SH = (float*)pSH;
    float* PART = (float*)pPart;
    uint32_t* W0H = (uint32_t*)pW0H; uint32_t* W0L = (uint32_t*)pW0L;
    uint32_t* W1H = (uint32_t*)pW1H; uint32_t* W1L = (uint32_t*)pW1L;
    uint32_t* W2H = (uint32_t*)pW2H; uint32_t* W2L = (uint32_t*)pW2L;

    // allow 71KB dynamic SMEM on the conv GEMM instantiations (idempotent)
    cudaFuncSetAttribute(k_gemm_bf<false, true,  false, true >,
                         cudaFuncAttributeMaxDynamicSharedMemorySize, SMEM_BYTES);
    cudaFuncSetAttribute(k_gemm_bf<true,  false, false, true >,
                         cudaFuncAttributeMaxDynamicSharedMemorySize, SMEM_BYTES);
    cudaFuncSetAttribute(k_gemm_bf<true,  false, true,  false>,
                         cudaFuncAttributeMaxDynamicSharedMemorySize, SMEM_BYTES);

    // stage 0: weight pre-split (tiny)
    k_prepW0<<<(144 * 128) / 256, 256>>>(w0);
    k_prepW128<<<(64 * 128) / 256, 256>>>(w1, W1H, W1L);
    k_prepW128<<<(64 * 128) / 256, 256>>>(w2, W2H, W2L);

    // stage 1: geometry + 3-NN (interp fused into GEMM0's A-loader)
    k_transpose<<<dim3(NS / 32, CF / 32, BB), dim3(32, 8)>>>(sfeat);
    k_gridpoints<<<M1 / 256, 256>>>(center, size_, heading);
    k_threenn<<<BB * 128, 128>>>(sxyz);

    // stage 2: SharedMLP on tensor cores (double-buffered, pre-split W).
    k_gemm_bf<false, true, false, true><<<M1 / 128, 256, SMEM_BYTES>>>(
        nullptr, 0, W0H, W0L, b0, nullptr, nullptr, Y1, PART, nullptr);
    k_bnfin512<<<1, 512>>>(1.f / M1, g0, be0, 0);

    k_gemm_bf<true, false, false, true><<<M1 / 128, 256, SMEM_BYTES>>>(
        Y1, HH, W1H, W1L, b1, SC + 0 * 128, SH + 0 * 128, Y2, PART, nullptr);
    k_bnfin512<<<1, 512>>>(1.f / M1, g1, be1, 1);

    k_gemm_bf<true, false, true, false><<<M1 / 128, 256, SMEM_BYTES>>>(
        Y2, HH, W2H, W2L, b2, SC + 1 * 128, SH + 1 * 128, nullptr, PART, F);
    k_bnfin512<<<1, 512>>>(1.f / M1, g2, be2, 2);

    // stage 3: FC head (fp32 SIMT, tiny). FC1 applies BN3+ReLU to raw pooled features.
    k_gemm<HH, true><<<MFC / 128, 256>>>(F, HH, cw1, cb1, SC + 2 * 128, SH + 2 * 128, N1);
    k_stats<<<8, 256>>>(N1, MFC);
    k_bnfin<<<1, 128>>>(8, 1.f / MFC, g3, be3, 3);

    k_gemm<HH, true><<<MFC / 128, 256>>>(N1, HH, cw2, cb2, SC + 3 * 128, SH + 3 * 128, N2);
    k_stats<<<8, 256>>>(N2, MFC);
    k_bnfin<<<1, 128>>>(8, 1.f / MFC, g4, be4, 4);

    k_final<<<(MFC * IOUS + 255) / 256, 256>>>(cw3, cb3, out);
}

// round 9
// speedup vs baseline: 1.0115x; 1.0115x over previous
#include <cuda_runtime.h>
#include <cuda_bf16.h>
#include <math.h>
#include <stdint.h>

// ---------------- problem constants ----------------
static constexpr int BB   = 4;
static constexpr int KK   = 256;
static constexpr int NS   = 1024;      // seeds
static constexpr int CF   = 256;       // seed feature channels
static constexpr int GPP  = 64;        // grid points per proposal
static constexpr int QQ   = KK * GPP;  // 16384 queries per batch
static constexpr int M1   = BB * QQ;   // 65536 rows for conv layers
static constexpr int CIN0 = CF + 3;    // 259 logical input channels
static constexpr int KPH0 = 288;       // padded logical K for layer0 (9 chunks of 32)
static constexpr int HH   = 128;
static constexpr int MFC  = BB * KK;   // 1024 rows for FC layers
static constexpr int IOUS = 18;
static constexpr int OUTC = 77;

// ---------------- scratch (static device memory; no allocations) ----------------
__device__ float g_wq[M1 * 3];
__device__ float g_rel[M1 * 3];
__device__ float g_featT[BB * NS * CF];        // [b][n][c]
__device__ int   g_idx3[M1 * 3];
__device__ float g_w3[M1 * 3];
__device__ float g_Y1[(long long)M1 * HH];
__device__ float g_Y2[(long long)M1 * HH];
__device__ float g_F [MFC * HH];               // RAW maxpool output (pre-BN3)
__device__ float g_N1[MFC * HH];
__device__ float g_N2[MFC * HH];
__device__ float g_part[512 * 256];            // per-CTA partial BN stats
__device__ float g_scale[5 * 128];
__device__ float g_shift[5 * 128];
// pre-split packed-bf16 weights: [kp][n] (kp = k/2), layer0 permuted + zero-padded
__device__ uint32_t g_W0H[144 * 128], g_W0L[144 * 128];
__device__ uint32_t g_W1H[ 64 * 128], g_W1L[ 64 * 128];
__device__ uint32_t g_W2H[ 64 * 128], g_W2L[ 64 * 128];

// ---------------- small helpers ----------------
// split two fp32 values into packed-bf16 (hi pair, lo pair); word = {k_even, k_odd}
__device__ __forceinline__ void split2_bf16(float v0, float v1, uint32_t& hi, uint32_t& lo) {
    __nv_bfloat16 h0 = __float2bfloat16_rn(v0);
    __nv_bfloat16 h1 = __float2bfloat16_rn(v1);
    float l0 = v0 - __bfloat162float(h0);
    float l1 = v1 - __bfloat162float(h1);
    __nv_bfloat162 hp = __halves2bfloat162(h0, h1);
    __nv_bfloat162 lp = __floats2bfloat162_rn(l0, l1);
    hi = *reinterpret_cast<uint32_t*>(&hp);
    lo = *reinterpret_cast<uint32_t*>(&lp);
}

__device__ __forceinline__ void mma_bf16(float& c0, float& c1, float& c2, float& c3,
                                         uint32_t a0, uint32_t a1, uint32_t a2, uint32_t a3,
                                         uint32_t b0, uint32_t b1) {
    asm volatile(
        "mma.sync.aligned.m16n8k16.row.col.f32.bf16.bf16.f32 "
        "{%0,%1,%2,%3}, {%4,%5,%6,%7}, {%8,%9}, {%0,%1,%2,%3};"
        : "+f"(c0), "+f"(c1), "+f"(c2), "+f"(c3)
        : "r"(a0), "r"(a1), "r"(a2), "r"(a3), "r"(b0), "r"(b1));
}

// ---------------- weight prep: fp32 -> packed bf16 hi/lo, tile-shaped [kp][n] ----------------
__global__ void k_prepW0(const float* __restrict__ W) {
    int t = blockIdx.x * blockDim.x + threadIdx.x;   // < 144*128
    int kp = t >> 7, n = t & 127;
    int k0 = 2 * kp, k1 = 2 * kp + 1;
    float v0 = 0.f, v1 = 0.f;
    if (k0 < CIN0) { int kl = (k0 < 256) ? k0 + 3 : k0 - 256; v0 = W[n * CIN0 + kl]; }
    if (k1 < CIN0) { int kl = (k1 < 256) ? k1 + 3 : k1 - 256; v1 = W[n * CIN0 + kl]; }
    uint32_t hi, lo;
    split2_bf16(v0, v1, hi, lo);
    g_W0H[t] = hi; g_W0L[t] = lo;
}

__global__ void k_prepW128(const float* __restrict__ W,
                           uint32_t* __restrict__ WH, uint32_t* __restrict__ WL) {
    int t = blockIdx.x * blockDim.x + threadIdx.x;   // < 64*128
    int kp = t >> 7, n = t & 127;
    float v0 = W[n * 128 + 2 * kp];
    float v1 = W[n * 128 + 2 * kp + 1];
    uint32_t hi, lo;
    split2_bf16(v0, v1, hi, lo);
    WH[t] = hi; WL[t] = lo;
}

// ---------------- stage-1 kernels ----------------

// seed_features [b][c][n] -> g_featT [b][n][c]
__global__ void k_transpose(const float* __restrict__ feat) {
    __shared__ float tile[32][33];
    int b  = blockIdx.z;
    int n0 = blockIdx.x * 32;
    int c0 = blockIdx.y * 32;
    const float* src = feat    + (long long)b * CF * NS;
    float*       dst = g_featT + (long long)b * NS * CF;
#pragma unroll
    for (int r = 0; r < 4; ++r) {
        int c = c0 + threadIdx.y + r * 8;
        tile[threadIdx.y + r * 8][threadIdx.x] = src[c * NS + n0 + threadIdx.x];
    }
    __syncthreads();
#pragma unroll
    for (int r = 0; r < 4; ++r) {
        int n = n0 + threadIdx.y + r * 8;
        dst[n * CF + c0 + threadIdx.x] = tile[threadIdx.x][threadIdx.y + r * 8];
    }
}

// rotate+scale grid -> g_rel, world points -> g_wq
__global__ void k_gridpoints(const float* __restrict__ center,
                             const float* __restrict__ size_,
                             const float* __restrict__ heading) {
    int m = blockIdx.x * blockDim.x + threadIdx.x;
    if (m >= M1) return;
    int g  = m & 63;
    int bk = m >> 6;
    float sx = size_[bk * 3 + 0], sy = size_[bk * 3 + 1], sz = size_[bk * 3 + 2];
    float h  = heading[bk];
    float ch = cosf(h), sh = sinf(h);
    float gx = -1.f + (float)( g >> 4      ) * (2.f / 3.f);
    float gy = -1.f + (float)((g >> 2) & 3 ) * (2.f / 3.f);
    float gz = -1.f + (float)( g       & 3 ) * (2.f / 3.f);
    float ax = gx * sx, ay = gy * sy, az = gz * sz;
    float rx = ax * ch - ay * sh;
    float ry = ax * sh + ay * ch;
    float rz = az;
    g_rel[m * 3 + 0] = rx;
    g_rel[m * 3 + 1] = ry;
    g_rel[m * 3 + 2] = rz;
    g_wq[m * 3 + 0] = rx + center[bk * 3 + 0];
    g_wq[m * 3 + 1] = ry + center[bk * 3 + 1];
    g_wq[m * 3 + 2] = rz + center[bk * 3 + 2];
}

// 3-NN per query over 1024 seeds (seeds cached in SMEM), inverse-distance weights
__global__ void k_threenn(const float* __restrict__ seed_xyz) {
    __shared__ float4 sp[NS];
    int b = blockIdx.x >> 7;
    int q = ((blockIdx.x & 127) << 7) + threadIdx.x;
    for (int i = threadIdx.x; i < NS; i += blockDim.x) {
        float x = seed_xyz[((long long)b * NS + i) * 3 + 0];
        float y = seed_xyz[((long long)b * NS + i) * 3 + 1];
        float z = seed_xyz[((long long)b * NS + i) * 3 + 2];
        sp[i] = make_float4(x, y, z, x * x + y * y + z * z);
    }
    __syncthreads();
    int m = b * QQ + q;
    float qx = g_wq[m * 3 + 0], qy = g_wq[m * 3 + 1], qz = g_wq[m * 3 + 2];
    float qq = qx * qx + qy * qy + qz * qz;
    float d0 = 1e30f, d1 = 1e30f, d2 = 1e30f;
    int   i0 = 0, i1 = 0, i2 = 0;
#pragma unroll 4
    for (int n = 0; n < NS; ++n) {
        float4 p = sp[n];
        float d = qq + p.w - 2.f * (qx * p.x + qy * p.y + qz * p.z);
        if (d < d2) {
            if (d < d1) {
                d2 = d1; i2 = i1;
                if (d < d0) { d1 = d0; i1 = i0; d0 = d; i0 = n; }
                else        { d1 = d;  i1 = n; }
            } else { d2 = d; i2 = n; }
        }
    }
    int ii[3] = {i0, i1, i2};
    float w[3];
#pragma unroll
    for (int j = 0; j < 3; ++j) {
        float4 p = sp[ii[j]];
        float dx = p.x - qx, dy = p.y - qy, dz = p.z - qz;
        float dist = sqrtf(dx * dx + dy * dy + dz * dz);
        w[j] = 1.f / (dist + 1e-8f);
    }
    float inv = 1.f / (w[0] + w[1] + w[2]);
#pragma unroll
    for (int j = 0; j < 3; ++j) {
        g_idx3[m * 3 + j] = ii[j];
        g_w3[m * 3 + j]   = w[j] * inv;
    }
}

// ---- split-bf16 tensor-core GEMM (round-7 structure) with pre-split W copy ----
// C[m,n] = sum_k act(A[m,k]) * W[n,k] + bias[n]
// 128x128 tile, K-chunks of 32, m16n8k16 bf16 MMA, acc += aL*bH + aH*bL + aH*bH.
// 8 warps (2 over M x 4 over N), 2 CTAs/SM, single-buffered, A register-prefetched.
// W arrives pre-split (packed bf16 hi/lo, tile-shaped [kp][n]) -> W build is a pure copy.
// GATHER: layer-0; A gathered on the fly from g_featT (L2-hot) + rel xyz; K=288 padded.
template <bool BNA, bool GATHER, bool POOL, bool STOREC>
__global__ void __launch_bounds__(256, 2)
k_gemm_bf(const float* __restrict__ A, int lda,
          const uint32_t* __restrict__ WHg,
          const uint32_t* __restrict__ WLg,
          const float* __restrict__ bias,
          const float* __restrict__ scl,
          const float* __restrict__ shf,
          float* __restrict__ C,
          float* __restrict__ partOut,
          float* __restrict__ poolOut) {
    __shared__ uint32_t AsH[16][136];
    __shared__ uint32_t AsL[16][136];
    __shared__ uint32_t WsH[16][136];
    __shared__ uint32_t WsL[16][136];
    __shared__ float redS[2][128];
    __shared__ float redQ[2][128];
    __shared__ float redM[2][128];

    const int tid  = threadIdx.x;
    const int lane = tid & 31;
    const int warp = tid >> 5;
    const int g    = lane >> 2;        // 0..7
    const int q    = lane & 3;         // 0..3
    const int wm   = warp & 1;         // 2 warps over M
    const int wn   = warp >> 1;        // 4 warps over N
    const int bm   = blockIdx.x * 128;

    float acc[4][4][4];
#pragma unroll
    for (int i = 0; i < 4; ++i)
#pragma unroll
        for (int j = 0; j < 4; ++j)
#pragma unroll
            for (int r = 0; r < 4; ++r) acc[i][j][r] = 0.f;

    const int ldrow = tid >> 1;         // 0..127
    const int ldkv  = (tid & 1) * 16;   // 0 or 16
    const int kp0   = ldkv / 2;         // 0 or 8
    const int NCH   = GATHER ? (KPH0 / 32) : 4;

    // W copy mapping: 256 threads cover 16 kp rows x 16 n-blocks of 8
    const int wkp = tid & 15;
    const int wn0 = (tid >> 4) * 8;

    // GATHER state (row fixed for the whole k-loop)
    const float *gf0 = nullptr, *gf1 = nullptr, *gf2 = nullptr;
    float gw0 = 0.f, gw1 = 0.f, gw2 = 0.f;
    float grel[3] = {0.f, 0.f, 0.f};
    if (GATHER) {
        const int m = bm + ldrow;
        const int b = m >> 14;
        int i0 = g_idx3[m * 3 + 0], i1 = g_idx3[m * 3 + 1], i2 = g_idx3[m * 3 + 2];
        gw0 = g_w3[m * 3 + 0]; gw1 = g_w3[m * 3 + 1]; gw2 = g_w3[m * 3 + 2];
        gf0 = g_featT + ((long long)b * NS + i0) * CF;
        gf1 = g_featT + ((long long)b * NS + i1) * CF;
        gf2 = g_featT + ((long long)b * NS + i2) * CF;
        grel[0] = g_rel[m * 3 + 0];
        grel[1] = g_rel[m * 3 + 1];
        grel[2] = g_rel[m * 3 + 2];
    }

    float vA[16];
    if (!GATHER) {
        const float* ap = A + (long long)(bm + ldrow) * lda + ldkv;
        float4 u0 = *(const float4*)(ap + 0);
        float4 u1 = *(const float4*)(ap + 4);
        float4 u2 = *(const float4*)(ap + 8);
        float4 u3 = *(const float4*)(ap + 12);
        vA[0]=u0.x; vA[1]=u0.y; vA[2]=u0.z; vA[3]=u0.w;
        vA[4]=u1.x; vA[5]=u1.y; vA[6]=u1.z; vA[7]=u1.w;
        vA[8]=u2.x; vA[9]=u2.y; vA[10]=u2.z; vA[11]=u2.w;
        vA[12]=u3.x; vA[13]=u3.y; vA[14]=u3.z; vA[15]=u3.w;
    }

    for (int ch = 0; ch < NCH; ++ch) {
        const int k0 = ch * 32;
        // ---- build + split A chunk -> SMEM ----
        {
            float v[16];
            if (GATHER) {
                const int kbase = k0 + ldkv;
                if (kbase < 256) {
#pragma unroll
                    for (int r4 = 0; r4 < 4; ++r4) {
                        float4 a  = *(const float4*)(gf0 + kbase + r4 * 4);
                        float4 bq = *(const float4*)(gf1 + kbase + r4 * 4);
                        float4 cq = *(const float4*)(gf2 + kbase + r4 * 4);
                        v[r4 * 4 + 0] = gw0 * a.x + gw1 * bq.x + gw2 * cq.x;
                        v[r4 * 4 + 1] = gw0 * a.y + gw1 * bq.y + gw2 * cq.y;
                        v[r4 * 4 + 2] = gw0 * a.z + gw1 * bq.z + gw2 * cq.z;
                        v[r4 * 4 + 3] = gw0 * a.w + gw1 * bq.w + gw2 * cq.w;
                    }
                } else {
#pragma unroll
                    for (int i = 0; i < 16; ++i) v[i] = 0.f;
                    if (kbase == 256) { v[0] = grel[0]; v[1] = grel[1]; v[2] = grel[2]; }
                }
            } else {
#pragma unroll
                for (int i = 0; i < 16; ++i) v[i] = vA[i];
                if (BNA) {
#pragma unroll
                    for (int i = 0; i < 16; ++i) {
                        int k = k0 + ldkv + i;   // KDIM=128 in BNA mode: always valid
                        v[i] = fmaxf(v[i] * scl[k] + shf[k], 0.f);
                    }
                }
            }
#pragma unroll
            for (int i = 0; i < 8; ++i) {
                uint32_t hi, lo;
                split2_bf16(v[2 * i], v[2 * i + 1], hi, lo);
                AsH[kp0 + i][ldrow] = hi;
                AsL[kp0 + i][ldrow] = lo;
            }
        }
        // ---- W tile: pure copy of pre-split packed bf16 ----
        {
            const uint4* sH = (const uint4*)(WHg + (ch * 16 + wkp) * 128 + wn0);
            const uint4* sL = (const uint4*)(WLg + (ch * 16 + wkp) * 128 + wn0);
            uint4* dH = (uint4*)(&WsH[wkp][wn0]);
            uint4* dL = (uint4*)(&WsL[wkp][wn0]);
            dH[0] = sH[0]; dH[1] = sH[1];
            dL[0] = sL[0]; dL[1] = sL[1];
        }
        __syncthreads();

        // ---- prefetch next A chunk (latency hidden behind MMAs; non-gather only) ----
        if (!GATHER && ch + 1 < NCH) {
            const float* ap = A + (long long)(bm + ldrow) * lda + (k0 + 32) + ldkv;
            float4 u0 = *(const float4*)(ap + 0);
            float4 u1 = *(const float4*)(ap + 4);
            float4 u2 = *(const float4*)(ap + 8);
            float4 u3 = *(const float4*)(ap + 12);
            vA[0]=u0.x; vA[1]=u0.y; vA[2]=u0.z; vA[3]=u0.w;
            vA[4]=u1.x; vA[5]=u1.y; vA[6]=u1.z; vA[7]=u1.w;
            vA[8]=u2.x; vA[9]=u2.y; vA[10]=u2.z; vA[11]=u2.w;
            vA[12]=u3.x; vA[13]=u3.y; vA[14]=u3.z; vA[15]=u3.w;
        }

        // ---- two k16 steps per chunk ----
#pragma unroll
        for (int kb = 0; kb < 16; kb += 8) {
            uint32_t bH[4][2], bL[4][2];
#pragma unroll
            for (int nt = 0; nt < 4; ++nt) {
                int nbase = wn * 32 + nt * 8;
                bH[nt][0] = WsH[kb + q    ][nbase + g];
                bH[nt][1] = WsH[kb + q + 4][nbase + g];
                bL[nt][0] = WsL[kb + q    ][nbase + g];
                bL[nt][1] = WsL[kb + q + 4][nbase + g];
            }
#pragma unroll
            for (int mt = 0; mt < 4; ++mt) {
                int mbase = wm * 64 + mt * 16;
                uint32_t aH0 = AsH[kb + q    ][mbase + g    ];
                uint32_t aH1 = AsH[kb + q    ][mbase + g + 8];
                uint32_t aH2 = AsH[kb + q + 4][mbase + g    ];
                uint32_t aH3 = AsH[kb + q + 4][mbase + g + 8];
                uint32_t aL0 = AsL[kb + q    ][mbase + g    ];
                uint32_t aL1 = AsL[kb + q    ][mbase + g + 8];
                uint32_t aL2 = AsL[kb + q + 4][mbase + g    ];
                uint32_t aL3 = AsL[kb + q + 4][mbase + g + 8];
#pragma unroll
                for (int nt = 0; nt < 4; ++nt) {
                    mma_bf16(acc[mt][nt][0], acc[mt][nt][1], acc[mt][nt][2], acc[mt][nt][3],
                             aL0, aL1, aL2, aL3, bH[nt][0], bH[nt][1]);
                    mma_bf16(acc[mt][nt][0], acc[mt][nt][1], acc[mt][nt][2], acc[mt][nt][3],
                             aH0, aH1, aH2, aH3, bL[nt][0], bL[nt][1]);
                    mma_bf16(acc[mt][nt][0], acc[mt][nt][1], acc[mt][nt][2], acc[mt][nt][3],
                             aH0, aH1, aH2, aH3, bH[nt][0], bH[nt][1]);
                }
            }
        }
        __syncthreads();
    }

    // ---- fused epilogue: bias, optional store, BN stats partials, optional maxpool ----
    float bsv[4][2];
#pragma unroll
    for (int nt = 0; nt < 4; ++nt) {
        int col = wn * 32 + nt * 8 + q * 2;
        bsv[nt][0] = bias[col];
        bsv[nt][1] = bias[col + 1];
    }
    float s[4][2], s2[4][2], mx[4][2];
#pragma unroll
    for (int nt = 0; nt < 4; ++nt)
#pragma unroll
        for (int j = 0; j < 2; ++j) { s[nt][j] = 0.f; s2[nt][j] = 0.f; mx[nt][j] = -1e30f; }

#pragma unroll
    for (int mt = 0; mt < 4; ++mt) {
#pragma unroll
        for (int nt = 0; nt < 4; ++nt) {
            float v0 = acc[mt][nt][0] + bsv[nt][0];
            float v1 = acc[mt][nt][1] + bsv[nt][1];
            float v2 = acc[mt][nt][2] + bsv[nt][0];
            float v3 = acc[mt][nt][3] + bsv[nt][1];
            if (STOREC) {
                int col = wn * 32 + nt * 8 + q * 2;
                int r0  = bm + wm * 64 + mt * 16 + g;
                *(float2*)(C + (long long)r0 * 128 + col)       = make_float2(v0, v1);
                *(float2*)(C + (long long)(r0 + 8) * 128 + col) = make_float2(v2, v3);
            }
            s [nt][0] += v0 + v2;       s [nt][1] += v1 + v3;
            s2[nt][0] += v0 * v0 + v2 * v2;
            s2[nt][1] += v1 * v1 + v3 * v3;
            if (POOL) {
                mx[nt][0] = fmaxf(mx[nt][0], fmaxf(v0, v2));
                mx[nt][1] = fmaxf(mx[nt][1], fmaxf(v1, v3));
            }
        }
    }
#pragma unroll
    for (int nt = 0; nt < 4; ++nt)
#pragma unroll
        for (int j = 0; j < 2; ++j) {
#pragma unroll
            for (int mask = 4; mask <= 16; mask <<= 1) {
                s [nt][j] += __shfl_xor_sync(0xffffffff, s [nt][j], mask);
                s2[nt][j] += __shfl_xor_sync(0xffffffff, s2[nt][j], mask);
                if (POOL)
                    mx[nt][j] = fmaxf(mx[nt][j], __shfl_xor_sync(0xffffffff, mx[nt][j], mask));
            }
        }
    if (g == 0) {
#pragma unroll
        for (int nt = 0; nt < 4; ++nt)
#pragma unroll
            for (int j = 0; j < 2; ++j) {
                int col = wn * 32 + nt * 8 + q * 2 + j;
                redS[wm][col] = s[nt][j];
                redQ[wm][col] = s2[nt][j];
                if (POOL) redM[wm][col] = mx[nt][j];
            }
    }
    __syncthreads();
    if (tid < 128) {
        partOut[blockIdx.x * 256 + tid]       = redS[0][tid] + redS[1][tid];
        partOut[blockIdx.x * 256 + 128 + tid] = redQ[0][tid] + redQ[1][tid];
    }
    if (POOL) {
        poolOut[(blockIdx.x * 2 + (tid >> 7)) * 128 + (tid & 127)] = redM[tid >> 7][tid & 127];
    }
}

// reduce 512 per-CTA partials -> folded BN scale/shift (1 block, 512 threads)
__global__ void k_bnfin512(float Minv,
                           const float* __restrict__ gamma,
                           const float* __restrict__ beta,
                           int slot) {
    __shared__ float rs[4][128], rq[4][128];
    int c  = threadIdx.x & 127;
    int sl = threadIdx.x >> 7;
    float s = 0.f, q = 0.f;
    for (int b = sl * 128; b < sl * 128 + 128; ++b) {
        s += g_part[b * 256 + c];
        q += g_part[b * 256 + 128 + c];
    }
    rs[sl][c] = s; rq[sl][c] = q;
    __syncthreads();
    if (threadIdx.x < 128) {
        float S = rs[0][c] + rs[1][c] + rs[2][c] + rs[3][c];
        float Q = rq[0][c] + rq[1][c] + rq[2][c] + rq[3][c];
        float mean = S * Minv;
        float var  = Q * Minv - mean * mean;
        float rstd = rsqrtf(var + 1e-5f);
        float sc   = gamma[c] * rstd;
        g_scale[slot * 128 + c] = sc;
        g_shift[slot * 128 + c] = beta[c] - mean * sc;
    }
}

// -------- fp32 SIMT GEMM for the tiny FC layers: 64x128 tile, grid=16 --------
template <int KDIM, bool BNA>
__global__ void __launch_bounds__(256)
k_gemm64(const float* __restrict__ A, int lda,
         const float* __restrict__ W,
         const float* __restrict__ bias,
         const float* __restrict__ scl,
         const float* __restrict__ shf,
         float* __restrict__ C) {
    __shared__ float As[16][64];
    __shared__ float Ws2[16][128];
    int tid = threadIdx.x;
    int bm  = blockIdx.x * 64;
    int tx  = tid & 15, ty = tid >> 4;   // tx: 16 col-blocks of 8, ty: 16 row-blocks of 4
    float acc[4][8];
#pragma unroll
    for (int i = 0; i < 4; ++i)
#pragma unroll
        for (int j = 0; j < 8; ++j) acc[i][j] = 0.f;

    const int KT = KDIM / 16;
    for (int kt = 0; kt < KT; ++kt) {
        int k0 = kt * 16;
        // A tile: 64 rows x 16 k, one float4 per thread
        {
            int row = tid >> 2;
            int kv  = (tid & 3) * 4;
            int k   = k0 + kv;
            float4 v = *reinterpret_cast<const float4*>(A + (long long)(bm + row) * lda + k);
            if (BNA) {
                v.x = fmaxf(v.x * scl[k + 0] + shf[k + 0], 0.f);
                v.y = fmaxf(v.y * scl[k + 1] + shf[k + 1], 0.f);
                v.z = fmaxf(v.z * scl[k + 2] + shf[k + 2], 0.f);
                v.w = fmaxf(v.w * scl[k + 3] + shf[k + 3], 0.f);
            }
            As[kv + 0][row] = v.x;
            As[kv + 1][row] = v.y;
            As[kv + 2][row] = v.z;
            As[kv + 3][row] = v.w;
        }
        // W tile: 128 n x 16 k
        {
            int n  = tid >> 1;
            int kb = (tid & 1) * 8;
#pragma unroll
            for (int i = 0; i < 8; ++i)
                Ws2[kb + i][n] = W[n * KDIM + k0 + kb + i];
        }
        __syncthreads();
#pragma unroll
        for (int kk = 0; kk < 16; ++kk) {
            float a[4], w8[8];
            *reinterpret_cast<float4*>(&a[0])  = *reinterpret_cast<const float4*>(&As[kk][ty * 4]);
            *reinterpret_cast<float4*>(&w8[0]) = *reinterpret_cast<const float4*>(&Ws2[kk][tx * 8]);
            *reinterpret_cast<float4*>(&w8[4]) = *reinterpret_cast<const float4*>(&Ws2[kk][tx * 8 + 4]);
#pragma unroll
            for (int i = 0; i < 4; ++i)
#pragma unroll
                for (int j = 0; j < 8; ++j) acc[i][j] += a[i] * w8[j];
        }
        __syncthreads();
    }
    float bv[8];
#pragma unroll
    for (int j = 0; j < 8; ++j) bv[j] = bias[tx * 8 + j];
#pragma unroll
    for (int i = 0; i < 4; ++i) {
        long long off = (long long)(bm + ty * 4 + i) * 128 + tx * 8;
        float4 o0 = make_float4(acc[i][0] + bv[0], acc[i][1] + bv[1],
                                acc[i][2] + bv[2], acc[i][3] + bv[3]);
        float4 o1 = make_float4(acc[i][4] + bv[4], acc[i][5] + bv[5],
                                acc[i][6] + bv[6], acc[i][7] + bv[7]);
        *reinterpret_cast<float4*>(C + off)     = o0;
        *reinterpret_cast<float4*>(C + off + 4) = o1;
    }
}

// deterministic two-stage BN stats for FC layers (small)
__global__ void k_stats(const float* __restrict__ Y, int M) {
    __shared__ float ss[256], sq[256];
    int c    = threadIdx.x & 127;
    int half = threadIdx.x >> 7;
    int rowsPer = M / gridDim.x;
    int r0 = blockIdx.x * rowsPer;
    float s = 0.f, s2 = 0.f;
    for (int r = r0 + half; r < r0 + rowsPer; r += 2) {
        float v = Y[(long long)r * 128 + c];
        s += v; s2 += v * v;
    }
    ss[threadIdx.x] = s; sq[threadIdx.x] = s2;
    __syncthreads();
    if (threadIdx.x < 128) {
        g_part[blockIdx.x * 256 + threadIdx.x]       = ss[threadIdx.x] + ss[threadIdx.x + 128];
        g_part[blockIdx.x * 256 + 128 + threadIdx.x] = sq[threadIdx.x] + sq[threadIdx.x + 128];
    }
}

__global__ void k_bnfin(int NB, float Minv,
                        const float* __restrict__ gamma,
                        const float* __restrict__ beta,
                        int slot) {
    int c = threadIdx.x;
    float s = 0.f, s2 = 0.f;
    for (int b = 0; b < NB; ++b) {
        s  += g_part[b * 256 + c];
        s2 += g_part[b * 256 + 128 + c];
    }
    float mean = s * Minv;
    float var  = s2 * Minv - mean * mean;
    float rstd = rsqrtf(var + 1e-5f);
    float sc   = gamma[c] * rstd;
    g_scale[slot * 128 + c] = sc;
    g_shift[slot * 128 + c] = beta[c] - mean * sc;
}

// BN5+ReLU on N2, project to the last 18 of 77 output channels
__global__ void k_final(const float* __restrict__ cw3,
                        const float* __restrict__ cb3,
                        float* __restrict__ out) {
    int t = blockIdx.x * blockDim.x + threadIdx.x;
    if (t >= MFC * IOUS) return;
    int j   = t % IOUS;
    int row = t / IOUS;
    int o   = (OUTC - IOUS) + j;
    const float* wrow = cw3 + o * 128;
    const float* x    = g_N2 + row * 128;
    float acc = cb3[o];
#pragma unroll 8
    for (int i = 0; i < 128; ++i) {
        float v = fmaxf(x[i] * g_scale[4 * 128 + i] + g_shift[4 * 128 + i], 0.f);
        acc += v * wrow[i];
    }
    out[t] = acc;
}

// ---------------- launcher ----------------
extern "C" void kernel_launch(void* const* d_in, const int* in_sizes, int n_in,
                              void* d_out, int out_size) {
    const float* center  = (const float*)d_in[0];
    const float* size_   = (const float*)d_in[1];
    const float* heading = (const float*)d_in[2];
    const float* sxyz    = (const float*)d_in[3];
    const float* sfeat   = (const float*)d_in[4];
    const float* w0  = (const float*)d_in[5];
    const float* b0  = (const float*)d_in[6];
    const float* g0  = (const float*)d_in[7];
    const float* be0 = (const float*)d_in[8];
    const float* w1  = (const float*)d_in[9];
    const float* b1  = (const float*)d_in[10];
    const float* g1  = (const float*)d_in[11];
    const float* be1 = (const float*)d_in[12];
    const float* w2  = (const float*)d_in[13];
    const float* b2  = (const float*)d_in[14];
    const float* g2  = (const float*)d_in[15];
    const float* be2 = (const float*)d_in[16];
    const float* cw1 = (const float*)d_in[17];
    const float* cb1 = (const float*)d_in[18];
    const float* g3  = (const float*)d_in[19];
    const float* be3 = (const float*)d_in[20];
    const float* cw2 = (const float*)d_in[21];
    const float* cb2 = (const float*)d_in[22];
    const float* g4  = (const float*)d_in[23];
    const float* be4 = (const float*)d_in[24];
    const float* cw3 = (const float*)d_in[25];
    const float* cb3 = (const float*)d_in[26];
    float* out = (float*)d_out;

    void *pY1, *pY2, *pF, *pN1, *pN2, *pSC, *pSH, *pPart;
    void *pW0H, *pW0L, *pW1H, *pW1L, *pW2H, *pW2L;
    cudaGetSymbolAddress(&pY1, g_Y1);
    cudaGetSymbolAddress(&pY2, g_Y2);
    cudaGetSymbolAddress(&pF,  g_F);
    cudaGetSymbolAddress(&pN1, g_N1);
    cudaGetSymbolAddress(&pN2, g_N2);
    cudaGetSymbolAddress(&pSC, g_scale);
    cudaGetSymbolAddress(&pSH, g_shift);
    cudaGetSymbolAddress(&pPart, g_part);
    cudaGetSymbolAddress(&pW0H, g_W0H);
    cudaGetSymbolAddress(&pW0L, g_W0L);
    cudaGetSymbolAddress(&pW1H, g_W1H);
    cudaGetSymbolAddress(&pW1L, g_W1L);
    cudaGetSymbolAddress(&pW2H, g_W2H);
    cudaGetSymbolAddress(&pW2L, g_W2L);
    float* Y1 = (float*)pY1;
    float* Y2 = (float*)pY2;
    float* F  = (float*)pF;
    float* N1 = (float*)pN1;
    float* N2 = (float*)pN2;
    float* SC = (float*)pSC;
    float* SH = (float*)pSH;
    float* PART = (float*)pPart;
    uint32_t* W0H = (uint32_t*)pW0H; uint32_t* W0L = (uint32_t*)pW0L;
    uint32_t* W1H = (uint32_t*)pW1H; uint32_t* W1L = (uint32_t*)pW1L;
    uint32_t* W2H = (uint32_t*)pW2H; uint32_t* W2L = (uint32_t*)pW2L;

    // stage 0: weight pre-split (tiny)
    k_prepW0<<<(144 * 128) / 256, 256>>>(w0);
    k_prepW128<<<(64 * 128) / 256, 256>>>(w1, W1H, W1L);
    k_prepW128<<<(64 * 128) / 256, 256>>>(w2, W2H, W2L);

    // stage 1: geometry + 3-NN (interp fused into GEMM0's A-loader)
    k_transpose<<<dim3(NS / 32, CF / 32, BB), dim3(32, 8)>>>(sfeat);
    k_gridpoints<<<M1 / 256, 256>>>(center, size_, heading);
    k_threenn<<<BB * 128, 128>>>(sxyz);

    // stage 2: SharedMLP on tensor cores (round-7 structure, pre-split W).
    k_gemm_bf<false, true, false, true><<<M1 / 128, 256>>>(
        nullptr, 0, W0H, W0L, b0, nullptr, nullptr, Y1, PART, nullptr);
    k_bnfin512<<<1, 512>>>(1.f / M1, g0, be0, 0);

    k_gemm_bf<true, false, false, true><<<M1 / 128, 256>>>(
        Y1, HH, W1H, W1L, b1, SC + 0 * 128, SH + 0 * 128, Y2, PART, nullptr);
    k_bnfin512<<<1, 512>>>(1.f / M1, g1, be1, 1);

    k_gemm_bf<true, false, true, false><<<M1 / 128, 256>>>(
        Y2, HH, W2H, W2L, b2, SC + 1 * 128, SH + 1 * 128, nullptr, PART, F);
    k_bnfin512<<<1, 512>>>(1.f / M1, g2, be2, 2);

    // stage 3: FC head (fp32 SIMT, 64-row tiles -> grid 16). FC1 applies BN3+ReLU.
    k_gemm64<HH, true><<<MFC / 64, 256>>>(F, HH, cw1, cb1, SC + 2 * 128, SH + 2 * 128, N1);
    k_stats<<<8, 256>>>(N1, MFC);
    k_bnfin<<<1, 128>>>(8, 1.f / MFC, g3, be3, 3);

    k_gemm64<HH, true><<<MFC / 64, 256>>>(N1, HH, cw2, cb2, SC + 3 * 128, SH + 3 * 128, N2);
    k_stats<<<8, 256>>>(N2, MFC);
    k_bnfin<<<1, 128>>>(8, 1.f / MFC, g4, be4, 4);

    k_final<<<(MFC * IOUS + 255) / 256, 256>>>(cw3, cb3, out);
}

// round 10
// speedup vs baseline: 1.2378x; 1.2237x over previous
#include <cuda_runtime.h>
#include <cuda_bf16.h>
#include <math.h>
#include <stdint.h>

// ---------------- problem constants ----------------
static constexpr int BB   = 4;
static constexpr int KK   = 256;
static constexpr int NS   = 1024;      // seeds
static constexpr int CF   = 256;       // seed feature channels
static constexpr int GPP  = 64;        // grid points per proposal
static constexpr int QQ   = KK * GPP;  // 16384 queries per batch
static constexpr int M1   = BB * QQ;   // 65536 rows for conv layers
static constexpr int CIN0 = CF + 3;    // 259 logical input channels
static constexpr int KPH0 = 288;       // padded logical K for layer0 (9 chunks of 32)
static constexpr int HH   = 128;
static constexpr int MFC  = BB * KK;   // 1024 rows for FC layers
static constexpr int IOUS = 18;
static constexpr int OUTC = 77;

// ---------------- scratch (static device memory; no allocations) ----------------
__device__ float g_wq[M1 * 3];
__device__ float g_rel[M1 * 3];
__device__ float g_featT[BB * NS * CF];        // [b][n][c]
__device__ int   g_idx3[M1 * 3];
__device__ float g_w3[M1 * 3];
__device__ float g_Y1[(long long)M1 * HH];
__device__ float g_Y2[(long long)M1 * HH];
__device__ float g_F [MFC * HH];               // RAW maxpool output (pre-BN3)
__device__ float g_N1[MFC * HH];
__device__ float g_N2[MFC * HH];
__device__ float g_part[512 * 256];            // per-CTA partial BN stats
__device__ float g_scale[5 * 128];
__device__ float g_shift[5 * 128];

// ---------------- small helpers ----------------
// split two fp32 values into packed-bf16 (hi pair, lo pair); word = {k_even, k_odd}
__device__ __forceinline__ void split2_bf16(float v0, float v1, uint32_t& hi, uint32_t& lo) {
    __nv_bfloat16 h0 = __float2bfloat16_rn(v0);
    __nv_bfloat16 h1 = __float2bfloat16_rn(v1);
    float l0 = v0 - __bfloat162float(h0);
    float l1 = v1 - __bfloat162float(h1);
    __nv_bfloat162 hp = __halves2bfloat162(h0, h1);
    __nv_bfloat162 lp = __floats2bfloat162_rn(l0, l1);
    hi = *reinterpret_cast<uint32_t*>(&hp);
    lo = *reinterpret_cast<uint32_t*>(&lp);
}

__device__ __forceinline__ void mma_bf16(float& c0, float& c1, float& c2, float& c3,
                                         uint32_t a0, uint32_t a1, uint32_t a2, uint32_t a3,
                                         uint32_t b0, uint32_t b1) {
    asm volatile(
        "mma.sync.aligned.m16n8k16.row.col.f32.bf16.bf16.f32 "
        "{%0,%1,%2,%3}, {%4,%5,%6,%7}, {%8,%9}, {%0,%1,%2,%3};"
        : "+f"(c0), "+f"(c1), "+f"(c2), "+f"(c3)
        : "r"(a0), "r"(a1), "r"(a2), "r"(a3), "r"(b0), "r"(b1));
}

// ---------------- stage-1 kernels ----------------

// seed_features [b][c][n] -> g_featT [b][n][c]
__global__ void k_transpose(const float* __restrict__ feat) {
    __shared__ float tile[32][33];
    int b  = blockIdx.z;
    int n0 = blockIdx.x * 32;
    int c0 = blockIdx.y * 32;
    const float* src = feat    + (long long)b * CF * NS;
    float*       dst = g_featT + (long long)b * NS * CF;
#pragma unroll
    for (int r = 0; r < 4; ++r) {
        int c = c0 + threadIdx.y + r * 8;
        tile[threadIdx.y + r * 8][threadIdx.x] = src[c * NS + n0 + threadIdx.x];
    }
    __syncthreads();
#pragma unroll
    for (int r = 0; r < 4; ++r) {
        int n = n0 + threadIdx.y + r * 8;
        dst[n * CF + c0 + threadIdx.x] = tile[threadIdx.x][threadIdx.y + r * 8];
    }
}

// rotate+scale grid -> g_rel, world points -> g_wq
__global__ void k_gridpoints(const float* __restrict__ center,
                             const float* __restrict__ size_,
                             const float* __restrict__ heading) {
    int m = blockIdx.x * blockDim.x + threadIdx.x;
    if (m >= M1) return;
    int g  = m & 63;
    int bk = m >> 6;
    float sx = size_[bk * 3 + 0], sy = size_[bk * 3 + 1], sz = size_[bk * 3 + 2];
    float h  = heading[bk];
    float ch = cosf(h), sh = sinf(h);
    float gx = -1.f + (float)( g >> 4      ) * (2.f / 3.f);
    float gy = -1.f + (float)((g >> 2) & 3 ) * (2.f / 3.f);
    float gz = -1.f + (float)( g       & 3 ) * (2.f / 3.f);
    float ax = gx * sx, ay = gy * sy, az = gz * sz;
    float rx = ax * ch - ay * sh;
    float ry = ax * sh + ay * ch;
    float rz = az;
    g_rel[m * 3 + 0] = rx;
    g_rel[m * 3 + 1] = ry;
    g_rel[m * 3 + 2] = rz;
    g_wq[m * 3 + 0] = rx + center[bk * 3 + 0];
    g_wq[m * 3 + 1] = ry + center[bk * 3 + 1];
    g_wq[m * 3 + 2] = rz + center[bk * 3 + 2];
}

// 3-NN per query over 1024 seeds (seeds cached in SMEM), inverse-distance weights
__global__ void k_threenn(const float* __restrict__ seed_xyz) {
    __shared__ float4 sp[NS];
    int b = blockIdx.x >> 7;
    int q = ((blockIdx.x & 127) << 7) + threadIdx.x;
    for (int i = threadIdx.x; i < NS; i += blockDim.x) {
        float x = seed_xyz[((long long)b * NS + i) * 3 + 0];
        float y = seed_xyz[((long long)b * NS + i) * 3 + 1];
        float z = seed_xyz[((long long)b * NS + i) * 3 + 2];
        sp[i] = make_float4(x, y, z, x * x + y * y + z * z);
    }
    __syncthreads();
    int m = b * QQ + q;
    float qx = g_wq[m * 3 + 0], qy = g_wq[m * 3 + 1], qz = g_wq[m * 3 + 2];
    float qq = qx * qx + qy * qy + qz * qz;
    float d0 = 1e30f, d1 = 1e30f, d2 = 1e30f;
    int   i0 = 0, i1 = 0, i2 = 0;
    for (int n = 0; n < NS; ++n) {
        float4 p = sp[n];
        float d = qq + p.w - 2.f * (qx * p.x + qy * p.y + qz * p.z);
        if (d < d2) {
            if (d < d1) {
                d2 = d1; i2 = i1;
                if (d < d0) { d1 = d0; i1 = i0; d0 = d; i0 = n; }
                else        { d1 = d;  i1 = n; }
            } else { d2 = d; i2 = n; }
        }
    }
    int ii[3] = {i0, i1, i2};
    float w[3];
#pragma unroll
    for (int j = 0; j < 3; ++j) {
        float4 p = sp[ii[j]];
        float dx = p.x - qx, dy = p.y - qy, dz = p.z - qz;
        float dist = sqrtf(dx * dx + dy * dy + dz * dz);
        w[j] = 1.f / (dist + 1e-8f);
    }
    float inv = 1.f / (w[0] + w[1] + w[2]);
#pragma unroll
    for (int j = 0; j < 3; ++j) {
        g_idx3[m * 3 + j] = ii[j];
        g_w3[m * 3 + j]   = w[j] * inv;
    }
}

// ---- split-bf16 tensor-core GEMM with fused epilogue (round-7 structure, verbatim) ----
// C[m,n] = sum_k act(A[m,k]) * W[n,k] + bias[n]
// 128x128 tile, K-chunks of 32, m16n8k16 bf16 MMA, acc += aL*bH + aH*bL + aH*bH.
// 8 warps (2 over M x 4 over N), 2 CTAs/SM, single-buffered, A register-prefetched.
// GATHER: layer-0 mode. A gathered on the fly from g_featT (L2-hot) + rel xyz.
template <int KDIM, bool BNA, bool GATHER, bool POOL, bool STOREC>
__global__ void __launch_bounds__(256, 2)
k_gemm_bf(const float* __restrict__ A, int lda,
          const float* __restrict__ W,
          const float* __restrict__ bias,
          const float* __restrict__ scl,
          const float* __restrict__ shf,
          float* __restrict__ C,
          float* __restrict__ partOut,
          float* __restrict__ poolOut) {
    __shared__ uint32_t AsH[16][136];
    __shared__ uint32_t AsL[16][136];
    __shared__ uint32_t WsH[16][136];
    __shared__ uint32_t WsL[16][136];
    __shared__ float redS[2][128];
    __shared__ float redQ[2][128];
    __shared__ float redM[2][128];

    const int tid  = threadIdx.x;
    const int lane = tid & 31;
    const int warp = tid >> 5;
    const int g    = lane >> 2;        // 0..7
    const int q    = lane & 3;         // 0..3
    const int wm   = warp & 1;         // 2 warps over M
    const int wn   = warp >> 1;        // 4 warps over N
    const int bm   = blockIdx.x * 128;

    float acc[4][4][4];
#pragma unroll
    for (int i = 0; i < 4; ++i)
#pragma unroll
        for (int j = 0; j < 4; ++j)
#pragma unroll
            for (int r = 0; r < 4; ++r) acc[i][j][r] = 0.f;

    const int ldrow = tid >> 1;         // 0..127
    const int ldkv  = (tid & 1) * 16;   // 0 or 16
    const int kp0   = ldkv / 2;         // 0 or 8
    const int NCH   = GATHER ? (KPH0 / 32) : 4;

    // GATHER state (row fixed for the whole k-loop)
    const float *gf0 = nullptr, *gf1 = nullptr, *gf2 = nullptr;
    float gw0 = 0.f, gw1 = 0.f, gw2 = 0.f;
    float grel[3] = {0.f, 0.f, 0.f};
    if (GATHER) {
        const int m = bm + ldrow;
        const int b = m >> 14;
        int i0 = g_idx3[m * 3 + 0], i1 = g_idx3[m * 3 + 1], i2 = g_idx3[m * 3 + 2];
        gw0 = g_w3[m * 3 + 0]; gw1 = g_w3[m * 3 + 1]; gw2 = g_w3[m * 3 + 2];
        gf0 = g_featT + ((long long)b * NS + i0) * CF;
        gf1 = g_featT + ((long long)b * NS + i1) * CF;
        gf2 = g_featT + ((long long)b * NS + i2) * CF;
        grel[0] = g_rel[m * 3 + 0];
        grel[1] = g_rel[m * 3 + 1];
        grel[2] = g_rel[m * 3 + 2];
    }

    float vA[16];
    if (!GATHER) {
        const float* ap = A + (long long)(bm + ldrow) * lda + ldkv;
        float4 u0 = *(const float4*)(ap + 0);
        float4 u1 = *(const float4*)(ap + 4);
        float4 u2 = *(const float4*)(ap + 8);
        float4 u3 = *(const float4*)(ap + 12);
        vA[0]=u0.x; vA[1]=u0.y; vA[2]=u0.z; vA[3]=u0.w;
        vA[4]=u1.x; vA[5]=u1.y; vA[6]=u1.z; vA[7]=u1.w;
        vA[8]=u2.x; vA[9]=u2.y; vA[10]=u2.z; vA[11]=u2.w;
        vA[12]=u3.x; vA[13]=u3.y; vA[14]=u3.z; vA[15]=u3.w;
    }

    for (int ch = 0; ch < NCH; ++ch) {
        const int k0 = ch * 32;
        // ---- build + split A chunk -> SMEM ----
        {
            float v[16];
            if (GATHER) {
                const int kbase = k0 + ldkv;
                if (kbase < 256) {
#pragma unroll
                    for (int r4 = 0; r4 < 4; ++r4) {
                        float4 a  = *(const float4*)(gf0 + kbase + r4 * 4);
                        float4 bq = *(const float4*)(gf1 + kbase + r4 * 4);
                        float4 cq = *(const float4*)(gf2 + kbase + r4 * 4);
                        v[r4 * 4 + 0] = gw0 * a.x + gw1 * bq.x + gw2 * cq.x;
                        v[r4 * 4 + 1] = gw0 * a.y + gw1 * bq.y + gw2 * cq.y;
                        v[r4 * 4 + 2] = gw0 * a.z + gw1 * bq.z + gw2 * cq.z;
                        v[r4 * 4 + 3] = gw0 * a.w + gw1 * bq.w + gw2 * cq.w;
                    }
                } else {
#pragma unroll
                    for (int i = 0; i < 16; ++i) v[i] = 0.f;
                    if (kbase == 256) { v[0] = grel[0]; v[1] = grel[1]; v[2] = grel[2]; }
                }
            } else {
#pragma unroll
                for (int i = 0; i < 16; ++i) v[i] = vA[i];
                if (BNA) {
#pragma unroll
                    for (int i = 0; i < 16; ++i) {
                        int k = k0 + ldkv + i;   // KDIM=128 in BNA mode: always valid
                        v[i] = fmaxf(v[i] * scl[k] + shf[k], 0.f);
                    }
                }
            }
#pragma unroll
            for (int i = 0; i < 8; ++i) {
                uint32_t hi, lo;
                split2_bf16(v[2 * i], v[2 * i + 1], hi, lo);
                AsH[kp0 + i][ldrow] = hi;
                AsL[kp0 + i][ldrow] = lo;
            }
        }
        // ---- W tile -> SMEM (inline split; W is L2-hot) ----
        {
            const int n = ldrow;
            float v[16];
            if (GATHER) {
                // layer-0 W permutation: logical col kl for phys k
#pragma unroll
                for (int i = 0; i < 16; ++i) {
                    int k = k0 + ldkv + i;
                    v[i] = 0.f;
                    if (k < KDIM) {
                        int kl = (k < 256) ? (k + 3) : (k - 256);
                        v[i] = W[n * KDIM + kl];
                    }
                }
            } else {
                const float* wp = W + (long long)n * KDIM + k0 + ldkv;
                float4 u0 = *(const float4*)(wp + 0);
                float4 u1 = *(const float4*)(wp + 4);
                float4 u2 = *(const float4*)(wp + 8);
                float4 u3 = *(const float4*)(wp + 12);
                v[0]=u0.x; v[1]=u0.y; v[2]=u0.z; v[3]=u0.w;
                v[4]=u1.x; v[5]=u1.y; v[6]=u1.z; v[7]=u1.w;
                v[8]=u2.x; v[9]=u2.y; v[10]=u2.z; v[11]=u2.w;
                v[12]=u3.x; v[13]=u3.y; v[14]=u3.z; v[15]=u3.w;
            }
#pragma unroll
            for (int i = 0; i < 8; ++i) {
                uint32_t hi, lo;
                split2_bf16(v[2 * i], v[2 * i + 1], hi, lo);
                WsH[kp0 + i][ldrow] = hi;
                WsL[kp0 + i][ldrow] = lo;
            }
        }
        __syncthreads();

        // ---- prefetch next A chunk (latency hidden behind MMAs; non-gather only) ----
        if (!GATHER && ch + 1 < NCH) {
            const float* ap = A + (long long)(bm + ldrow) * lda + (k0 + 32) + ldkv;
            float4 u0 = *(const float4*)(ap + 0);
            float4 u1 = *(const float4*)(ap + 4);
            float4 u2 = *(const float4*)(ap + 8);
            float4 u3 = *(const float4*)(ap + 12);
            vA[0]=u0.x; vA[1]=u0.y; vA[2]=u0.z; vA[3]=u0.w;
            vA[4]=u1.x; vA[5]=u1.y; vA[6]=u1.z; vA[7]=u1.w;
            vA[8]=u2.x; vA[9]=u2.y; vA[10]=u2.z; vA[11]=u2.w;
            vA[12]=u3.x; vA[13]=u3.y; vA[14]=u3.z; vA[15]=u3.w;
        }

        // ---- two k16 steps per chunk ----
#pragma unroll
        for (int kb = 0; kb < 16; kb += 8) {
            uint32_t bH[4][2], bL[4][2];
#pragma unroll
            for (int nt = 0; nt < 4; ++nt) {
                int nbase = wn * 32 + nt * 8;
                bH[nt][0] = WsH[kb + q    ][nbase + g];
                bH[nt][1] = WsH[kb + q + 4][nbase + g];
                bL[nt][0] = WsL[kb + q    ][nbase + g];
                bL[nt][1] = WsL[kb + q + 4][nbase + g];
            }
#pragma unroll
            for (int mt = 0; mt < 4; ++mt) {
                int mbase = wm * 64 + mt * 16;
                uint32_t aH0 = AsH[kb + q    ][mbase + g    ];
                uint32_t aH1 = AsH[kb + q    ][mbase + g + 8];
                uint32_t aH2 = AsH[kb + q + 4][mbase + g    ];
                uint32_t aH3 = AsH[kb + q + 4][mbase + g + 8];
                uint32_t aL0 = AsL[kb + q    ][mbase + g    ];
                uint32_t aL1 = AsL[kb + q    ][mbase + g + 8];
                uint32_t aL2 = AsL[kb + q + 4][mbase + g    ];
                uint32_t aL3 = AsL[kb + q + 4][mbase + g + 8];
#pragma unroll
                for (int nt = 0; nt < 4; ++nt) {
                    mma_bf16(acc[mt][nt][0], acc[mt][nt][1], acc[mt][nt][2], acc[mt][nt][3],
                             aL0, aL1, aL2, aL3, bH[nt][0], bH[nt][1]);
                    mma_bf16(acc[mt][nt][0], acc[mt][nt][1], acc[mt][nt][2], acc[mt][nt][3],
                             aH0, aH1, aH2, aH3, bL[nt][0], bL[nt][1]);
                    mma_bf16(acc[mt][nt][0], acc[mt][nt][1], acc[mt][nt][2], acc[mt][nt][3],
                             aH0, aH1, aH2, aH3, bH[nt][0], bH[nt][1]);
                }
            }
        }
        __syncthreads();
    }

    // ---- fused epilogue: bias, optional store, BN stats partials, optional maxpool ----
    float bsv[4][2];
#pragma unroll
    for (int nt = 0; nt < 4; ++nt) {
        int col = wn * 32 + nt * 8 + q * 2;
        bsv[nt][0] = bias[col];
        bsv[nt][1] = bias[col + 1];
    }
    float s[4][2], s2[4][2], mx[4][2];
#pragma unroll
    for (int nt = 0; nt < 4; ++nt)
#pragma unroll
        for (int j = 0; j < 2; ++j) { s[nt][j] = 0.f; s2[nt][j] = 0.f; mx[nt][j] = -1e30f; }

#pragma unroll
    for (int mt = 0; mt < 4; ++mt) {
#pragma unroll
        for (int nt = 0; nt < 4; ++nt) {
            float v0 = acc[mt][nt][0] + bsv[nt][0];
            float v1 = acc[mt][nt][1] + bsv[nt][1];
            float v2 = acc[mt][nt][2] + bsv[nt][0];
            float v3 = acc[mt][nt][3] + bsv[nt][1];
            if (STOREC) {
                int col = wn * 32 + nt * 8 + q * 2;
                int r0  = bm + wm * 64 + mt * 16 + g;
                *(float2*)(C + (long long)r0 * 128 + col)       = make_float2(v0, v1);
                *(float2*)(C + (long long)(r0 + 8) * 128 + col) = make_float2(v2, v3);
            }
            s [nt][0] += v0 + v2;       s [nt][1] += v1 + v3;
            s2[nt][0] += v0 * v0 + v2 * v2;
            s2[nt][1] += v1 * v1 + v3 * v3;
            if (POOL) {
                mx[nt][0] = fmaxf(mx[nt][0], fmaxf(v0, v2));
                mx[nt][1] = fmaxf(mx[nt][1], fmaxf(v1, v3));
            }
        }
    }
#pragma unroll
    for (int nt = 0; nt < 4; ++nt)
#pragma unroll
        for (int j = 0; j < 2; ++j) {
#pragma unroll
            for (int mask = 4; mask <= 16; mask <<= 1) {
                s [nt][j] += __shfl_xor_sync(0xffffffff, s [nt][j], mask);
                s2[nt][j] += __shfl_xor_sync(0xffffffff, s2[nt][j], mask);
                if (POOL)
                    mx[nt][j] = fmaxf(mx[nt][j], __shfl_xor_sync(0xffffffff, mx[nt][j], mask));
            }
        }
    if (g == 0) {
#pragma unroll
        for (int nt = 0; nt < 4; ++nt)
#pragma unroll
            for (int j = 0; j < 2; ++j) {
                int col = wn * 32 + nt * 8 + q * 2 + j;
                redS[wm][col] = s[nt][j];
                redQ[wm][col] = s2[nt][j];
                if (POOL) redM[wm][col] = mx[nt][j];
            }
    }
    __syncthreads();
    if (tid < 128) {
        partOut[blockIdx.x * 256 + tid]       = redS[0][tid] + redS[1][tid];
        partOut[blockIdx.x * 256 + 128 + tid] = redQ[0][tid] + redQ[1][tid];
    }
    if (POOL) {
        poolOut[(blockIdx.x * 2 + (tid >> 7)) * 128 + (tid & 127)] = redM[tid >> 7][tid & 127];
    }
}

// reduce 512 per-CTA partials -> folded BN scale/shift (1 block, 512 threads)
__global__ void k_bnfin512(float Minv,
                           const float* __restrict__ gamma,
                           const float* __restrict__ beta,
                           int slot) {
    __shared__ float rs[4][128], rq[4][128];
    int c  = threadIdx.x & 127;
    int sl = threadIdx.x >> 7;
    float s = 0.f, q = 0.f;
    for (int b = sl * 128; b < sl * 128 + 128; ++b) {
        s += g_part[b * 256 + c];
        q += g_part[b * 256 + 128 + c];
    }
    rs[sl][c] = s; rq[sl][c] = q;
    __syncthreads();
    if (threadIdx.x < 128) {
        float S = rs[0][c] + rs[1][c] + rs[2][c] + rs[3][c];
        float Q = rq[0][c] + rq[1][c] + rq[2][c] + rq[3][c];
        float mean = S * Minv;
        float var  = Q * Minv - mean * mean;
        float rstd = rsqrtf(var + 1e-5f);
        float sc   = gamma[c] * rstd;
        g_scale[slot * 128 + c] = sc;
        g_shift[slot * 128 + c] = beta[c] - mean * sc;
    }
}

// -------- fp32 SIMT GEMM for FC layers: 64x128 tile, grid=16, fused BN-stats --------
template <int KDIM, bool BNA>
__global__ void __launch_bounds__(256)
k_gemm64(const float* __restrict__ A, int lda,
         const float* __restrict__ W,
         const float* __restrict__ bias,
         const float* __restrict__ scl,
         const float* __restrict__ shf,
         float* __restrict__ C,
         float* __restrict__ partOut) {
    __shared__ float As[16][64];
    __shared__ float Ws2[16][128];
    __shared__ float redS[16][128];
    __shared__ float redQ[16][128];
    int tid = threadIdx.x;
    int bm  = blockIdx.x * 64;
    int tx  = tid & 15, ty = tid >> 4;   // tx: 16 col-blocks of 8, ty: 16 row-blocks of 4
    float acc[4][8];
#pragma unroll
    for (int i = 0; i < 4; ++i)
#pragma unroll
        for (int j = 0; j < 8; ++j) acc[i][j] = 0.f;

    const int KT = KDIM / 16;
    for (int kt = 0; kt < KT; ++kt) {
        int k0 = kt * 16;
        // A tile: 64 rows x 16 k, one float4 per thread
        {
            int row = tid >> 2;
            int kv  = (tid & 3) * 4;
            int k   = k0 + kv;
            float4 v = *reinterpret_cast<const float4*>(A + (long long)(bm + row) * lda + k);
            if (BNA) {
                v.x = fmaxf(v.x * scl[k + 0] + shf[k + 0], 0.f);
                v.y = fmaxf(v.y * scl[k + 1] + shf[k + 1], 0.f);
                v.z = fmaxf(v.z * scl[k + 2] + shf[k + 2], 0.f);
                v.w = fmaxf(v.w * scl[k + 3] + shf[k + 3], 0.f);
            }
            As[kv + 0][row] = v.x;
            As[kv + 1][row] = v.y;
            As[kv + 2][row] = v.z;
            As[kv + 3][row] = v.w;
        }
        // W tile: 128 n x 16 k
        {
            int n  = tid >> 1;
            int kb = (tid & 1) * 8;
#pragma unroll
            for (int i = 0; i < 8; ++i)
                Ws2[kb + i][n] = W[n * KDIM + k0 + kb + i];
        }
        __syncthreads();
#pragma unroll
        for (int kk = 0; kk < 16; ++kk) {
            float a[4], w8[8];
            *reinterpret_cast<float4*>(&a[0])  = *reinterpret_cast<const float4*>(&As[kk][ty * 4]);
            *reinterpret_cast<float4*>(&w8[0]) = *reinterpret_cast<const float4*>(&Ws2[kk][tx * 8]);
            *reinterpret_cast<float4*>(&w8[4]) = *reinterpret_cast<const float4*>(&Ws2[kk][tx * 8 + 4]);
#pragma unroll
            for (int i = 0; i < 4; ++i)
#pragma unroll
                for (int j = 0; j < 8; ++j) acc[i][j] += a[i] * w8[j];
        }
        __syncthreads();
    }
    // epilogue: bias + store + per-CTA channel stats
    float bv[8];
#pragma unroll
    for (int j = 0; j < 8; ++j) bv[j] = bias[tx * 8 + j];
    float s[8], s2[8];
#pragma unroll
    for (int j = 0; j < 8; ++j) { s[j] = 0.f; s2[j] = 0.f; }
#pragma unroll
    for (int i = 0; i < 4; ++i) {
        long long off = (long long)(bm + ty * 4 + i) * 128 + tx * 8;
        float o[8];
#pragma unroll
        for (int j = 0; j < 8; ++j) {
            o[j] = acc[i][j] + bv[j];
            s[j] += o[j];
            s2[j] += o[j] * o[j];
        }
        *reinterpret_cast<float4*>(C + off)     = make_float4(o[0], o[1], o[2], o[3]);
        *reinterpret_cast<float4*>(C + off + 4) = make_float4(o[4], o[5], o[6], o[7]);
    }
#pragma unroll
    for (int j = 0; j < 8; ++j) {
        redS[ty][tx * 8 + j] = s[j];
        redQ[ty][tx * 8 + j] = s2[j];
    }
    __syncthreads();
    if (tid < 128) {
        float S = 0.f, Q = 0.f;
#pragma unroll
        for (int t = 0; t < 16; ++t) { S += redS[t][tid]; Q += redQ[t][tid]; }
        partOut[blockIdx.x * 256 + tid]       = S;
        partOut[blockIdx.x * 256 + 128 + tid] = Q;
    }
}

// reduce NB per-CTA partials -> folded BN scale/shift
__global__ void k_bnfin(int NB, float Minv,
                        const float* __restrict__ gamma,
                        const float* __restrict__ beta,
                        int slot) {
    int c = threadIdx.x;
    float s = 0.f, s2 = 0.f;
    for (int b = 0; b < NB; ++b) {
        s  += g_part[b * 256 + c];
        s2 += g_part[b * 256 + 128 + c];
    }
    float mean = s * Minv;
    float var  = s2 * Minv - mean * mean;
    float rstd = rsqrtf(var + 1e-5f);
    float sc   = gamma[c] * rstd;
    g_scale[slot * 128 + c] = sc;
    g_shift[slot * 128 + c] = beta[c] - mean * sc;
}

// BN5+ReLU on N2, project to the last 18 of 77 output channels
__global__ void k_final(const float* __restrict__ cw3,
                        const float* __restrict__ cb3,
                        float* __restrict__ out) {
    int t = blockIdx.x * blockDim.x + threadIdx.x;
    if (t >= MFC * IOUS) return;
    int j   = t % IOUS;
    int row = t / IOUS;
    int o   = (OUTC - IOUS) + j;
    const float* wrow = cw3 + o * 128;
    const float* x    = g_N2 + row * 128;
    float acc = cb3[o];
#pragma unroll 8
    for (int i = 0; i < 128; ++i) {
        float v = fmaxf(x[i] * g_scale[4 * 128 + i] + g_shift[4 * 128 + i], 0.f);
        acc += v * wrow[i];
    }
    out[t] = acc;
}

// ---------------- launcher ----------------
extern "C" void kernel_launch(void* const* d_in, const int* in_sizes, int n_in,
                              void* d_out, int out_size) {
    const float* center  = (const float*)d_in[0];
    const float* size_   = (const float*)d_in[1];
    const float* heading = (const float*)d_in[2];
    const float* sxyz    = (const float*)d_in[3];
    const float* sfeat   = (const float*)d_in[4];
    const float* w0  = (const float*)d_in[5];
    const float* b0  = (const float*)d_in[6];
    const float* g0  = (const float*)d_in[7];
    const float* be0 = (const float*)d_in[8];
    const float* w1  = (const float*)d_in[9];
    const float* b1  = (const float*)d_in[10];
    const float* g1  = (const float*)d_in[11];
    const float* be1 = (const float*)d_in[12];
    const float* w2  = (const float*)d_in[13];
    const float* b2  = (const float*)d_in[14];
    const float* g2  = (const float*)d_in[15];
    const float* be2 = (const float*)d_in[16];
    const float* cw1 = (const float*)d_in[17];
    const float* cb1 = (const float*)d_in[18];
    const float* g3  = (const float*)d_in[19];
    const float* be3 = (const float*)d_in[20];
    const float* cw2 = (const float*)d_in[21];
    const float* cb2 = (const float*)d_in[22];
    const float* g4  = (const float*)d_in[23];
    const float* be4 = (const float*)d_in[24];
    const float* cw3 = (const float*)d_in[25];
    const float* cb3 = (const float*)d_in[26];
    float* out = (float*)d_out;

    void *pY1, *pY2, *pF, *pN1, *pN2, *pSC, *pSH, *pPart;
    cudaGetSymbolAddress(&pY1, g_Y1);
    cudaGetSymbolAddress(&pY2, g_Y2);
    cudaGetSymbolAddress(&pF,  g_F);
    cudaGetSymbolAddress(&pN1, g_N1);
    cudaGetSymbolAddress(&pN2, g_N2);
    cudaGetSymbolAddress(&pSC, g_scale);
    cudaGetSymbolAddress(&pSH, g_shift);
    cudaGetSymbolAddress(&pPart, g_part);
    float* Y1 = (float*)pY1;
    float* Y2 = (float*)pY2;
    float* F  = (float*)pF;
    float* N1 = (float*)pN1;
    float* N2 = (float*)pN2;
    float* SC = (float*)pSC;
    float* SH = (float*)pSH;
    float* PART = (float*)pPart;

    // stage 1: geometry + 3-NN (interp fused into GEMM0's A-loader)
    k_transpose<<<dim3(NS / 32, CF / 32, BB), dim3(32, 8)>>>(sfeat);
    k_gridpoints<<<M1 / 256, 256>>>(center, size_, heading);
    k_threenn<<<BB * 128, 128>>>(sxyz);

    // stage 2: SharedMLP on tensor cores; BN stats fused into each GEMM epilogue.
    // Layer0 gathers its input on the fly (GATHER). Last conv layer fuses the
    // 64-point maxpool (raw max; BN3+ReLU folded into FC1).
    k_gemm_bf<CIN0, false, true, false, true><<<M1 / 128, 256>>>(
        nullptr, 0, w0, b0, nullptr, nullptr, Y1, PART, nullptr);
    k_bnfin512<<<1, 512>>>(1.f / M1, g0, be0, 0);

    k_gemm_bf<HH, true, false, false, true><<<M1 / 128, 256>>>(
        Y1, HH, w1, b1, SC + 0 * 128, SH + 0 * 128, Y2, PART, nullptr);
    k_bnfin512<<<1, 512>>>(1.f / M1, g1, be1, 1);

    k_gemm_bf<HH, true, false, true, false><<<M1 / 128, 256>>>(
        Y2, HH, w2, b2, SC + 1 * 128, SH + 1 * 128, nullptr, PART, F);
    k_bnfin512<<<1, 512>>>(1.f / M1, g2, be2, 2);

    // stage 3: FC head (fp32 SIMT, 64-row tiles, fused BN stats). FC1 applies BN3+ReLU.
    k_gemm64<HH, true><<<MFC / 64, 256>>>(F, HH, cw1, cb1, SC + 2 * 128, SH + 2 * 128, N1, PART);
    k_bnfin<<<1, 128>>>(16, 1.f / MFC, g3, be3, 3);

    k_gemm64<HH, true><<<MFC / 64, 256>>>(N1, HH, cw2, cb2, SC + 3 * 128, SH + 3 * 128, N2, PART);
    k_bnfin<<<1, 128>>>(16, 1.f / MFC, g4, be4, 4);

    k_final<<<(MFC * IOUS + 255) / 256, 256>>>(cw3, cb3, out);
}

// round 12
// speedup vs baseline: 1.2643x; 1.0214x over previous
#include <cuda_runtime.h>
#include <cuda_bf16.h>
#include <math.h>
#include <stdint.h>

// ---------------- problem constants ----------------
static constexpr int BB   = 4;
static constexpr int KK   = 256;
static constexpr int NS   = 1024;      // seeds
static constexpr int CF   = 256;       // seed feature channels
static constexpr int GPP  = 64;        // grid points per proposal
static constexpr int QQ   = KK * GPP;  // 16384 queries per batch
static constexpr int M1   = BB * QQ;   // 65536 rows for conv layers
static constexpr int CIN0 = CF + 3;    // 259 logical input channels
static constexpr int KPH0 = 288;       // padded logical K for layer0 (9 chunks of 32)
static constexpr int HH   = 128;
static constexpr int MFC  = BB * KK;   // 1024 rows for FC layers
static constexpr int IOUS = 18;
static constexpr int OUTC = 77;

// ---------------- scratch (static device memory; no allocations) ----------------
__device__ float g_wq[M1 * 3];
__device__ float g_rel[M1 * 3];
__device__ float g_featT[BB * NS * CF];        // [b][n][c]
__device__ int   g_idx3[M1 * 3];
__device__ float g_w3[M1 * 3];
__device__ float g_Y1[(long long)M1 * HH];
__device__ float g_Y2[(long long)M1 * HH];
__device__ float g_F [MFC * HH];               // RAW maxpool output (pre-BN3)
__device__ float g_N1[MFC * HH];
__device__ float g_N2[MFC * HH];
__device__ float g_part[512 * 256];            // per-CTA partial BN stats
__device__ float g_scale[5 * 128];
__device__ float g_shift[5 * 128];
// pre-split packed-bf16 weights, tile-shaped [kp][n] (kp=k/2); W0 permuted+padded
__device__ uint32_t g_W0H[144 * 128], g_W0L[144 * 128];
__device__ uint32_t g_W1H[ 64 * 128], g_W1L[ 64 * 128];
__device__ uint32_t g_W2H[ 64 * 128], g_W2L[ 64 * 128];

// ---------------- small helpers ----------------
// split two fp32 values into packed-bf16 (hi pair, lo pair); word = {k_even, k_odd}
__device__ __forceinline__ void split2_bf16(float v0, float v1, uint32_t& hi, uint32_t& lo) {
    __nv_bfloat16 h0 = __float2bfloat16_rn(v0);
    __nv_bfloat16 h1 = __float2bfloat16_rn(v1);
    float l0 = v0 - __bfloat162float(h0);
    float l1 = v1 - __bfloat162float(h1);
    __nv_bfloat162 hp = __halves2bfloat162(h0, h1);
    __nv_bfloat162 lp = __floats2bfloat162_rn(l0, l1);
    hi = *reinterpret_cast<uint32_t*>(&hp);
    lo = *reinterpret_cast<uint32_t*>(&lp);
}

__device__ __forceinline__ void mma_bf16(float& c0, float& c1, float& c2, float& c3,
                                         uint32_t a0, uint32_t a1, uint32_t a2, uint32_t a3,
                                         uint32_t b0, uint32_t b1) {
    asm volatile(
        "mma.sync.aligned.m16n8k16.row.col.f32.bf16.bf16.f32 "
        "{%0,%1,%2,%3}, {%4,%5,%6,%7}, {%8,%9}, {%0,%1,%2,%3};"
        : "+f"(c0), "+f"(c1), "+f"(c2), "+f"(c3)
        : "r"(a0), "r"(a1), "r"(a2), "r"(a3), "r"(b0), "r"(b1));
}

__device__ __forceinline__ void cp_async16(uint32_t smem_addr, const void* gptr) {
    asm volatile("cp.async.cg.shared.global [%0], [%1], 16;"
                 :: "r"(smem_addr), "l"(gptr));
}
__device__ __forceinline__ void cp_async_commit() {
    asm volatile("cp.async.commit_group;");
}
__device__ __forceinline__ void cp_async_wait0() {
    asm volatile("cp.async.wait_group 0;");
}

// ---------------- weight prep: fp32 -> packed bf16 hi/lo, tile-shaped [kp][n] ----------------
__global__ void k_prepW0(const float* __restrict__ W) {
    int t = blockIdx.x * blockDim.x + threadIdx.x;   // < 144*128
    int kp = t >> 7, n = t & 127;
    int k0 = 2 * kp, k1 = 2 * kp + 1;
    float v0 = 0.f, v1 = 0.f;
    if (k0 < CIN0) { int kl = (k0 < 256) ? k0 + 3 : k0 - 256; v0 = W[n * CIN0 + kl]; }
    if (k1 < CIN0) { int kl = (k1 < 256) ? k1 + 3 : k1 - 256; v1 = W[n * CIN0 + kl]; }
    uint32_t hi, lo;
    split2_bf16(v0, v1, hi, lo);
    g_W0H[t] = hi; g_W0L[t] = lo;
}

__global__ void k_prepW128(const float* __restrict__ W,
                           uint32_t* __restrict__ WH, uint32_t* __restrict__ WL) {
    int t = blockIdx.x * blockDim.x + threadIdx.x;   // < 64*128
    int kp = t >> 7, n = t & 127;
    float v0 = W[n * 128 + 2 * kp];
    float v1 = W[n * 128 + 2 * kp + 1];
    uint32_t hi, lo;
    split2_bf16(v0, v1, hi, lo);
    WH[t] = hi; WL[t] = lo;
}

// ---------------- stage-1 kernels ----------------

// seed_features [b][c][n] -> g_featT [b][n][c]
__global__ void k_transpose(const float* __restrict__ feat) {
    __shared__ float tile[32][33];
    int b  = blockIdx.z;
    int n0 = blockIdx.x * 32;
    int c0 = blockIdx.y * 32;
    const float* src = feat    + (long long)b * CF * NS;
    float*       dst = g_featT + (long long)b * NS * CF;
#pragma unroll
    for (int r = 0; r < 4; ++r) {
        int c = c0 + threadIdx.y + r * 8;
        tile[threadIdx.y + r * 8][threadIdx.x] = src[c * NS + n0 + threadIdx.x];
    }
    __syncthreads();
#pragma unroll
    for (int r = 0; r < 4; ++r) {
        int n = n0 + threadIdx.y + r * 8;
        dst[n * CF + c0 + threadIdx.x] = tile[threadIdx.x][threadIdx.y + r * 8];
    }
}

// rotate+scale grid -> g_rel, world points -> g_wq
__global__ void k_gridpoints(const float* __restrict__ center,
                             const float* __restrict__ size_,
                             const float* __restrict__ heading) {
    int m = blockIdx.x * blockDim.x + threadIdx.x;
    if (m >= M1) return;
    int g  = m & 63;
    int bk = m >> 6;
    float sx = size_[bk * 3 + 0], sy = size_[bk * 3 + 1], sz = size_[bk * 3 + 2];
    float h  = heading[bk];
    float ch = cosf(h), sh = sinf(h);
    float gx = -1.f + (float)( g >> 4      ) * (2.f / 3.f);
    float gy = -1.f + (float)((g >> 2) & 3 ) * (2.f / 3.f);
    float gz = -1.f + (float)( g       & 3 ) * (2.f / 3.f);
    float ax = gx * sx, ay = gy * sy, az = gz * sz;
    float rx = ax * ch - ay * sh;
    float ry = ax * sh + ay * ch;
    float rz = az;
    g_rel[m * 3 + 0] = rx;
    g_rel[m * 3 + 1] = ry;
    g_rel[m * 3 + 2] = rz;
    g_wq[m * 3 + 0] = rx + center[bk * 3 + 0];
    g_wq[m * 3 + 1] = ry + center[bk * 3 + 1];
    g_wq[m * 3 + 2] = rz + center[bk * 3 + 2];
}

// 3-NN per query over 1024 seeds (seeds cached in SMEM), inverse-distance weights
__global__ void k_threenn(const float* __restrict__ seed_xyz) {
    __shared__ float4 sp[NS];
    int b = blockIdx.x >> 7;
    int q = ((blockIdx.x & 127) << 7) + threadIdx.x;
    for (int i = threadIdx.x; i < NS; i += blockDim.x) {
        float x = seed_xyz[((long long)b * NS + i) * 3 + 0];
        float y = seed_xyz[((long long)b * NS + i) * 3 + 1];
        float z = seed_xyz[((long long)b * NS + i) * 3 + 2];
        sp[i] = make_float4(x, y, z, x * x + y * y + z * z);
    }
    __syncthreads();
    int m = b * QQ + q;
    float qx = g_wq[m * 3 + 0], qy = g_wq[m * 3 + 1], qz = g_wq[m * 3 + 2];
    float qq = qx * qx + qy * qy + qz * qz;
    float d0 = 1e30f, d1 = 1e30f, d2 = 1e30f;
    int   i0 = 0, i1 = 0, i2 = 0;
    for (int n = 0; n < NS; ++n) {
        float4 p = sp[n];
        float d = qq + p.w - 2.f * (qx * p.x + qy * p.y + qz * p.z);
        if (d < d2) {
            if (d < d1) {
                d2 = d1; i2 = i1;
                if (d < d0) { d1 = d0; i1 = i0; d0 = d; i0 = n; }
                else        { d1 = d;  i1 = n; }
            } else { d2 = d; i2 = n; }
        }
    }
    int ii[3] = {i0, i1, i2};
    float w[3];
#pragma unroll
    for (int j = 0; j < 3; ++j) {
        float4 p = sp[ii[j]];
        float dx = p.x - qx, dy = p.y - qy, dz = p.z - qz;
        float dist = sqrtf(dx * dx + dy * dy + dz * dz);
        w[j] = 1.f / (dist + 1e-8f);
    }
    float inv = 1.f / (w[0] + w[1] + w[2]);
#pragma unroll
    for (int j = 0; j < 3; ++j) {
        g_idx3[m * 3 + j] = ii[j];
        g_w3[m * 3 + j]   = w[j] * inv;
    }
}

// ---- split-bf16 tensor-core GEMM with fused epilogue ----
// Round-10 structure; W now arrives pre-split (packed bf16 hi/lo, tile-shaped
// [kp][n]) and is copied with coalesced cp.async overlapping the A build.
// C[m,n] = sum_k act(A[m,k]) * W[n,k] + bias[n]
// 128x128 tile, K-chunks of 32, m16n8k16 bf16 MMA, acc += aL*bH + aH*bL + aH*bH.
// 8 warps (2 over M x 4 over N), 2 CTAs/SM, single-buffered, A register-prefetched.
// GATHER: layer-0 mode. A gathered on the fly from g_featT (L2-hot) + rel xyz;
//         W0 is pre-permuted/padded so no PERM branches remain.
template <bool BNA, bool GATHER, bool POOL, bool STOREC>
__global__ void __launch_bounds__(256, 2)
k_gemm_bf(const float* __restrict__ A, int lda,
          const uint32_t* __restrict__ WHg,
          const uint32_t* __restrict__ WLg,
          const float* __restrict__ bias,
          const float* __restrict__ scl,
          const float* __restrict__ shf,
          float* __restrict__ C,
          float* __restrict__ partOut,
          float* __restrict__ poolOut) {
    __shared__ uint32_t AsH[16][136];
    __shared__ uint32_t AsL[16][136];
    __shared__ uint32_t WsH[16][136];
    __shared__ uint32_t WsL[16][136];
    __shared__ float redS[2][128];
    __shared__ float redQ[2][128];
    __shared__ float redM[2][128];

    const int tid  = threadIdx.x;
    const int lane = tid & 31;
    const int warp = tid >> 5;
    const int g    = lane >> 2;        // 0..7
    const int q    = lane & 3;         // 0..3
    const int wm   = warp & 1;         // 2 warps over M
    const int wn   = warp >> 1;        // 4 warps over N
    const int bm   = blockIdx.x * 128;

    float acc[4][4][4];
#pragma unroll
    for (int i = 0; i < 4; ++i)
#pragma unroll
        for (int j = 0; j < 4; ++j)
#pragma unroll
            for (int r = 0; r < 4; ++r) acc[i][j][r] = 0.f;

    const int ldrow = tid >> 1;         // 0..127
    const int ldkv  = (tid & 1) * 16;   // 0 or 16
    const int kp0   = ldkv / 2;         // 0 or 8
    const int NCH   = GATHER ? (KPH0 / 32) : 4;

    // W cp.async mapping: kp row = tid>>4, n block = (tid&15)*8 -> coalesced rows
    const int wkp = tid >> 4;           // 0..15
    const int wn0 = (tid & 15) * 8;     // 0..120
    const uint32_t dWH0 = (uint32_t)__cvta_generic_to_shared(&WsH[wkp][wn0]);
    const uint32_t dWH1 = (uint32_t)__cvta_generic_to_shared(&WsH[wkp][wn0 + 4]);
    const uint32_t dWL0 = (uint32_t)__cvta_generic_to_shared(&WsL[wkp][wn0]);
    const uint32_t dWL1 = (uint32_t)__cvta_generic_to_shared(&WsL[wkp][wn0 + 4]);

    // GATHER state (row fixed for the whole k-loop)
    const float *gf0 = nullptr, *gf1 = nullptr, *gf2 = nullptr;
    float gw0 = 0.f, gw1 = 0.f, gw2 = 0.f;
    float grel[3] = {0.f, 0.f, 0.f};
    if (GATHER) {
        const int m = bm + ldrow;
        const int b = m >> 14;
        int i0 = g_idx3[m * 3 + 0], i1 = g_idx3[m * 3 + 1], i2 = g_idx3[m * 3 + 2];
        gw0 = g_w3[m * 3 + 0]; gw1 = g_w3[m * 3 + 1]; gw2 = g_w3[m * 3 + 2];
        gf0 = g_featT + ((long long)b * NS + i0) * CF;
        gf1 = g_featT + ((long long)b * NS + i1) * CF;
        gf2 = g_featT + ((long long)b * NS + i2) * CF;
        grel[0] = g_rel[m * 3 + 0];
        grel[1] = g_rel[m * 3 + 1];
        grel[2] = g_rel[m * 3 + 2];
    }

    float vA[16];
    if (!GATHER) {
        const float* ap = A + (long long)(bm + ldrow) * lda + ldkv;
        float4 u0 = *(const float4*)(ap + 0);
        float4 u1 = *(const float4*)(ap + 4);
        float4 u2 = *(const float4*)(ap + 8);
        float4 u3 = *(const float4*)(ap + 12);
        vA[0]=u0.x; vA[1]=u0.y; vA[2]=u0.z; vA[3]=u0.w;
        vA[4]=u1.x; vA[5]=u1.y; vA[6]=u1.z; vA[7]=u1.w;
        vA[8]=u2.x; vA[9]=u2.y; vA[10]=u2.z; vA[11]=u2.w;
        vA[12]=u3.x; vA[13]=u3.y; vA[14]=u3.z; vA[15]=u3.w;
    }

    for (int ch = 0; ch < NCH; ++ch) {
        const int k0 = ch * 32;
        // ---- issue async W copy (overlaps the A build below) ----
        {
            const uint32_t* sH = WHg + (ch * 16 + wkp) * 128 + wn0;
            const uint32_t* sL = WLg + (ch * 16 + wkp) * 128 + wn0;
            cp_async16(dWH0, sH);
            cp_async16(dWH1, sH + 4);
            cp_async16(dWL0, sL);
            cp_async16(dWL1, sL + 4);
            cp_async_commit();
        }
        // ---- build + split A chunk -> SMEM ----
        {
            float v[16];
            if (GATHER) {
                const int kbase = k0 + ldkv;
                if (kbase < 256) {
#pragma unroll
                    for (int r4 = 0; r4 < 4; ++r4) {
                        float4 a  = *(const float4*)(gf0 + kbase + r4 * 4);
                        float4 bq = *(const float4*)(gf1 + kbase + r4 * 4);
                        float4 cq = *(const float4*)(gf2 + kbase + r4 * 4);
                        v[r4 * 4 + 0] = gw0 * a.x + gw1 * bq.x + gw2 * cq.x;
                        v[r4 * 4 + 1] = gw0 * a.y + gw1 * bq.y + gw2 * cq.y;
                        v[r4 * 4 + 2] = gw0 * a.z + gw1 * bq.z + gw2 * cq.z;
                        v[r4 * 4 + 3] = gw0 * a.w + gw1 * bq.w + gw2 * cq.w;
                    }
                } else {
#pragma unroll
                    for (int i = 0; i < 16; ++i) v[i] = 0.f;
                    if (kbase == 256) { v[0] = grel[0]; v[1] = grel[1]; v[2] = grel[2]; }
                }
            } else {
#pragma unroll
                for (int i = 0; i < 16; ++i) v[i] = vA[i];
                if (BNA) {
#pragma unroll
                    for (int i = 0; i < 16; ++i) {
                        int k = k0 + ldkv + i;   // KDIM=128 in BNA mode: always valid
                        v[i] = fmaxf(v[i] * scl[k] + shf[k], 0.f);
                    }
                }
            }
#pragma unroll
            for (int i = 0; i < 8; ++i) {
                uint32_t hi, lo;
                split2_bf16(v[2 * i], v[2 * i + 1], hi, lo);
                AsH[kp0 + i][ldrow] = hi;
                AsL[kp0 + i][ldrow] = lo;
            }
        }
        cp_async_wait0();
        __syncthreads();

        // ---- prefetch next A chunk (latency hidden behind MMAs; non-gather only) ----
        if (!GATHER && ch + 1 < NCH) {
            const float* ap = A + (long long)(bm + ldrow) * lda + (k0 + 32) + ldkv;
            float4 u0 = *(const float4*)(ap + 0);
            float4 u1 = *(const float4*)(ap + 4);
            float4 u2 = *(const float4*)(ap + 8);
            float4 u3 = *(const float4*)(ap + 12);
            vA[0]=u0.x; vA[1]=u0.y; vA[2]=u0.z; vA[3]=u0.w;
            vA[4]=u1.x; vA[5]=u1.y; vA[6]=u1.z; vA[7]=u1.w;
            vA[8]=u2.x; vA[9]=u2.y; vA[10]=u2.z; vA[11]=u2.w;
            vA[12]=u3.x; vA[13]=u3.y; vA[14]=u3.z; vA[15]=u3.w;
        }

        // ---- two k16 steps per chunk ----
#pragma unroll
        for (int kb = 0; kb < 16; kb += 8) {
            uint32_t bH[4][2], bL[4][2];
#pragma unroll
            for (int nt = 0; nt < 4; ++nt) {
                int nbase = wn * 32 + nt * 8;
                bH[nt][0] = WsH[kb + q    ][nbase + g];
                bH[nt][1] = WsH[kb + q + 4][nbase + g];
                bL[nt][0] = WsL[kb + q    ][nbase + g];
                bL[nt][1] = WsL[kb + q + 4][nbase + g];
            }
#pragma unroll
            for (int mt = 0; mt < 4; ++mt) {
                int mbase = wm * 64 + mt * 16;
                uint32_t aH0 = AsH[kb + q    ][mbase + g    ];
                uint32_t aH1 = AsH[kb + q    ][mbase + g + 8];
                uint32_t aH2 = AsH[kb + q + 4][mbase + g    ];
                uint32_t aH3 = AsH[kb + q + 4][mbase + g + 8];
                uint32_t aL0 = AsL[kb + q    ][mbase + g    ];
                uint32_t aL1 = AsL[kb + q    ][mbase + g + 8];
                uint32_t aL2 = AsL[kb + q + 4][mbase + g    ];
                uint32_t aL3 = AsL[kb + q + 4][mbase + g + 8];
#pragma unroll
                for (int nt = 0; nt < 4; ++nt) {
                    mma_bf16(acc[mt][nt][0], acc[mt][nt][1], acc[mt][nt][2], acc[mt][nt][3],
                             aL0, aL1, aL2, aL3, bH[nt][0], bH[nt][1]);
                    mma_bf16(acc[mt][nt][0], acc[mt][nt][1], acc[mt][nt][2], acc[mt][nt][3],
                             aH0, aH1, aH2, aH3, bL[nt][0], bL[nt][1]);
                    mma_bf16(acc[mt][nt][0], acc[mt][nt][1], acc[mt][nt][2], acc[mt][nt][3],
                             aH0, aH1, aH2, aH3, bH[nt][0], bH[nt][1]);
                }
            }
        }
        __syncthreads();
    }

    // ---- fused epilogue: bias, optional store, BN stats partials, optional maxpool ----
    float bsv[4][2];
#pragma unroll
    for (int nt = 0; nt < 4; ++nt) {
        int col = wn * 32 + nt * 8 + q * 2;
        bsv[nt][0] = bias[col];
        bsv[nt][1] = bias[col + 1];
    }
    float s[4][2], s2[4][2], mx[4][2];
#pragma unroll
    for (int nt = 0; nt < 4; ++nt)
#pragma unroll
        for (int j = 0; j < 2; ++j) { s[nt][j] = 0.f; s2[nt][j] = 0.f; mx[nt][j] = -1e30f; }

#pragma unroll
    for (int mt = 0; mt < 4; ++mt) {
#pragma unroll
        for (int nt = 0; nt < 4; ++nt) {
            float v0 = acc[mt][nt][0] + bsv[nt][0];
            float v1 = acc[mt][nt][1] + bsv[nt][1];
            float v2 = acc[mt][nt][2] + bsv[nt][0];
            float v3 = acc[mt][nt][3] + bsv[nt][1];
            if (STOREC) {
                int col = wn * 32 + nt * 8 + q * 2;
                int r0  = bm + wm * 64 + mt * 16 + g;
                *(float2*)(C + (long long)r0 * 128 + col)       = make_float2(v0, v1);
                *(float2*)(C + (long long)(r0 + 8) * 128 + col) = make_float2(v2, v3);
            }
            s [nt][0] += v0 + v2;       s [nt][1] += v1 + v3;
            s2[nt][0] += v0 * v0 + v2 * v2;
            s2[nt][1] += v1 * v1 + v3 * v3;
            if (POOL) {
                mx[nt][0] = fmaxf(mx[nt][0], fmaxf(v0, v2));
                mx[nt][1] = fmaxf(mx[nt][1], fmaxf(v1, v3));
            }
        }
    }
#pragma unroll
    for (int nt = 0; nt < 4; ++nt)
#pragma unroll
        for (int j = 0; j < 2; ++j) {
#pragma unroll
            for (int mask = 4; mask <= 16; mask <<= 1) {
                s [nt][j] += __shfl_xor_sync(0xffffffff, s [nt][j], mask);
                s2[nt][j] += __shfl_xor_sync(0xffffffff, s2[nt][j], mask);
                if (POOL)
                    mx[nt][j] = fmaxf(mx[nt][j], __shfl_xor_sync(0xffffffff, mx[nt][j], mask));
            }
        }
    if (g == 0) {
#pragma unroll
        for (int nt = 0; nt < 4; ++nt)
#pragma unroll
            for (int j = 0; j < 2; ++j) {
                int col = wn * 32 + nt * 8 + q * 2 + j;
                redS[wm][col] = s[nt][j];
                redQ[wm][col] = s2[nt][j];
                if (POOL) redM[wm][col] = mx[nt][j];
            }
    }
    __syncthreads();
    if (tid < 128) {
        partOut[blockIdx.x * 256 + tid]       = redS[0][tid] + redS[1][tid];
        partOut[blockIdx.x * 256 + 128 + tid] = redQ[0][tid] + redQ[1][tid];
    }
    if (POOL) {
        poolOut[(blockIdx.x * 2 + (tid >> 7)) * 128 + (tid & 127)] = redM[tid >> 7][tid & 127];
    }
}

// reduce 512 per-CTA partials -> folded BN scale/shift (1 block, 512 threads)
__global__ void k_bnfin512(float Minv,
                           const float* __restrict__ gamma,
                           const float* __restrict__ beta,
                           int slot) {
    __shared__ float rs[4][128], rq[4][128];
    int c  = threadIdx.x & 127;
    int sl = threadIdx.x >> 7;
    float s = 0.f, q = 0.f;
    for (int b = sl * 128; b < sl * 128 + 128; ++b) {
        s += g_part[b * 256 + c];
        q += g_part[b * 256 + 128 + c];
    }
    rs[sl][c] = s; rq[sl][c] = q;
    __syncthreads();
    if (threadIdx.x < 128) {
        float S = rs[0][c] + rs[1][c] + rs[2][c] + rs[3][c];
        float Q = rq[0][c] + rq[1][c] + rq[2][c] + rq[3][c];
        float mean = S * Minv;
        float var  = Q * Minv - mean * mean;
        float rstd = rsqrtf(var + 1e-5f);
        float sc   = gamma[c] * rstd;
        g_scale[slot * 128 + c] = sc;
        g_shift[slot * 128 + c] = beta[c] - mean * sc;
    }
}

// -------- fp32 SIMT GEMM for FC layers: 64x128 tile, grid=16, fused BN-stats --------
template <int KDIM, bool BNA>
__global__ void __launch_bounds__(256)
k_gemm64(const float* __restrict__ A, int lda,
         const float* __restrict__ W,
         const float* __restrict__ bias,
         const float* __restrict__ scl,
         const float* __restrict__ shf,
         float* __restrict__ C,
         float* __restrict__ partOut) {
    __shared__ float As[16][64];
    __shared__ float Ws2[16][128];
    __shared__ float redS[16][128];
    __shared__ float redQ[16][128];
    int tid = threadIdx.x;
    int bm  = blockIdx.x * 64;
    int tx  = tid & 15, ty = tid >> 4;
    float acc[4][8];
#pragma unroll
    for (int i = 0; i < 4; ++i)
#pragma unroll
        for (int j = 0; j < 8; ++j) acc[i][j] = 0.f;

    const int KT = KDIM / 16;
    for (int kt = 0; kt < KT; ++kt) {
        int k0 = kt * 16;
        {
            int row = tid >> 2;
            int kv  = (tid & 3) * 4;
            int k   = k0 + kv;
            float4 v = *reinterpret_cast<const float4*>(A + (long long)(bm + row) * lda + k);
            if (BNA) {
                v.x = fmaxf(v.x * scl[k + 0] + shf[k + 0], 0.f);
                v.y = fmaxf(v.y * scl[k + 1] + shf[k + 1], 0.f);
                v.z = fmaxf(v.z * scl[k + 2] + shf[k + 2], 0.f);
                v.w = fmaxf(v.w * scl[k + 3] + shf[k + 3], 0.f);
            }
            As[kv + 0][row] = v.x;
            As[kv + 1][row] = v.y;
            As[kv + 2][row] = v.z;
            As[kv + 3][row] = v.w;
        }
        {
            int n  = tid >> 1;
            int kb = (tid & 1) * 8;
#pragma unroll
            for (int i = 0; i < 8; ++i)
                Ws2[kb + i][n] = W[n * KDIM + k0 + kb + i];
        }
        __syncthreads();
#pragma unroll
        for (int kk = 0; kk < 16; ++kk) {
            float a[4], w8[8];
            *reinterpret_cast<float4*>(&a[0])  = *reinterpret_cast<const float4*>(&As[kk][ty * 4]);
            *reinterpret_cast<float4*>(&w8[0]) = *reinterpret_cast<const float4*>(&Ws2[kk][tx * 8]);
            *reinterpret_cast<float4*>(&w8[4]) = *reinterpret_cast<const float4*>(&Ws2[kk][tx * 8 + 4]);
#pragma unroll
            for (int i = 0; i < 4; ++i)
#pragma unroll
                for (int j = 0; j < 8; ++j) acc[i][j] += a[i] * w8[j];
        }
        __syncthreads();
    }
    float bv[8];
#pragma unroll
    for (int j = 0; j < 8; ++j) bv[j] = bias[tx * 8 + j];
    float s[8], s2[8];
#pragma unroll
    for (int j = 0; j < 8; ++j) { s[j] = 0.f; s2[j] = 0.f; }
#pragma unroll
    for (int i = 0; i < 4; ++i) {
        long long off = (long long)(bm + ty * 4 + i) * 128 + tx * 8;
        float o[8];
#pragma unroll
        for (int j = 0; j < 8; ++j) {
            o[j] = acc[i][j] + bv[j];
            s[j] += o[j];
            s2[j] += o[j] * o[j];
        }
        *reinterpret_cast<float4*>(C + off)     = make_float4(o[0], o[1], o[2], o[3]);
        *reinterpret_cast<float4*>(C + off + 4) = make_float4(o[4], o[5], o[6], o[7]);
    }
#pragma unroll
    for (int j = 0; j < 8; ++j) {
        redS[ty][tx * 8 + j] = s[j];
        redQ[ty][tx * 8 + j] = s2[j];
    }
    __syncthreads();
    if (tid < 128) {
        float S = 0.f, Q = 0.f;
#pragma unroll
        for (int t = 0; t < 16; ++t) { S += redS[t][tid]; Q += redQ[t][tid]; }
        partOut[blockIdx.x * 256 + tid]       = S;
        partOut[blockIdx.x * 256 + 128 + tid] = Q;
    }
}

// reduce NB per-CTA partials -> folded BN scale/shift
__global__ void k_bnfin(int NB, float Minv,
                        const float* __restrict__ gamma,
                        const float* __restrict__ beta,
                        int slot) {
    int c = threadIdx.x;
    float s = 0.f, s2 = 0.f;
    for (int b = 0; b < NB; ++b) {
        s  += g_part[b * 256 + c];
        s2 += g_part[b * 256 + 128 + c];
    }
    float mean = s * Minv;
    float var  = s2 * Minv - mean * mean;
    float rstd = rsqrtf(var + 1e-5f);
    float sc   = gamma[c] * rstd;
    g_scale[slot * 128 + c] = sc;
    g_shift[slot * 128 + c] = beta[c] - mean * sc;
}

// BN5+ReLU on N2, project to the last 18 of 77 output channels
__global__ void k_final(const float* __restrict__ cw3,
                        const float* __restrict__ cb3,
                        float* __restrict__ out) {
    int t = blockIdx.x * blockDim.x + threadIdx.x;
    if (t >= MFC * IOUS) return;
    int j   = t % IOUS;
    int row = t / IOUS;
    int o   = (OUTC - IOUS) + j;
    const float* wrow = cw3 + o * 128;
    const float* x    = g_N2 + row * 128;
    float acc = cb3[o];
#pragma unroll 8
    for (int i = 0; i < 128; ++i) {
        float v = fmaxf(x[i] * g_scale[4 * 128 + i] + g_shift[4 * 128 + i], 0.f);
        acc += v * wrow[i];
    }
    out[t] = acc;
}

// ---------------- launcher ----------------
extern "C" void kernel_launch(void* const* d_in, const int* in_sizes, int n_in,
                              void* d_out, int out_size) {
    const float* center  = (const float*)d_in[0];
    const float* size_   = (const float*)d_in[1];
    const float* heading = (const float*)d_in[2];
    const float* sxyz    = (const float*)d_in[3];
    const float* sfeat   = (const float*)d_in[4];
    const float* w0  = (const float*)d_in[5];
    const float* b0  = (const float*)d_in[6];
    const float* g0  = (const float*)d_in[7];
    const float* be0 = (const float*)d_in[8];
    const float* w1  = (const float*)d_in[9];
    const float* b1  = (const float*)d_in[10];
    const float* g1  = (const float*)d_in[11];
    const float* be1 = (const float*)d_in[12];
    const float* w2  = (const float*)d_in[13];
    const float* b2  = (const float*)d_in[14];
    const float* g2  = (const float*)d_in[15];
    const float* be2 = (const float*)d_in[16];
    const float* cw1 = (const float*)d_in[17];
    const float* cb1 = (const float*)d_in[18];
    const float* g3  = (const float*)d_in[19];
    const float* be3 = (const float*)d_in[20];
    const float* cw2 = (const float*)d_in[21];
    const float* cb2 = (const float*)d_in[22];
    const float* g4  = (const float*)d_in[23];
    const float* be4 = (const float*)d_in[24];
    const float* cw3 = (const float*)d_in[25];
    const float* cb3 = (const float*)d_in[26];
    float* out = (float*)d_out;

    void *pY1, *pY2, *pF, *pN1, *pN2, *pSC, *pSH, *pPart;
    void *pW0H, *pW0L, *pW1H, *pW1L, *pW2H, *pW2L;
    cudaGetSymbolAddress(&pY1, g_Y1);
    cudaGetSymbolAddress(&pY2, g_Y2);
    cudaGetSymbolAddress(&pF,  g_F);
    cudaGetSymbolAddress(&pN1, g_N1);
    cudaGetSymbolAddress(&pN2, g_N2);
    cudaGetSymbolAddress(&pSC, g_scale);
    cudaGetSymbolAddress(&pSH, g_shift);
    cudaGetSymbolAddress(&pPart, g_part);
    cudaGetSymbolAddress(&pW0H, g_W0H);
    cudaGetSymbolAddress(&pW0L, g_W0L);
    cudaGetSymbolAddress(&pW1H, g_W1H);
    cudaGetSymbolAddress(&pW1L, g_W1L);
    cudaGetSymbolAddress(&pW2H, g_W2H);
    cudaGetSymbolAddress(&pW2L, g_W2L);
    float* Y1 = (float*)pY1;
    float* Y2 = (float*)pY2;
    float* F  = (float*)pF;
    float* N1 = (float*)pN1;
    float* N2 = (float*)pN2;
    float* SC = (float*)pSC;
    float* SH = (float*)pSH;
    float* PART = (float*)pPart;
    uint32_t* W0H = (uint32_t*)pW0H; uint32_t* W0L = (uint32_t*)pW0L;
    uint32_t* W1H = (uint32_t*)pW1H; uint32_t* W1L = (uint32_t*)pW1L;
    uint32_t* W2H = (uint32_t*)pW2H; uint32_t* W2L = (uint32_t*)pW2L;

    // stage 0: weight pre-split (tiny)
    k_prepW0<<<(144 * 128) / 256, 256>>>(w0);
    k_prepW128<<<(64 * 128) / 256, 256>>>(w1, W1H, W1L);
    k_prepW128<<<(64 * 128) / 256, 256>>>(w2, W2H, W2L);

    // stage 1: geometry + 3-NN (interp fused into GEMM0's A-loader)
    k_transpose<<<dim3(NS / 32, CF / 32, BB), dim3(32, 8)>>>(sfeat);
    k_gridpoints<<<M1 / 256, 256>>>(center, size_, heading);
    k_threenn<<<BB * 128, 128>>>(sxyz);

    // stage 2: SharedMLP on tensor cores; BN stats fused into each GEMM epilogue.
    // Layer0 gathers its input on the fly (GATHER). Last conv layer fuses the
    // 64-point maxpool (raw max; BN3+ReLU folded into FC1).
    k_gemm_bf<false, true, false, true><<<M1 / 128, 256>>>(
        nullptr, 0, W0H, W0L, b0, nullptr, nullptr, Y1, PART, nullptr);
    k_bnfin512<<<1, 512>>>(1.f / M1, g0, be0, 0);

    k_gemm_bf<true, false, false, true><<<M1 / 128, 256>>>(
        Y1, HH, W1H, W1L, b1, SC + 0 * 128, SH + 0 * 128, Y2, PART, nullptr);
    k_bnfin512<<<1, 512>>>(1.f / M1, g1, be1, 1);

    k_gemm_bf<true, false, true, false><<<M1 / 128, 256>>>(
        Y2, HH, W2H, W2L, b2, SC + 1 * 128, SH + 1 * 128, nullptr, PART, F);
    k_bnfin512<<<1, 512>>>(1.f / M1, g2, be2, 2);

    // stage 3: FC head (fp32 SIMT, 64-row tiles, fused BN stats). FC1 applies BN3+ReLU.
    k_gemm64<HH, true><<<MFC / 64, 256>>>(F, HH, cw1, cb1, SC + 2 * 128, SH + 2 * 128, N1, PART);
    k_bnfin<<<1, 128>>>(16, 1.f / MFC, g3, be3, 3);

    k_gemm64<HH, true><<<MFC / 64, 256>>>(N1, HH, cw2, cb2, SC + 3 * 128, SH + 3 * 128, N2, PART);
    k_bnfin<<<1, 128>>>(16, 1.f / MFC, g4, be4, 4);

    k_final<<<(MFC * IOUS + 255) / 256, 256>>>(cw3, cb3, out);
}

// round 14
// speedup vs baseline: 1.2734x; 1.0072x over previous
#include <cuda_runtime.h>
#include <cuda_bf16.h>
#include <math.h>
#include <stdint.h>

// ---------------- problem constants ----------------
static constexpr int BB   = 4;
static constexpr int KK   = 256;
static constexpr int NS   = 1024;      // seeds
static constexpr int CF   = 256;       // seed feature channels
static constexpr int GPP  = 64;        // grid points per proposal
static constexpr int QQ   = KK * GPP;  // 16384 queries per batch
static constexpr int M1   = BB * QQ;   // 65536 rows for conv layers
static constexpr int CIN0 = CF + 3;    // 259 logical input channels
static constexpr int KPH0 = 288;       // padded logical K for layer0 (9 chunks of 32)
static constexpr int HH   = 128;
static constexpr int MFC  = BB * KK;   // 1024 rows for FC layers
static constexpr int IOUS = 18;
static constexpr int OUTC = 77;
static constexpr int KPP  = 20;        // padded pairs per SMEM row (16 used + 4 pad)

// ---------------- scratch (static device memory; no allocations) ----------------
__device__ float g_wq[M1 * 3];
__device__ float g_rel[M1 * 3];
__device__ float g_featT[BB * NS * CF];        // [b][n][c]
__device__ int   g_idx3[M1 * 3];
__device__ float g_w3[M1 * 3];
__device__ float g_Y1[(long long)M1 * HH];
__device__ float g_Y2[(long long)M1 * HH];
__device__ float g_F [MFC * HH];               // RAW maxpool output (pre-BN3)
__device__ float g_N1[MFC * HH];
__device__ float g_N2[MFC * HH];
__device__ float g_part[512 * 256];            // per-CTA partial BN stats
__device__ float g_scale[5 * 128];
__device__ float g_shift[5 * 128];
// pre-split packed-bf16 weights, layout [ch][n][kp16]; W0 permuted+padded
__device__ uint32_t g_W0H[9 * 128 * 16], g_W0L[9 * 128 * 16];
__device__ uint32_t g_W1H[4 * 128 * 16], g_W1L[4 * 128 * 16];
__device__ uint32_t g_W2H[4 * 128 * 16], g_W2L[4 * 128 * 16];

// ---------------- small helpers ----------------
// split two fp32 values into packed-bf16 (hi pair, lo pair); word = {k_even, k_odd}
__device__ __forceinline__ void split2_bf16(float v0, float v1, uint32_t& hi, uint32_t& lo) {
    __nv_bfloat16 h0 = __float2bfloat16_rn(v0);
    __nv_bfloat16 h1 = __float2bfloat16_rn(v1);
    float l0 = v0 - __bfloat162float(h0);
    float l1 = v1 - __bfloat162float(h1);
    __nv_bfloat162 hp = __halves2bfloat162(h0, h1);
    __nv_bfloat162 lp = __floats2bfloat162_rn(l0, l1);
    hi = *reinterpret_cast<uint32_t*>(&hp);
    lo = *reinterpret_cast<uint32_t*>(&lp);
}

__device__ __forceinline__ void mma_bf16(float& c0, float& c1, float& c2, float& c3,
                                         uint32_t a0, uint32_t a1, uint32_t a2, uint32_t a3,
                                         uint32_t b0, uint32_t b1) {
    asm volatile(
        "mma.sync.aligned.m16n8k16.row.col.f32.bf16.bf16.f32 "
        "{%0,%1,%2,%3}, {%4,%5,%6,%7}, {%8,%9}, {%0,%1,%2,%3};"
        : "+f"(c0), "+f"(c1), "+f"(c2), "+f"(c3)
        : "r"(a0), "r"(a1), "r"(a2), "r"(a3), "r"(b0), "r"(b1));
}

__device__ __forceinline__ void ldsm_x4(uint32_t& r0, uint32_t& r1, uint32_t& r2, uint32_t& r3,
                                        uint32_t addr) {
    asm volatile("ldmatrix.sync.aligned.m8n8.x4.shared.b16 {%0,%1,%2,%3}, [%4];"
                 : "=r"(r0), "=r"(r1), "=r"(r2), "=r"(r3) : "r"(addr));
}

__device__ __forceinline__ void cp_async16(uint32_t smem_addr, const void* gptr) {
    asm volatile("cp.async.cg.shared.global [%0], [%1], 16;"
                 :: "r"(smem_addr), "l"(gptr));
}
__device__ __forceinline__ void cp_async_commit() {
    asm volatile("cp.async.commit_group;");
}
__device__ __forceinline__ void cp_async_wait0() {
    asm volatile("cp.async.wait_group 0;");
}

// ---------------- weight prep: fp32 -> packed bf16 hi/lo, layout [ch][n][kp16] ----------------
__global__ void k_prepW0(const float* __restrict__ W) {
    int t = blockIdx.x * blockDim.x + threadIdx.x;   // < 144*128
    int kp = t >> 7, n = t & 127;
    int k0 = 2 * kp, k1 = 2 * kp + 1;
    float v0 = 0.f, v1 = 0.f;
    if (k0 < CIN0) { int kl = (k0 < 256) ? k0 + 3 : k0 - 256; v0 = W[n * CIN0 + kl]; }
    if (k1 < CIN0) { int kl = (k1 < 256) ? k1 + 3 : k1 - 256; v1 = W[n * CIN0 + kl]; }
    uint32_t hi, lo;
    split2_bf16(v0, v1, hi, lo);
    int dst = (((kp >> 4) * 128) + n) * 16 + (kp & 15);
    g_W0H[dst] = hi; g_W0L[dst] = lo;
}

__global__ void k_prepW128(const float* __restrict__ W,
                           uint32_t* __restrict__ WH, uint32_t* __restrict__ WL) {
    int t = blockIdx.x * blockDim.x + threadIdx.x;   // < 64*128
    int kp = t >> 7, n = t & 127;
    float v0 = W[n * 128 + 2 * kp];
    float v1 = W[n * 128 + 2 * kp + 1];
    uint32_t hi, lo;
    split2_bf16(v0, v1, hi, lo);
    int dst = (((kp >> 4) * 128) + n) * 16 + (kp & 15);
    WH[dst] = hi; WL[dst] = lo;
}

// ---------------- stage-1 kernels ----------------

// seed_features [b][c][n] -> g_featT [b][n][c]
__global__ void k_transpose(const float* __restrict__ feat) {
    __shared__ float tile[32][33];
    int b  = blockIdx.z;
    int n0 = blockIdx.x * 32;
    int c0 = blockIdx.y * 32;
    const float* src = feat    + (long long)b * CF * NS;
    float*       dst = g_featT + (long long)b * NS * CF;
#pragma unroll
    for (int r = 0; r < 4; ++r) {
        int c = c0 + threadIdx.y + r * 8;
        tile[threadIdx.y + r * 8][threadIdx.x] = src[c * NS + n0 + threadIdx.x];
    }
    __syncthreads();
#pragma unroll
    for (int r = 0; r < 4; ++r) {
        int n = n0 + threadIdx.y + r * 8;
        dst[n * CF + c0 + threadIdx.x] = tile[threadIdx.x][threadIdx.y + r * 8];
    }
}

// rotate+scale grid -> g_rel, world points -> g_wq
__global__ void k_gridpoints(const float* __restrict__ center,
                             const float* __restrict__ size_,
                             const float* __restrict__ heading) {
    int m = blockIdx.x * blockDim.x + threadIdx.x;
    if (m >= M1) return;
    int g  = m & 63;
    int bk = m >> 6;
    float sx = size_[bk * 3 + 0], sy = size_[bk * 3 + 1], sz = size_[bk * 3 + 2];
    float h  = heading[bk];
    float ch = cosf(h), sh = sinf(h);
    float gx = -1.f + (float)( g >> 4      ) * (2.f / 3.f);
    float gy = -1.f + (float)((g >> 2) & 3 ) * (2.f / 3.f);
    float gz = -1.f + (float)( g       & 3 ) * (2.f / 3.f);
    float ax = gx * sx, ay = gy * sy, az = gz * sz;
    float rx = ax * ch - ay * sh;
    float ry = ax * sh + ay * ch;
    float rz = az;
    g_rel[m * 3 + 0] = rx;
    g_rel[m * 3 + 1] = ry;
    g_rel[m * 3 + 2] = rz;
    g_wq[m * 3 + 0] = rx + center[bk * 3 + 0];
    g_wq[m * 3 + 1] = ry + center[bk * 3 + 1];
    g_wq[m * 3 + 2] = rz + center[bk * 3 + 2];
}

// 3-NN per query over 1024 seeds (seeds cached in SMEM), inverse-distance weights
__global__ void k_threenn(const float* __restrict__ seed_xyz) {
    __shared__ float4 sp[NS];
    int b = blockIdx.x >> 7;
    int q = ((blockIdx.x & 127) << 7) + threadIdx.x;
    for (int i = threadIdx.x; i < NS; i += blockDim.x) {
        float x = seed_xyz[((long long)b * NS + i) * 3 + 0];
        float y = seed_xyz[((long long)b * NS + i) * 3 + 1];
        float z = seed_xyz[((long long)b * NS + i) * 3 + 2];
        sp[i] = make_float4(x, y, z, x * x + y * y + z * z);
    }
    __syncthreads();
    int m = b * QQ + q;
    float qx = g_wq[m * 3 + 0], qy = g_wq[m * 3 + 1], qz = g_wq[m * 3 + 2];
    float qq = qx * qx + qy * qy + qz * qz;
    float d0 = 1e30f, d1 = 1e30f, d2 = 1e30f;
    int   i0 = 0, i1 = 0, i2 = 0;
    for (int n = 0; n < NS; ++n) {
        float4 p = sp[n];
        float d = qq + p.w - 2.f * (qx * p.x + qy * p.y + qz * p.z);
        if (d < d2) {
            if (d < d1) {
                d2 = d1; i2 = i1;
                if (d < d0) { d1 = d0; i1 = i0; d0 = d; i0 = n; }
                else        { d1 = d;  i1 = n; }
            } else { d2 = d; i2 = n; }
        }
    }
    int ii[3] = {i0, i1, i2};
    float w[3];
#pragma unroll
    for (int j = 0; j < 3; ++j) {
        float4 p = sp[ii[j]];
        float dx = p.x - qx, dy = p.y - qy, dz = p.z - qz;
        float dist = sqrtf(dx * dx + dy * dy + dz * dz);
        w[j] = 1.f / (dist + 1e-8f);
    }
    float inv = 1.f / (w[0] + w[1] + w[2]);
#pragma unroll
    for (int j = 0; j < 3; ++j) {
        g_idx3[m * 3 + j] = ii[j];
        g_w3[m * 3 + j]   = w[j] * inv;
    }
}

// ---- split-bf16 tensor-core GEMM, ldmatrix fragment loads, fused epilogue ----
// SMEM tiles are row-major [m][kp] / [n][kp] (pad to 20 words): A-store is 2x STS.128,
// fragment loads are ldmatrix.x4 (24 per chunk vs 96 scalar LDS).
// C[m,n] = sum_k act(A[m,k]) * W[n,k] + bias[n]
// 128x128 tile, K-chunks of 32, m16n8k16 bf16 MMA, acc += aL*bH + aH*bL + aH*bH.
// 8 warps (2 over M x 4 over N), 2 CTAs/SM, single-buffered, A register-prefetched.
// W arrives pre-split [ch][n][kp16] and is fetched with coalesced cp.async.
// GATHER: layer-0; A gathered on the fly from g_featT (L2-hot) + rel xyz.
template <bool BNA, bool GATHER, bool POOL, bool STOREC>
__global__ void __launch_bounds__(256, 2)
k_gemm_bf(const float* __restrict__ A, int lda,
          const uint32_t* __restrict__ WHg,
          const uint32_t* __restrict__ WLg,
          const float* __restrict__ bias,
          const float* __restrict__ scl,
          const float* __restrict__ shf,
          float* __restrict__ C,
          float* __restrict__ partOut,
          float* __restrict__ poolOut) {
    __shared__ uint32_t AsH[128][KPP];
    __shared__ uint32_t AsL[128][KPP];
    __shared__ uint32_t WsH[128][KPP];
    __shared__ uint32_t WsL[128][KPP];
    __shared__ float redS[2][128];
    __shared__ float redQ[2][128];
    __shared__ float redM[2][128];

    const int tid  = threadIdx.x;
    const int lane = tid & 31;
    const int warp = tid >> 5;
    const int g    = lane >> 2;        // 0..7
    const int q    = lane & 3;         // 0..3
    const int wm   = warp & 1;         // 2 warps over M
    const int wn   = warp >> 1;        // 4 warps over N
    const int bm   = blockIdx.x * 128;

    float acc[4][4][4];
#pragma unroll
    for (int i = 0; i < 4; ++i)
#pragma unroll
        for (int j = 0; j < 4; ++j)
#pragma unroll
            for (int r = 0; r < 4; ++r) acc[i][j][r] = 0.f;

    const int ldrow = tid >> 1;         // 0..127
    const int ldkv  = (tid & 1) * 16;   // 0 or 16
    const int kp0   = ldkv / 2;         // 0 or 8
    const int NCH   = GATHER ? (KPH0 / 32) : 4;

    // ldmatrix lane addresses
    // A x4: lane -> row mbase+(lane&15), pair kb + (lane>>4)*4
    const int arow = lane & 15;
    const int akp  = (lane >> 4) * 4;
    uint32_t aAdrH[4], aAdrL[4];
#pragma unroll
    for (int mt = 0; mt < 4; ++mt) {
        int r = wm * 64 + mt * 16 + arow;
        aAdrH[mt] = (uint32_t)__cvta_generic_to_shared(&AsH[r][akp]);
        aAdrL[mt] = (uint32_t)__cvta_generic_to_shared(&AsL[r][akp]);
    }
    // B x4 (two nt groups): lane -> col wn*32 + t*16 + (lane>>4)*8 + (lane&7),
    //                       pair kb + ((lane>>3)&1)*4
    const int bcol = wn * 32 + ((lane >> 4) * 8) + (lane & 7);
    const int bkp  = ((lane >> 3) & 1) * 4;
    uint32_t bAdrH[2], bAdrL[2];
#pragma unroll
    for (int t = 0; t < 2; ++t) {
        bAdrH[t] = (uint32_t)__cvta_generic_to_shared(&WsH[bcol + t * 16][bkp]);
        bAdrL[t] = (uint32_t)__cvta_generic_to_shared(&WsL[bcol + t * 16][bkp]);
    }

    // W cp.async mapping: n = tid>>1, kp half = tid&1 -> coalesced 1KB per warp
    const int wcn = tid >> 1;
    const int wch = (tid & 1) * 8;
    const uint32_t dWH0 = (uint32_t)__cvta_generic_to_shared(&WsH[wcn][wch]);
    const uint32_t dWH1 = (uint32_t)__cvta_generic_to_shared(&WsH[wcn][wch + 4]);
    const uint32_t dWL0 = (uint32_t)__cvta_generic_to_shared(&WsL[wcn][wch]);
    const uint32_t dWL1 = (uint32_t)__cvta_generic_to_shared(&WsL[wcn][wch + 4]);

    // GATHER state (row fixed for the whole k-loop)
    const float *gf0 = nullptr, *gf1 = nullptr, *gf2 = nullptr;
    float gw0 = 0.f, gw1 = 0.f, gw2 = 0.f;
    float grel[3] = {0.f, 0.f, 0.f};
    if (GATHER) {
        const int m = bm + ldrow;
        const int b = m >> 14;
        int i0 = g_idx3[m * 3 + 0], i1 = g_idx3[m * 3 + 1], i2 = g_idx3[m * 3 + 2];
        gw0 = g_w3[m * 3 + 0]; gw1 = g_w3[m * 3 + 1]; gw2 = g_w3[m * 3 + 2];
        gf0 = g_featT + ((long long)b * NS + i0) * CF;
        gf1 = g_featT + ((long long)b * NS + i1) * CF;
        gf2 = g_featT + ((long long)b * NS + i2) * CF;
        grel[0] = g_rel[m * 3 + 0];
        grel[1] = g_rel[m * 3 + 1];
        grel[2] = g_rel[m * 3 + 2];
    }

    float vA[16];
    if (!GATHER) {
        const float* ap = A + (long long)(bm + ldrow) * lda + ldkv;
        float4 u0 = *(const float4*)(ap + 0);
        float4 u1 = *(const float4*)(ap + 4);
        float4 u2 = *(const float4*)(ap + 8);
        float4 u3 = *(const float4*)(ap + 12);
        vA[0]=u0.x; vA[1]=u0.y; vA[2]=u0.z; vA[3]=u0.w;
        vA[4]=u1.x; vA[5]=u1.y; vA[6]=u1.z; vA[7]=u1.w;
        vA[8]=u2.x; vA[9]=u2.y; vA[10]=u2.z; vA[11]=u2.w;
        vA[12]=u3.x; vA[13]=u3.y; vA[14]=u3.z; vA[15]=u3.w;
    }

    for (int ch = 0; ch < NCH; ++ch) {
        const int k0 = ch * 32;
        // ---- issue async W copy (overlaps the A build below) ----
        {
            const uint32_t* sH = WHg + ((ch * 128 + wcn) * 16) + wch;
            const uint32_t* sL = WLg + ((ch * 128 + wcn) * 16) + wch;
            cp_async16(dWH0, sH);
            cp_async16(dWH1, sH + 4);
            cp_async16(dWL0, sL);
            cp_async16(dWL1, sL + 4);
            cp_async_commit();
        }
        // ---- build + split A chunk -> SMEM ([m][kp], 2x STS.128 per plane) ----
        {
            float v[16];
            if (GATHER) {
                const int kbase = k0 + ldkv;
                if (kbase < 256) {
#pragma unroll
                    for (int r4 = 0; r4 < 4; ++r4) {
                        float4 a  = *(const float4*)(gf0 + kbase + r4 * 4);
                        float4 bq = *(const float4*)(gf1 + kbase + r4 * 4);
                        float4 cq = *(const float4*)(gf2 + kbase + r4 * 4);
                        v[r4 * 4 + 0] = gw0 * a.x + gw1 * bq.x + gw2 * cq.x;
                        v[r4 * 4 + 1] = gw0 * a.y + gw1 * bq.y + gw2 * cq.y;
                        v[r4 * 4 + 2] = gw0 * a.z + gw1 * bq.z + gw2 * cq.z;
                        v[r4 * 4 + 3] = gw0 * a.w + gw1 * bq.w + gw2 * cq.w;
                    }
                } else {
#pragma unroll
                    for (int i = 0; i < 16; ++i) v[i] = 0.f;
                    if (kbase == 256) { v[0] = grel[0]; v[1] = grel[1]; v[2] = grel[2]; }
                }
            } else {
#pragma unroll
                for (int i = 0; i < 16; ++i) v[i] = vA[i];
                if (BNA) {
#pragma unroll
                    for (int i = 0; i < 16; ++i) {
                        int k = k0 + ldkv + i;   // KDIM=128 in BNA mode: always valid
                        v[i] = fmaxf(v[i] * scl[k] + shf[k], 0.f);
                    }
                }
            }
            uint32_t hi[8], lo[8];
#pragma unroll
            for (int i = 0; i < 8; ++i)
                split2_bf16(v[2 * i], v[2 * i + 1], hi[i], lo[i]);
            *(uint4*)&AsH[ldrow][kp0]     = make_uint4(hi[0], hi[1], hi[2], hi[3]);
            *(uint4*)&AsH[ldrow][kp0 + 4] = make_uint4(hi[4], hi[5], hi[6], hi[7]);
            *(uint4*)&AsL[ldrow][kp0]     = make_uint4(lo[0], lo[1], lo[2], lo[3]);
            *(uint4*)&AsL[ldrow][kp0 + 4] = make_uint4(lo[4], lo[5], lo[6], lo[7]);
        }
        cp_async_wait0();
        __syncthreads();

        // ---- prefetch next A chunk (latency hidden behind MMAs; non-gather only) ----
        if (!GATHER && ch + 1 < NCH) {
            const float* ap = A + (long long)(bm + ldrow) * lda + (k0 + 32) + ldkv;
            float4 u0 = *(const float4*)(ap + 0);
            float4 u1 = *(const float4*)(ap + 4);
            float4 u2 = *(const float4*)(ap + 8);
            float4 u3 = *(const float4*)(ap + 12);
            vA[0]=u0.x; vA[1]=u0.y; vA[2]=u0.z; vA[3]=u0.w;
            vA[4]=u1.x; vA[5]=u1.y; vA[6]=u1.z; vA[7]=u1.w;
            vA[8]=u2.x; vA[9]=u2.y; vA[10]=u2.z; vA[11]=u2.w;
            vA[12]=u3.x; vA[13]=u3.y; vA[14]=u3.z; vA[15]=u3.w;
        }

        // ---- two k16 steps per chunk; fragments via ldmatrix ----
#pragma unroll
        for (int kb = 0; kb < 16; kb += 8) {
            const int kboff = kb * 4;   // bytes: 8 pairs * 4B
            uint32_t bH[4][2], bL[4][2];
#pragma unroll
            for (int t = 0; t < 2; ++t) {
                ldsm_x4(bH[2 * t][0], bH[2 * t][1], bH[2 * t + 1][0], bH[2 * t + 1][1],
                        bAdrH[t] + kboff);
                ldsm_x4(bL[2 * t][0], bL[2 * t][1], bL[2 * t + 1][0], bL[2 * t + 1][1],
                        bAdrL[t] + kboff);
            }
#pragma unroll
            for (int mt = 0; mt < 4; ++mt) {
                uint32_t aH0, aH1, aH2, aH3, aL0, aL1, aL2, aL3;
                ldsm_x4(aH0, aH1, aH2, aH3, aAdrH[mt] + kboff);
                ldsm_x4(aL0, aL1, aL2, aL3, aAdrL[mt] + kboff);
#pragma unroll
                for (int nt = 0; nt < 4; ++nt) {
                    mma_bf16(acc[mt][nt][0], acc[mt][nt][1], acc[mt][nt][2], acc[mt][nt][3],
                             aL0, aL1, aL2, aL3, bH[nt][0], bH[nt][1]);
                    mma_bf16(acc[mt][nt][0], acc[mt][nt][1], acc[mt][nt][2], acc[mt][nt][3],
                             aH0, aH1, aH2, aH3, bL[nt][0], bL[nt][1]);
                    mma_bf16(acc[mt][nt][0], acc[mt][nt][1], acc[mt][nt][2], acc[mt][nt][3],
                             aH0, aH1, aH2, aH3, bH[nt][0], bH[nt][1]);
                }
            }
        }
        __syncthreads();
    }

    // ---- fused epilogue: bias, optional store, BN stats partials, optional maxpool ----
    float bsv[4][2];
#pragma unroll
    for (int nt = 0; nt < 4; ++nt) {
        int col = wn * 32 + nt * 8 + q * 2;
        bsv[nt][0] = bias[col];
        bsv[nt][1] = bias[col + 1];
    }
    float s[4][2], s2[4][2], mx[4][2];
#pragma unroll
    for (int nt = 0; nt < 4; ++nt)
#pragma unroll
        for (int j = 0; j < 2; ++j) { s[nt][j] = 0.f; s2[nt][j] = 0.f; mx[nt][j] = -1e30f; }

#pragma unroll
    for (int mt = 0; mt < 4; ++mt) {
#pragma unroll
        for (int nt = 0; nt < 4; ++nt) {
            float v0 = acc[mt][nt][0] + bsv[nt][0];
            float v1 = acc[mt][nt][1] + bsv[nt][1];
            float v2 = acc[mt][nt][2] + bsv[nt][0];
            float v3 = acc[mt][nt][3] + bsv[nt][1];
            if (STOREC) {
                int col = wn * 32 + nt * 8 + q * 2;
                int r0  = bm + wm * 64 + mt * 16 + g;
                *(float2*)(C + (long long)r0 * 128 + col)       = make_float2(v0, v1);
                *(float2*)(C + (long long)(r0 + 8) * 128 + col) = make_float2(v2, v3);
            }
            s [nt][0] += v0 + v2;       s [nt][1] += v1 + v3;
            s2[nt][0] += v0 * v0 + v2 * v2;
            s2[nt][1] += v1 * v1 + v3 * v3;
            if (POOL) {
                mx[nt][0] = fmaxf(mx[nt][0], fmaxf(v0, v2));
                mx[nt][1] = fmaxf(mx[nt][1], fmaxf(v1, v3));
            }
        }
    }
#pragma unroll
    for (int nt = 0; nt < 4; ++nt)
#pragma unroll
        for (int j = 0; j < 2; ++j) {
#pragma unroll
            for (int mask = 4; mask <= 16; mask <<= 1) {
                s [nt][j] += __shfl_xor_sync(0xffffffff, s [nt][j], mask);
                s2[nt][j] += __shfl_xor_sync(0xffffffff, s2[nt][j], mask);
                if (POOL)
                    mx[nt][j] = fmaxf(mx[nt][j], __shfl_xor_sync(0xffffffff, mx[nt][j], mask));
            }
        }
    if (g == 0) {
#pragma unroll
        for (int nt = 0; nt < 4; ++nt)
#pragma unroll
            for (int j = 0; j < 2; ++j) {
                int col = wn * 32 + nt * 8 + q * 2 + j;
                redS[wm][col] = s[nt][j];
                redQ[wm][col] = s2[nt][j];
                if (POOL) redM[wm][col] = mx[nt][j];
            }
    }
    __syncthreads();
    if (tid < 128) {
        partOut[blockIdx.x * 256 + tid]       = redS[0][tid] + redS[1][tid];
        partOut[blockIdx.x * 256 + 128 + tid] = redQ[0][tid] + redQ[1][tid];
    }
    if (POOL) {
        poolOut[(blockIdx.x * 2 + (tid >> 7)) * 128 + (tid & 127)] = redM[tid >> 7][tid & 127];
    }
}

// reduce 512 per-CTA partials -> folded BN scale/shift (1 block, 512 threads)
__global__ void k_bnfin512(float Minv,
                           const float* __restrict__ gamma,
                           const float* __restrict__ beta,
                           int slot) {
    __shared__ float rs[4][128], rq[4][128];
    int c  = threadIdx.x & 127;
    int sl = threadIdx.x >> 7;
    float s = 0.f, q = 0.f;
    for (int b = sl * 128; b < sl * 128 + 128; ++b) {
        s += g_part[b * 256 + c];
        q += g_part[b * 256 + 128 + c];
    }
    rs[sl][c] = s; rq[sl][c] = q;
    __syncthreads();
    if (threadIdx.x < 128) {
        float S = rs[0][c] + rs[1][c] + rs[2][c] + rs[3][c];
        float Q = rq[0][c] + rq[1][c] + rq[2][c] + rq[3][c];
        float mean = S * Minv;
        float var  = Q * Minv - mean * mean;
        float rstd = rsqrtf(var + 1e-5f);
        float sc   = gamma[c] * rstd;
        g_scale[slot * 128 + c] = sc;
        g_shift[slot * 128 + c] = beta[c] - mean * sc;
    }
}

// -------- fp32 SIMT GEMM for FC layers: 64x128 tile, grid=16, fused BN-stats --------
template <int KDIM, bool BNA>
__global__ void __launch_bounds__(256)
k_gemm64(const float* __restrict__ A, int lda,
         const float* __restrict__ W,
         const float* __restrict__ bias,
         const float* __restrict__ scl,
         const float* __restrict__ shf,
         float* __restrict__ C,
         float* __restrict__ partOut) {
    __shared__ float As[16][64];
    __shared__ float Ws2[16][128];
    __shared__ float redS[16][128];
    __shared__ float redQ[16][128];
    int tid = threadIdx.x;
    int bm  = blockIdx.x * 64;
    int tx  = tid & 15, ty = tid >> 4;
    float acc[4][8];
#pragma unroll
    for (int i = 0; i < 4; ++i)
#pragma unroll
        for (int j = 0; j < 8; ++j) acc[i][j] = 0.f;

    const int KT = KDIM / 16;
    for (int kt = 0; kt < KT; ++kt) {
        int k0 = kt * 16;
        {
            int row = tid >> 2;
            int kv  = (tid & 3) * 4;
            int k   = k0 + kv;
            float4 v = *reinterpret_cast<const float4*>(A + (long long)(bm + row) * lda + k);
            if (BNA) {
                v.x = fmaxf(v.x * scl[k + 0] + shf[k + 0], 0.f);
                v.y = fmaxf(v.y * scl[k + 1] + shf[k + 1], 0.f);
                v.z = fmaxf(v.z * scl[k + 2] + shf[k + 2], 0.f);
                v.w = fmaxf(v.w * scl[k + 3] + shf[k + 3], 0.f);
            }
            As[kv + 0][row] = v.x;
            As[kv + 1][row] = v.y;
            As[kv + 2][row] = v.z;
            As[kv + 3][row] = v.w;
        }
        {
            int n  = tid >> 1;
            int kb = (tid & 1) * 8;
#pragma unroll
            for (int i = 0; i < 8; ++i)
                Ws2[kb + i][n] = W[n * KDIM + k0 + kb + i];
        }
        __syncthreads();
#pragma unroll
        for (int kk = 0; kk < 16; ++kk) {
            float a[4], w8[8];
            *reinterpret_cast<float4*>(&a[0])  = *reinterpret_cast<const float4*>(&As[kk][ty * 4]);
            *reinterpret_cast<float4*>(&w8[0]) = *reinterpret_cast<const float4*>(&Ws2[kk][tx * 8]);
            *reinterpret_cast<float4*>(&w8[4]) = *reinterpret_cast<const float4*>(&Ws2[kk][tx * 8 + 4]);
#pragma unroll
            for (int i = 0; i < 4; ++i)
#pragma unroll
                for (int j = 0; j < 8; ++j) acc[i][j] += a[i] * w8[j];
        }
        __syncthreads();
    }
    float bv[8];
#pragma unroll
    for (int j = 0; j < 8; ++j) bv[j] = bias[tx * 8 + j];
    float s[8], s2[8];
#pragma unroll
    for (int j = 0; j < 8; ++j) { s[j] = 0.f; s2[j] = 0.f; }
#pragma unroll
    for (int i = 0; i < 4; ++i) {
        long long off = (long long)(bm + ty * 4 + i) * 128 + tx * 8;
        float o[8];
#pragma unroll
        for (int j = 0; j < 8; ++j) {
            o[j] = acc[i][j] + bv[j];
            s[j] += o[j];
            s2[j] += o[j] * o[j];
        }
        *reinterpret_cast<float4*>(C + off)     = make_float4(o[0], o[1], o[2], o[3]);
        *reinterpret_cast<float4*>(C + off + 4) = make_float4(o[4], o[5], o[6], o[7]);
    }
#pragma unroll
    for (int j = 0; j < 8; ++j) {
        redS[ty][tx * 8 + j] = s[j];
        redQ[ty][tx * 8 + j] = s2[j];
    }
    __syncthreads();
    if (tid < 128) {
        float S = 0.f, Q = 0.f;
#pragma unroll
        for (int t = 0; t < 16; ++t) { S += redS[t][tid]; Q += redQ[t][tid]; }
        partOut[blockIdx.x * 256 + tid]       = S;
        partOut[blockIdx.x * 256 + 128 + tid] = Q;
    }
}

// reduce NB per-CTA partials -> folded BN scale/shift
__global__ void k_bnfin(int NB, float Minv,
                        const float* __restrict__ gamma,
                        const float* __restrict__ beta,
                        int slot) {
    int c = threadIdx.x;
    float s = 0.f, s2 = 0.f;
    for (int b = 0; b < NB; ++b) {
        s  += g_part[b * 256 + c];
        s2 += g_part[b * 256 + 128 + c];
    }
    float mean = s * Minv;
    float var  = s2 * Minv - mean * mean;
    float rstd = rsqrtf(var + 1e-5f);
    float sc   = gamma[c] * rstd;
    g_scale[slot * 128 + c] = sc;
    g_shift[slot * 128 + c] = beta[c] - mean * sc;
}

// BN5+ReLU on N2, project to the last 18 of 77 output channels
__global__ void k_final(const float* __restrict__ cw3,
                        const float* __restrict__ cb3,
                        float* __restrict__ out) {
    int t = blockIdx.x * blockDim.x + threadIdx.x;
    if (t >= MFC * IOUS) return;
    int j   = t % IOUS;
    int row = t / IOUS;
    int o   = (OUTC - IOUS) + j;
    const float* wrow = cw3 + o * 128;
    const float* x    = g_N2 + row * 128;
    float acc = cb3[o];
#pragma unroll 8
    for (int i = 0; i < 128; ++i) {
        float v = fmaxf(x[i] * g_scale[4 * 128 + i] + g_shift[4 * 128 + i], 0.f);
        acc += v * wrow[i];
    }
    out[t] = acc;
}

// ---------------- launcher ----------------
extern "C" void kernel_launch(void* const* d_in, const int* in_sizes, int n_in,
                              void* d_out, int out_size) {
    const float* center  = (const float*)d_in[0];
    const float* size_   = (const float*)d_in[1];
    const float* heading = (const float*)d_in[2];
    const float* sxyz    = (const float*)d_in[3];
    const float* sfeat   = (const float*)d_in[4];
    const float* w0  = (const float*)d_in[5];
    const float* b0  = (const float*)d_in[6];
    const float* g0  = (const float*)d_in[7];
    const float* be0 = (const float*)d_in[8];
    const float* w1  = (const float*)d_in[9];
    const float* b1  = (const float*)d_in[10];
    const float* g1  = (const float*)d_in[11];
    const float* be1 = (const float*)d_in[12];
    const float* w2  = (const float*)d_in[13];
    const float* b2  = (const float*)d_in[14];
    const float* g2  = (const float*)d_in[15];
    const float* be2 = (const float*)d_in[16];
    const float* cw1 = (const float*)d_in[17];
    const float* cb1 = (const float*)d_in[18];
    const float* g3  = (const float*)d_in[19];
    const float* be3 = (const float*)d_in[20];
    const float* cw2 = (const float*)d_in[21];
    const float* cb2 = (const float*)d_in[22];
    const float* g4  = (const float*)d_in[23];
    const float* be4 = (const float*)d_in[24];
    const float* cw3 = (const float*)d_in[25];
    const float* cb3 = (const float*)d_in[26];
    float* out = (float*)d_out;

    void *pY1, *pY2, *pF, *pN1, *pN2, *pSC, *pSH, *pPart;
    void *pW0H, *pW0L, *pW1H, *pW1L, *pW2H, *pW2L;
    cudaGetSymbolAddress(&pY1, g_Y1);
    cudaGetSymbolAddress(&pY2, g_Y2);
    cudaGetSymbolAddress(&pF,  g_F);
    cudaGetSymbolAddress(&pN1, g_N1);
    cudaGetSymbolAddress(&pN2, g_N2);
    cudaGetSymbolAddress(&pSC, g_scale);
    cudaGetSymbolAddress(&pSH, g_shift);
    cudaGetSymbolAddress(&pPart, g_part);
    cudaGetSymbolAddress(&pW0H, g_W0H);
    cudaGetSymbolAddress(&pW0L, g_W0L);
    cudaGetSymbolAddress(&pW1H, g_W1H);
    cudaGetSymbolAddress(&pW1L, g_W1L);
    cudaGetSymbolAddress(&pW2H, g_W2H);
    cudaGetSymbolAddress(&pW2L, g_W2L);
    float* Y1 = (float*)pY1;
    float* Y2 = (float*)pY2;
    float* F  = (float*)pF;
    float* N1 = (float*)pN1;
    float* N2 = (float*)pN2;
    float* SC = (float*)pSC;
    float* SH = (float*)pSH;
    float* PART = (float*)pPart;
    uint32_t* W0H = (uint32_t*)pW0H; uint32_t* W0L = (uint32_t*)pW0L;
    uint32_t* W1H = (uint32_t*)pW1H; uint32_t* W1L = (uint32_t*)pW1L;
    uint32_t* W2H = (uint32_t*)pW2H; uint32_t* W2L = (uint32_t*)pW2L;

    // stage 0: weight pre-split (tiny)
    k_prepW0<<<(144 * 128) / 256, 256>>>(w0);
    k_prepW128<<<(64 * 128) / 256, 256>>>(w1, W1H, W1L);
    k_prepW128<<<(64 * 128) / 256, 256>>>(w2, W2H, W2L);

    // stage 1: geometry + 3-NN (interp fused into GEMM0's A-loader)
    k_transpose<<<dim3(NS / 32, CF / 32, BB), dim3(32, 8)>>>(sfeat);
    k_gridpoints<<<M1 / 256, 256>>>(center, size_, heading);
    k_threenn<<<BB * 128, 128>>>(sxyz);

    // stage 2: SharedMLP on tensor cores; BN stats fused into each GEMM epilogue.
    // Layer0 gathers its input on the fly (GATHER). Last conv layer fuses the
    // 64-point maxpool (raw max; BN3+ReLU folded into FC1).
    k_gemm_bf<false, true, false, true><<<M1 / 128, 256>>>(
        nullptr, 0, W0H, W0L, b0, nullptr, nullptr, Y1, PART, nullptr);
    k_bnfin512<<<1, 512>>>(1.f / M1, g0, be0, 0);

    k_gemm_bf<true, false, false, true><<<M1 / 128, 256>>>(
        Y1, HH, W1H, W1L, b1, SC + 0 * 128, SH + 0 * 128, Y2, PART, nullptr);
    k_bnfin512<<<1, 512>>>(1.f / M1, g1, be1, 1);

    k_gemm_bf<true, false, true, false><<<M1 / 128, 256>>>(
        Y2, HH, W2H, W2L, b2, SC + 1 * 128, SH + 1 * 128, nullptr, PART, F);
    k_bnfin512<<<1, 512>>>(1.f / M1, g2, be2, 2);

    // stage 3: FC head (fp32 SIMT, 64-row tiles, fused BN stats). FC1 applies BN3+ReLU.
    k_gemm64<HH, true><<<MFC / 64, 256>>>(F, HH, cw1, cb1, SC + 2 * 128, SH + 2 * 128, N1, PART);
    k_bnfin<<<1, 128>>>(16, 1.f / MFC, g3, be3, 3);

    k_gemm64<HH, true><<<MFC / 64, 256>>>(N1, HH, cw2, cb2, SC + 3 * 128, SH + 3 * 128, N2, PART);
    k_bnfin<<<1, 128>>>(16, 1.f / MFC, g4, be4, 4);

    k_final<<<(MFC * IOUS + 255) / 256, 256>>>(cw3, cb3, out);
}

// round 15
// speedup vs baseline: 1.3209x; 1.0373x over previous
#include <cuda_runtime.h>
#include <cuda_bf16.h>
#include <math.h>
#include <stdint.h>

// ---------------- problem constants ----------------
static constexpr int BB   = 4;
static constexpr int KK   = 256;
static constexpr int NS   = 1024;      // seeds
static constexpr int CF   = 256;       // seed feature channels
static constexpr int GPP  = 64;        // grid points per proposal
static constexpr int QQ   = KK * GPP;  // 16384 queries per batch
static constexpr int M1   = BB * QQ;   // 65536 rows for conv layers
static constexpr int CIN0 = CF + 3;    // 259 logical input channels
static constexpr int KPH0 = 288;       // padded logical K for layer0 (9 chunks of 32)
static constexpr int HH   = 128;
static constexpr int MFC  = BB * KK;   // 1024 rows for FC layers
static constexpr int IOUS = 18;
static constexpr int OUTC = 77;
static constexpr int KPP  = 20;        // padded pairs per SMEM row (16 used + 4 pad)

// ---------------- scratch (static device memory; no allocations) ----------------
__device__ float g_rel[M1 * 3];
__device__ float g_featT[BB * NS * CF];        // [b][n][c]
__device__ int   g_idx3[M1 * 3];
__device__ float g_w3[M1 * 3];
__device__ float g_Y1[(long long)M1 * HH];
__device__ float g_Y2[(long long)M1 * HH];
__device__ float g_F [MFC * HH];               // RAW maxpool output (pre-BN3)
__device__ float g_N1[MFC * HH];
__device__ float g_N2[MFC * HH];
__device__ float g_part[512 * 256];            // per-CTA partial BN stats
__device__ float g_scale[5 * 128];
__device__ float g_shift[5 * 128];
// pre-split packed-bf16 weights, layout [ch][n][kp16]; W0 permuted+padded
__device__ uint32_t g_W0H[9 * 128 * 16], g_W0L[9 * 128 * 16];
__device__ uint32_t g_W1H[4 * 128 * 16], g_W1L[4 * 128 * 16];
__device__ uint32_t g_W2H[4 * 128 * 16], g_W2L[4 * 128 * 16];

// ---------------- small helpers ----------------
// split two fp32 values into packed-bf16 (hi pair, lo pair); word = {k_even, k_odd}
__device__ __forceinline__ void split2_bf16(float v0, float v1, uint32_t& hi, uint32_t& lo) {
    __nv_bfloat16 h0 = __float2bfloat16_rn(v0);
    __nv_bfloat16 h1 = __float2bfloat16_rn(v1);
    float l0 = v0 - __bfloat162float(h0);
    float l1 = v1 - __bfloat162float(h1);
    __nv_bfloat162 hp = __halves2bfloat162(h0, h1);
    __nv_bfloat162 lp = __floats2bfloat162_rn(l0, l1);
    hi = *reinterpret_cast<uint32_t*>(&hp);
    lo = *reinterpret_cast<uint32_t*>(&lp);
}

__device__ __forceinline__ void mma_bf16(float& c0, float& c1, float& c2, float& c3,
                                         uint32_t a0, uint32_t a1, uint32_t a2, uint32_t a3,
                                         uint32_t b0, uint32_t b1) {
    asm volatile(
        "mma.sync.aligned.m16n8k16.row.col.f32.bf16.bf16.f32 "
        "{%0,%1,%2,%3}, {%4,%5,%6,%7}, {%8,%9}, {%0,%1,%2,%3};"
        : "+f"(c0), "+f"(c1), "+f"(c2), "+f"(c3)
        : "r"(a0), "r"(a1), "r"(a2), "r"(a3), "r"(b0), "r"(b1));
}

__device__ __forceinline__ void ldsm_x4(uint32_t& r0, uint32_t& r1, uint32_t& r2, uint32_t& r3,
                                        uint32_t addr) {
    asm volatile("ldmatrix.sync.aligned.m8n8.x4.shared.b16 {%0,%1,%2,%3}, [%4];"
                 : "=r"(r0), "=r"(r1), "=r"(r2), "=r"(r3) : "r"(addr));
}

__device__ __forceinline__ void cp_async16(uint32_t smem_addr, const void* gptr) {
    asm volatile("cp.async.cg.shared.global [%0], [%1], 16;"
                 :: "r"(smem_addr), "l"(gptr));
}
__device__ __forceinline__ void cp_async_commit() {
    asm volatile("cp.async.commit_group;");
}
__device__ __forceinline__ void cp_async_wait0() {
    asm volatile("cp.async.wait_group 0;");
}

// ---------------- merged weight prep: fp32 -> packed bf16 hi/lo, [ch][n][kp16] ----------------
// flat index: [0, 18432) -> W0 ; [18432, 26624) -> W1 ; [26624, 34816) -> W2
__global__ void k_prepW(const float* __restrict__ W0,
                        const float* __restrict__ W1,
                        const float* __restrict__ W2) {
    int t = blockIdx.x * blockDim.x + threadIdx.x;
    if (t < 144 * 128) {
        int kp = t >> 7, n = t & 127;
        int k0 = 2 * kp, k1 = 2 * kp + 1;
        float v0 = 0.f, v1 = 0.f;
        if (k0 < CIN0) { int kl = (k0 < 256) ? k0 + 3 : k0 - 256; v0 = W0[n * CIN0 + kl]; }
        if (k1 < CIN0) { int kl = (k1 < 256) ? k1 + 3 : k1 - 256; v1 = W0[n * CIN0 + kl]; }
        uint32_t hi, lo;
        split2_bf16(v0, v1, hi, lo);
        int dst = (((kp >> 4) * 128) + n) * 16 + (kp & 15);
        g_W0H[dst] = hi; g_W0L[dst] = lo;
    } else {
        int u = t - 144 * 128;
        const float* W  = (u < 64 * 128) ? W1 : W2;
        uint32_t* WH    = (u < 64 * 128) ? g_W1H : g_W2H;
        uint32_t* WL    = (u < 64 * 128) ? g_W1L : g_W2L;
        if (u >= 64 * 128) u -= 64 * 128;
        int kp = u >> 7, n = u & 127;
        float v0 = W[n * 128 + 2 * kp];
        float v1 = W[n * 128 + 2 * kp + 1];
        uint32_t hi, lo;
        split2_bf16(v0, v1, hi, lo);
        int dst = (((kp >> 4) * 128) + n) * 16 + (kp & 15);
        WH[dst] = hi; WL[dst] = lo;
    }
}

// ---------------- stage-1 kernels ----------------

// seed_features [b][c][n] -> g_featT [b][n][c]
__global__ void k_transpose(const float* __restrict__ feat) {
    __shared__ float tile[32][33];
    int b  = blockIdx.z;
    int n0 = blockIdx.x * 32;
    int c0 = blockIdx.y * 32;
    const float* src = feat    + (long long)b * CF * NS;
    float*       dst = g_featT + (long long)b * NS * CF;
#pragma unroll
    for (int r = 0; r < 4; ++r) {
        int c = c0 + threadIdx.y + r * 8;
        tile[threadIdx.y + r * 8][threadIdx.x] = src[c * NS + n0 + threadIdx.x];
    }
    __syncthreads();
#pragma unroll
    for (int r = 0; r < 4; ++r) {
        int n = n0 + threadIdx.y + r * 8;
        dst[n * CF + c0 + threadIdx.x] = tile[threadIdx.x][threadIdx.y + r * 8];
    }
}

// fused grid-point + 3-NN kernel: computes rel/world point inline, writes g_rel,
// then scans 1024 seeds (SMEM-cached; sp.w = -0.5*|p|^2) maximizing
// t = q.p - 0.5|p|^2  (equivalent ordering to minimizing |q-p|^2).
__global__ void k_threenn(const float* __restrict__ center,
                          const float* __restrict__ size_,
                          const float* __restrict__ heading,
                          const float* __restrict__ seed_xyz) {
    __shared__ float4 sp[NS];
    int b = blockIdx.x >> 7;
    int q = ((blockIdx.x & 127) << 7) + threadIdx.x;
    for (int i = threadIdx.x; i < NS; i += blockDim.x) {
        float x = seed_xyz[((long long)b * NS + i) * 3 + 0];
        float y = seed_xyz[((long long)b * NS + i) * 3 + 1];
        float z = seed_xyz[((long long)b * NS + i) * 3 + 2];
        sp[i] = make_float4(x, y, z, -0.5f * (x * x + y * y + z * z));
    }
    __syncthreads();

    int m  = b * QQ + q;
    int g  = m & 63;
    int bk = m >> 6;
    float sx = size_[bk * 3 + 0], sy = size_[bk * 3 + 1], sz = size_[bk * 3 + 2];
    float h  = heading[bk];
    float ch = cosf(h), sh = sinf(h);
    float gx = -1.f + (float)( g >> 4      ) * (2.f / 3.f);
    float gy = -1.f + (float)((g >> 2) & 3 ) * (2.f / 3.f);
    float gz = -1.f + (float)( g       & 3 ) * (2.f / 3.f);
    float ax = gx * sx, ay = gy * sy, az = gz * sz;
    float rx = ax * ch - ay * sh;
    float ry = ax * sh + ay * ch;
    float rz = az;
    g_rel[m * 3 + 0] = rx;
    g_rel[m * 3 + 1] = ry;
    g_rel[m * 3 + 2] = rz;
    float qx = rx + center[bk * 3 + 0];
    float qy = ry + center[bk * 3 + 1];
    float qz = rz + center[bk * 3 + 2];

    float t0 = -1e30f, t1 = -1e30f, t2 = -1e30f;   // 3 LARGEST t
    int   i0 = 0, i1 = 0, i2 = 0;
#pragma unroll 4
    for (int n = 0; n < NS; ++n) {
        float4 p = sp[n];
        float t = fmaf(qx, p.x, fmaf(qy, p.y, fmaf(qz, p.z, p.w)));
        if (t > t2) {
            if (t > t1) {
                t2 = t1; i2 = i1;
                if (t > t0) { t1 = t0; i1 = i0; t0 = t; i0 = n; }
                else        { t1 = t;  i1 = n; }
            } else { t2 = t; i2 = n; }
        }
    }
    int ii[3] = {i0, i1, i2};
    float w[3];
#pragma unroll
    for (int j = 0; j < 3; ++j) {
        float4 p = sp[ii[j]];
        float dx = p.x - qx, dy = p.y - qy, dz = p.z - qz;
        float dist = sqrtf(dx * dx + dy * dy + dz * dz);
        w[j] = 1.f / (dist + 1e-8f);
    }
    float inv = 1.f / (w[0] + w[1] + w[2]);
#pragma unroll
    for (int j = 0; j < 3; ++j) {
        g_idx3[m * 3 + j] = ii[j];
        g_w3[m * 3 + j]   = w[j] * inv;
    }
}

// ---- split-bf16 tensor-core GEMM, ldmatrix fragment loads, fused epilogue ----
// (structure identical to the measured 284.7us round-14 kernel)
template <bool BNA, bool GATHER, bool POOL, bool STOREC>
__global__ void __launch_bounds__(256, 2)
k_gemm_bf(const float* __restrict__ A, int lda,
          const uint32_t* __restrict__ WHg,
          const uint32_t* __restrict__ WLg,
          const float* __restrict__ bias,
          const float* __restrict__ scl,
          const float* __restrict__ shf,
          float* __restrict__ C,
          float* __restrict__ partOut,
          float* __restrict__ poolOut) {
    __shared__ uint32_t AsH[128][KPP];
    __shared__ uint32_t AsL[128][KPP];
    __shared__ uint32_t WsH[128][KPP];
    __shared__ uint32_t WsL[128][KPP];
    __shared__ float redS[2][128];
    __shared__ float redQ[2][128];
    __shared__ float redM[2][128];

    const int tid  = threadIdx.x;
    const int lane = tid & 31;
    const int warp = tid >> 5;
    const int g    = lane >> 2;        // 0..7
    const int q    = lane & 3;         // 0..3
    const int wm   = warp & 1;         // 2 warps over M
    const int wn   = warp >> 1;        // 4 warps over N
    const int bm   = blockIdx.x * 128;

    float acc[4][4][4];
#pragma unroll
    for (int i = 0; i < 4; ++i)
#pragma unroll
        for (int j = 0; j < 4; ++j)
#pragma unroll
            for (int r = 0; r < 4; ++r) acc[i][j][r] = 0.f;

    const int ldrow = tid >> 1;         // 0..127
    const int ldkv  = (tid & 1) * 16;   // 0 or 16
    const int kp0   = ldkv / 2;         // 0 or 8
    const int NCH   = GATHER ? (KPH0 / 32) : 4;

    // ldmatrix lane addresses
    const int arow = lane & 15;
    const int akp  = (lane >> 4) * 4;
    uint32_t aAdrH[4], aAdrL[4];
#pragma unroll
    for (int mt = 0; mt < 4; ++mt) {
        int r = wm * 64 + mt * 16 + arow;
        aAdrH[mt] = (uint32_t)__cvta_generic_to_shared(&AsH[r][akp]);
        aAdrL[mt] = (uint32_t)__cvta_generic_to_shared(&AsL[r][akp]);
    }
    const int bcol = wn * 32 + ((lane >> 4) * 8) + (lane & 7);
    const int bkp  = ((lane >> 3) & 1) * 4;
    uint32_t bAdrH[2], bAdrL[2];
#pragma unroll
    for (int t = 0; t < 2; ++t) {
        bAdrH[t] = (uint32_t)__cvta_generic_to_shared(&WsH[bcol + t * 16][bkp]);
        bAdrL[t] = (uint32_t)__cvta_generic_to_shared(&WsL[bcol + t * 16][bkp]);
    }

    // W cp.async mapping: n = tid>>1, kp half = tid&1 -> coalesced
    const int wcn = tid >> 1;
    const int wch = (tid & 1) * 8;
    const uint32_t dWH0 = (uint32_t)__cvta_generic_to_shared(&WsH[wcn][wch]);
    const uint32_t dWH1 = (uint32_t)__cvta_generic_to_shared(&WsH[wcn][wch + 4]);
    const uint32_t dWL0 = (uint32_t)__cvta_generic_to_shared(&WsL[wcn][wch]);
    const uint32_t dWL1 = (uint32_t)__cvta_generic_to_shared(&WsL[wcn][wch + 4]);

    // GATHER state (row fixed for the whole k-loop)
    const float *gf0 = nullptr, *gf1 = nullptr, *gf2 = nullptr;
    float gw0 = 0.f, gw1 = 0.f, gw2 = 0.f;
    float grel[3] = {0.f, 0.f, 0.f};
    if (GATHER) {
        const int m = bm + ldrow;
        const int b = m >> 14;
        int i0 = g_idx3[m * 3 + 0], i1 = g_idx3[m * 3 + 1], i2 = g_idx3[m * 3 + 2];
        gw0 = g_w3[m * 3 + 0]; gw1 = g_w3[m * 3 + 1]; gw2 = g_w3[m * 3 + 2];
        gf0 = g_featT + ((long long)b * NS + i0) * CF;
        gf1 = g_featT + ((long long)b * NS + i1) * CF;
        gf2 = g_featT + ((long long)b * NS + i2) * CF;
        grel[0] = g_rel[m * 3 + 0];
        grel[1] = g_rel[m * 3 + 1];
        grel[2] = g_rel[m * 3 + 2];
    }

    float vA[16];
    if (!GATHER) {
        const float* ap = A + (long long)(bm + ldrow) * lda + ldkv;
        float4 u0 = *(const float4*)(ap + 0);
        float4 u1 = *(const float4*)(ap + 4);
        float4 u2 = *(const float4*)(ap + 8);
        float4 u3 = *(const float4*)(ap + 12);
        vA[0]=u0.x; vA[1]=u0.y; vA[2]=u0.z; vA[3]=u0.w;
        vA[4]=u1.x; vA[5]=u1.y; vA[6]=u1.z; vA[7]=u1.w;
        vA[8]=u2.x; vA[9]=u2.y; vA[10]=u2.z; vA[11]=u2.w;
        vA[12]=u3.x; vA[13]=u3.y; vA[14]=u3.z; vA[15]=u3.w;
    }

    for (int ch = 0; ch < NCH; ++ch) {
        const int k0 = ch * 32;
        // ---- issue async W copy (overlaps the A build below) ----
        {
            const uint32_t* sH = WHg + ((ch * 128 + wcn) * 16) + wch;
            const uint32_t* sL = WLg + ((ch * 128 + wcn) * 16) + wch;
            cp_async16(dWH0, sH);
            cp_async16(dWH1, sH + 4);
            cp_async16(dWL0, sL);
            cp_async16(dWL1, sL + 4);
            cp_async_commit();
        }
        // ---- build + split A chunk -> SMEM ([m][kp], 2x STS.128 per plane) ----
        {
            float v[16];
            if (GATHER) {
                const int kbase = k0 + ldkv;
                if (kbase < 256) {
#pragma unroll
                    for (int r4 = 0; r4 < 4; ++r4) {
                        float4 a  = *(const float4*)(gf0 + kbase + r4 * 4);
                        float4 bq = *(const float4*)(gf1 + kbase + r4 * 4);
                        float4 cq = *(const float4*)(gf2 + kbase + r4 * 4);
                        v[r4 * 4 + 0] = gw0 * a.x + gw1 * bq.x + gw2 * cq.x;
                        v[r4 * 4 + 1] = gw0 * a.y + gw1 * bq.y + gw2 * cq.y;
                        v[r4 * 4 + 2] = gw0 * a.z + gw1 * bq.z + gw2 * cq.z;
                        v[r4 * 4 + 3] = gw0 * a.w + gw1 * bq.w + gw2 * cq.w;
                    }
                } else {
#pragma unroll
                    for (int i = 0; i < 16; ++i) v[i] = 0.f;
                    if (kbase == 256) { v[0] = grel[0]; v[1] = grel[1]; v[2] = grel[2]; }
                }
            } else {
#pragma unroll
                for (int i = 0; i < 16; ++i) v[i] = vA[i];
                if (BNA) {
#pragma unroll
                    for (int i = 0; i < 16; ++i) {
                        int k = k0 + ldkv + i;   // KDIM=128 in BNA mode: always valid
                        v[i] = fmaxf(v[i] * scl[k] + shf[k], 0.f);
                    }
                }
            }
            uint32_t hi[8], lo[8];
#pragma unroll
            for (int i = 0; i < 8; ++i)
                split2_bf16(v[2 * i], v[2 * i + 1], hi[i], lo[i]);
            *(uint4*)&AsH[ldrow][kp0]     = make_uint4(hi[0], hi[1], hi[2], hi[3]);
            *(uint4*)&AsH[ldrow][kp0 + 4] = make_uint4(hi[4], hi[5], hi[6], hi[7]);
            *(uint4*)&AsL[ldrow][kp0]     = make_uint4(lo[0], lo[1], lo[2], lo[3]);
            *(uint4*)&AsL[ldrow][kp0 + 4] = make_uint4(lo[4], lo[5], lo[6], lo[7]);
        }
        cp_async_wait0();
        __syncthreads();

        // ---- prefetch next A chunk (latency hidden behind MMAs; non-gather only) ----
        if (!GATHER && ch + 1 < NCH) {
            const float* ap = A + (long long)(bm + ldrow) * lda + (k0 + 32) + ldkv;
            float4 u0 = *(const float4*)(ap + 0);
            float4 u1 = *(const float4*)(ap + 4);
            float4 u2 = *(const float4*)(ap + 8);
            float4 u3 = *(const float4*)(ap + 12);
            vA[0]=u0.x; vA[1]=u0.y; vA[2]=u0.z; vA[3]=u0.w;
            vA[4]=u1.x; vA[5]=u1.y; vA[6]=u1.z; vA[7]=u1.w;
            vA[8]=u2.x; vA[9]=u2.y; vA[10]=u2.z; vA[11]=u2.w;
            vA[12]=u3.x; vA[13]=u3.y; vA[14]=u3.z; vA[15]=u3.w;
        }

        // ---- two k16 steps per chunk; fragments via ldmatrix ----
#pragma unroll
        for (int kb = 0; kb < 16; kb += 8) {
            const int kboff = kb * 4;   // bytes: 8 pairs * 4B
            uint32_t bH[4][2], bL[4][2];
#pragma unroll
            for (int t = 0; t < 2; ++t) {
                ldsm_x4(bH[2 * t][0], bH[2 * t][1], bH[2 * t + 1][0], bH[2 * t + 1][1],
                        bAdrH[t] + kboff);
                ldsm_x4(bL[2 * t][0], bL[2 * t][1], bL[2 * t + 1][0], bL[2 * t + 1][1],
                        bAdrL[t] + kboff);
            }
#pragma unroll
            for (int mt = 0; mt < 4; ++mt) {
                uint32_t aH0, aH1, aH2, aH3, aL0, aL1, aL2, aL3;
                ldsm_x4(aH0, aH1, aH2, aH3, aAdrH[mt] + kboff);
                ldsm_x4(aL0, aL1, aL2, aL3, aAdrL[mt] + kboff);
#pragma unroll
                for (int nt = 0; nt < 4; ++nt) {
                    mma_bf16(acc[mt][nt][0], acc[mt][nt][1], acc[mt][nt][2], acc[mt][nt][3],
                             aL0, aL1, aL2, aL3, bH[nt][0], bH[nt][1]);
                    mma_bf16(acc[mt][nt][0], acc[mt][nt][1], acc[mt][nt][2], acc[mt][nt][3],
                             aH0, aH1, aH2, aH3, bL[nt][0], bL[nt][1]);
                    mma_bf16(acc[mt][nt][0], acc[mt][nt][1], acc[mt][nt][2], acc[mt][nt][3],
                             aH0, aH1, aH2, aH3, bH[nt][0], bH[nt][1]);
                }
            }
        }
        __syncthreads();
    }

    // ---- fused epilogue: bias, optional store, BN stats partials, optional maxpool ----
    float bsv[4][2];
#pragma unroll
    for (int nt = 0; nt < 4; ++nt) {
        int col = wn * 32 + nt * 8 + q * 2;
        bsv[nt][0] = bias[col];
        bsv[nt][1] = bias[col + 1];
    }
    float s[4][2], s2[4][2], mx[4][2];
#pragma unroll
    for (int nt = 0; nt < 4; ++nt)
#pragma unroll
        for (int j = 0; j < 2; ++j) { s[nt][j] = 0.f; s2[nt][j] = 0.f; mx[nt][j] = -1e30f; }

#pragma unroll
    for (int mt = 0; mt < 4; ++mt) {
#pragma unroll
        for (int nt = 0; nt < 4; ++nt) {
            float v0 = acc[mt][nt][0] + bsv[nt][0];
            float v1 = acc[mt][nt][1] + bsv[nt][1];
            float v2 = acc[mt][nt][2] + bsv[nt][0];
            float v3 = acc[mt][nt][3] + bsv[nt][1];
            if (STOREC) {
                int col = wn * 32 + nt * 8 + q * 2;
                int r0  = bm + wm * 64 + mt * 16 + g;
                *(float2*)(C + (long long)r0 * 128 + col)       = make_float2(v0, v1);
                *(float2*)(C + (long long)(r0 + 8) * 128 + col) = make_float2(v2, v3);
            }
            s [nt][0] += v0 + v2;       s [nt][1] += v1 + v3;
            s2[nt][0] += v0 * v0 + v2 * v2;
            s2[nt][1] += v1 * v1 + v3 * v3;
            if (POOL) {
                mx[nt][0] = fmaxf(mx[nt][0], fmaxf(v0, v2));
                mx[nt][1] = fmaxf(mx[nt][1], fmaxf(v1, v3));
            }
        }
    }
#pragma unroll
    for (int nt = 0; nt < 4; ++nt)
#pragma unroll
        for (int j = 0; j < 2; ++j) {
#pragma unroll
            for (int mask = 4; mask <= 16; mask <<= 1) {
                s [nt][j] += __shfl_xor_sync(0xffffffff, s [nt][j], mask);
                s2[nt][j] += __shfl_xor_sync(0xffffffff, s2[nt][j], mask);
                if (POOL)
                    mx[nt][j] = fmaxf(mx[nt][j], __shfl_xor_sync(0xffffffff, mx[nt][j], mask));
            }
        }
    if (g == 0) {
#pragma unroll
        for (int nt = 0; nt < 4; ++nt)
#pragma unroll
            for (int j = 0; j < 2; ++j) {
                int col = wn * 32 + nt * 8 + q * 2 + j;
                redS[wm][col] = s[nt][j];
                redQ[wm][col] = s2[nt][j];
                if (POOL) redM[wm][col] = mx[nt][j];
            }
    }
    __syncthreads();
    if (tid < 128) {
        partOut[blockIdx.x * 256 + tid]       = redS[0][tid] + redS[1][tid];
        partOut[blockIdx.x * 256 + 128 + tid] = redQ[0][tid] + redQ[1][tid];
    }
    if (POOL) {
        poolOut[(blockIdx.x * 2 + (tid >> 7)) * 128 + (tid & 127)] = redM[tid >> 7][tid & 127];
    }
}

// reduce 512 per-CTA partials -> folded BN scale/shift (1 block, 512 threads)
__global__ void k_bnfin512(float Minv,
                           const float* __restrict__ gamma,
                           const float* __restrict__ beta,
                           int slot) {
    __shared__ float rs[4][128], rq[4][128];
    int c  = threadIdx.x & 127;
    int sl = threadIdx.x >> 7;
    float s = 0.f, q = 0.f;
    for (int b = sl * 128; b < sl * 128 + 128; ++b) {
        s += g_part[b * 256 + c];
        q += g_part[b * 256 + 128 + c];
    }
    rs[sl][c] = s; rq[sl][c] = q;
    __syncthreads();
    if (threadIdx.x < 128) {
        float S = rs[0][c] + rs[1][c] + rs[2][c] + rs[3][c];
        float Q = rq[0][c] + rq[1][c] + rq[2][c] + rq[3][c];
        float mean = S * Minv;
        float var  = Q * Minv - mean * mean;
        float rstd = rsqrtf(var + 1e-5f);
        float sc   = gamma[c] * rstd;
        g_scale[slot * 128 + c] = sc;
        g_shift[slot * 128 + c] = beta[c] - mean * sc;
    }
}

// -------- fp32 SIMT GEMM for FC layers: 64x128 tile, grid=16, fused BN-stats --------
template <int KDIM, bool BNA>
__global__ void __launch_bounds__(256)
k_gemm64(const float* __restrict__ A, int lda,
         const float* __restrict__ W,
         const float* __restrict__ bias,
         const float* __restrict__ scl,
         const float* __restrict__ shf,
         float* __restrict__ C,
         float* __restrict__ partOut) {
    __shared__ float As[16][64];
    __shared__ float Ws2[16][128];
    __shared__ float redS[16][128];
    __shared__ float redQ[16][128];
    int tid = threadIdx.x;
    int bm  = blockIdx.x * 64;
    int tx  = tid & 15, ty = tid >> 4;
    float acc[4][8];
#pragma unroll
    for (int i = 0; i < 4; ++i)
#pragma unroll
        for (int j = 0; j < 8; ++j) acc[i][j] = 0.f;

    const int KT = KDIM / 16;
    for (int kt = 0; kt < KT; ++kt) {
        int k0 = kt * 16;
        {
            int row = tid >> 2;
            int kv  = (tid & 3) * 4;
            int k   = k0 + kv;
            float4 v = *reinterpret_cast<const float4*>(A + (long long)(bm + row) * lda + k);
            if (BNA) {
                v.x = fmaxf(v.x * scl[k + 0] + shf[k + 0], 0.f);
                v.y = fmaxf(v.y * scl[k + 1] + shf[k + 1], 0.f);
                v.z = fmaxf(v.z * scl[k + 2] + shf[k + 2], 0.f);
                v.w = fmaxf(v.w * scl[k + 3] + shf[k + 3], 0.f);
            }
            As[kv + 0][row] = v.x;
            As[kv + 1][row] = v.y;
            As[kv + 2][row] = v.z;
            As[kv + 3][row] = v.w;
        }
        {
            int n  = tid >> 1;
            int kb = (tid & 1) * 8;
#pragma unroll
            for (int i = 0; i < 8; ++i)
                Ws2[kb + i][n] = W[n * KDIM + k0 + kb + i];
        }
        __syncthreads();
#pragma unroll
        for (int kk = 0; kk < 16; ++kk) {
            float a[4], w8[8];
            *reinterpret_cast<float4*>(&a[0])  = *reinterpret_cast<const float4*>(&As[kk][ty * 4]);
            *reinterpret_cast<float4*>(&w8[0]) = *reinterpret_cast<const float4*>(&Ws2[kk][tx * 8]);
            *reinterpret_cast<float4*>(&w8[4]) = *reinterpret_cast<const float4*>(&Ws2[kk][tx * 8 + 4]);
#pragma unroll
            for (int i = 0; i < 4; ++i)
#pragma unroll
                for (int j = 0; j < 8; ++j) acc[i][j] += a[i] * w8[j];
        }
        __syncthreads();
    }
    float bv[8];
#pragma unroll
    for (int j = 0; j < 8; ++j) bv[j] = bias[tx * 8 + j];
    float s[8], s2[8];
#pragma unroll
    for (int j = 0; j < 8; ++j) { s[j] = 0.f; s2[j] = 0.f; }
#pragma unroll
    for (int i = 0; i < 4; ++i) {
        long long off = (long long)(bm + ty * 4 + i) * 128 + tx * 8;
        float o[8];
#pragma unroll
        for (int j = 0; j < 8; ++j) {
            o[j] = acc[i][j] + bv[j];
            s[j] += o[j];
            s2[j] += o[j] * o[j];
        }
        *reinterpret_cast<float4*>(C + off)     = make_float4(o[0], o[1], o[2], o[3]);
        *reinterpret_cast<float4*>(C + off + 4) = make_float4(o[4], o[5], o[6], o[7]);
    }
#pragma unroll
    for (int j = 0; j < 8; ++j) {
        redS[ty][tx * 8 + j] = s[j];
        redQ[ty][tx * 8 + j] = s2[j];
    }
    __syncthreads();
    if (tid < 128) {
        float S = 0.f, Q = 0.f;
#pragma unroll
        for (int t = 0; t < 16; ++t) { S += redS[t][tid]; Q += redQ[t][tid]; }
        partOut[blockIdx.x * 256 + tid]       = S;
        partOut[blockIdx.x * 256 + 128 + tid] = Q;
    }
}

// reduce NB per-CTA partials -> folded BN scale/shift
__global__ void k_bnfin(int NB, float Minv,
                        const float* __restrict__ gamma,
                        const float* __restrict__ beta,
                        int slot) {
    int c = threadIdx.x;
    float s = 0.f, s2 = 0.f;
    for (int b = 0; b < NB; ++b) {
        s  += g_part[b * 256 + c];
        s2 += g_part[b * 256 + 128 + c];
    }
    float mean = s * Minv;
    float var  = s2 * Minv - mean * mean;
    float rstd = rsqrtf(var + 1e-5f);
    float sc   = gamma[c] * rstd;
    g_scale[slot * 128 + c] = sc;
    g_shift[slot * 128 + c] = beta[c] - mean * sc;
}

// BN5+ReLU on N2, project to the last 18 of 77 output channels
__global__ void k_final(const float* __restrict__ cw3,
                        const float* __restrict__ cb3,
                        float* __restrict__ out) {
    int t = blockIdx.x * blockDim.x + threadIdx.x;
    if (t >= MFC * IOUS) return;
    int j   = t % IOUS;
    int row = t / IOUS;
    int o   = (OUTC - IOUS) + j;
    const float* wrow = cw3 + o * 128;
    const float* x    = g_N2 + row * 128;
    float acc = cb3[o];
#pragma unroll 8
    for (int i = 0; i < 128; ++i) {
        float v = fmaxf(x[i] * g_scale[4 * 128 + i] + g_shift[4 * 128 + i], 0.f);
        acc += v * wrow[i];
    }
    out[t] = acc;
}

// ---------------- launcher ----------------
extern "C" void kernel_launch(void* const* d_in, const int* in_sizes, int n_in,
                              void* d_out, int out_size) {
    const float* center  = (const float*)d_in[0];
    const float* size_   = (const float*)d_in[1];
    const float* heading = (const float*)d_in[2];
    const float* sxyz    = (const float*)d_in[3];
    const float* sfeat   = (const float*)d_in[4];
    const float* w0  = (const float*)d_in[5];
    const float* b0  = (const float*)d_in[6];
    const float* g0  = (const float*)d_in[7];
    const float* be0 = (const float*)d_in[8];
    const float* w1  = (const float*)d_in[9];
    const float* b1  = (const float*)d_in[10];
    const float* g1  = (const float*)d_in[11];
    const float* be1 = (const float*)d_in[12];
    const float* w2  = (const float*)d_in[13];
    const float* b2  = (const float*)d_in[14];
    const float* g2  = (const float*)d_in[15];
    const float* be2 = (const float*)d_in[16];
    const float* cw1 = (const float*)d_in[17];
    const float* cb1 = (const float*)d_in[18];
    const float* g3  = (const float*)d_in[19];
    const float* be3 = (const float*)d_in[20];
    const float* cw2 = (const float*)d_in[21];
    const float* cb2 = (const float*)d_in[22];
    const float* g4  = (const float*)d_in[23];
    const float* be4 = (const float*)d_in[24];
    const float* cw3 = (const float*)d_in[25];
    const float* cb3 = (const float*)d_in[26];
    float* out = (float*)d_out;

    void *pY1, *pY2, *pF, *pN1, *pN2, *pSC, *pSH, *pPart;
    void *pW0H, *pW0L, *pW1H, *pW1L, *pW2H, *pW2L;
    cudaGetSymbolAddress(&pY1, g_Y1);
    cudaGetSymbolAddress(&pY2, g_Y2);
    cudaGetSymbolAddress(&pF,  g_F);
    cudaGetSymbolAddress(&pN1, g_N1);
    cudaGetSymbolAddress(&pN2, g_N2);
    cudaGetSymbolAddress(&pSC, g_scale);
    cudaGetSymbolAddress(&pSH, g_shift);
    cudaGetSymbolAddress(&pPart, g_part);
    cudaGetSymbolAddress(&pW0H, g_W0H);
    cudaGetSymbolAddress(&pW0L, g_W0L);
    cudaGetSymbolAddress(&pW1H, g_W1H);
    cudaGetSymbolAddress(&pW1L, g_W1L);
    cudaGetSymbolAddress(&pW2H, g_W2H);
    cudaGetSymbolAddress(&pW2L, g_W2L);
    float* Y1 = (float*)pY1;
    float* Y2 = (float*)pY2;
    float* F  = (float*)pF;
    float* N1 = (float*)pN1;
    float* N2 = (float*)pN2;
    float* SC = (float*)pSC;
    float* SH = (float*)pSH;
    float* PART = (float*)pPart;
    uint32_t* W0H = (uint32_t*)pW0H; uint32_t* W0L = (uint32_t*)pW0L;
    uint32_t* W1H = (uint32_t*)pW1H; uint32_t* W1L = (uint32_t*)pW1L;
    uint32_t* W2H = (uint32_t*)pW2H; uint32_t* W2L = (uint32_t*)pW2L;

    // stage 0: merged weight pre-split (one launch; 144*128 + 2*64*128 = 34816 threads)
    k_prepW<<<(34816 + 255) / 256, 256>>>(w0, w1, w2);

    // stage 1: transpose + fused gridpoint/3-NN (gridpoints kernel eliminated)
    k_transpose<<<dim3(NS / 32, CF / 32, BB), dim3(32, 8)>>>(sfeat);
    k_threenn<<<BB * 128, 128>>>(center, size_, heading, sxyz);

    // stage 2: SharedMLP on tensor cores; BN stats fused into each GEMM epilogue.
    k_gemm_bf<false, true, false, true><<<M1 / 128, 256>>>(
        nullptr, 0, W0H, W0L, b0, nullptr, nullptr, Y1, PART, nullptr);
    k_bnfin512<<<1, 512>>>(1.f / M1, g0, be0, 0);

    k_gemm_bf<true, false, false, true><<<M1 / 128, 256>>>(
        Y1, HH, W1H, W1L, b1, SC + 0 * 128, SH + 0 * 128, Y2, PART, nullptr);
    k_bnfin512<<<1, 512>>>(1.f / M1, g1, be1, 1);

    k_gemm_bf<true, false, true, false><<<M1 / 128, 256>>>(
        Y2, HH, W2H, W2L, b2, SC + 1 * 128, SH + 1 * 128, nullptr, PART, F);
    k_bnfin512<<<1, 512>>>(1.f / M1, g2, be2, 2);

    // stage 3: FC head (fp32 SIMT, 64-row tiles, fused BN stats). FC1 applies BN3+ReLU.
    k_gemm64<HH, true><<<MFC / 64, 256>>>(F, HH, cw1, cb1, SC + 2 * 128, SH + 2 * 128, N1, PART);
    k_bnfin<<<1, 128>>>(16, 1.f / MFC, g3, be3, 3);

    k_gemm64<HH, true><<<MFC / 64, 256>>>(N1, HH, cw2, cb2, SC + 3 * 128, SH + 3 * 128, N2, PART);
    k_bnfin<<<1, 128>>>(16, 1.f / MFC, g4, be4, 4);

    k_final<<<(MFC * IOUS + 255) / 256, 256>>>(cw3, cb3, out);
}